// round 1
// baseline (speedup 1.0000x reference)
#include <cuda_runtime.h>
#include <math_constants.h>

#define B_ 8
#define S_ 256
#define D_ 1024
#define H_ 16
#define E_ 4
#define FF_ 4096
#define HD_ 64
#define NPAIR (E_*B_)
#define SCALE_ 0.125f
#define EPS_FILL_F 2.2204460492503131e-16f

// ---------------- scratch (device globals: no allocations allowed) ----------
__device__ float g_xs[B_*D_];
__device__ float g_gates[B_*E_];
__device__ float g_q[(size_t)NPAIR*S_*D_];
__device__ float g_k[(size_t)NPAIR*S_*D_];
__device__ float g_v[(size_t)NPAIR*S_*D_];
__device__ float g_att[(size_t)NPAIR*S_*D_];
__device__ float g_ff[(size_t)NPAIR*S_*FF_];

// ---------------- xs = x.sum(axis=1) ----------------
__global__ void sumx_kernel(const float* __restrict__ x)
{
    int d = blockIdx.x*256 + threadIdx.x;
    int b = blockIdx.y;
    const float* xp = x + (size_t)b*S_*D_ + d;
    float acc = 0.f;
    #pragma unroll 4
    for (int s = 0; s < S_; s++) acc += xp[(size_t)s*D_];
    g_xs[b*D_ + d] = acc;
}

// ---------------- noisy top-k gating + aux loss ----------------
__global__ void gate_kernel(const float* __restrict__ w_gate,
                            const float* __restrict__ w_noise,
                            const float* __restrict__ noise,
                            float* __restrict__ loss_out)
{
    __shared__ float s_clean[B_][E_], s_raw[B_][E_], s_prob[B_][E_], s_gate[B_][E_];
    int tid = threadIdx.x;
    int wid = tid >> 5, lane = tid & 31;
    {   // 32 warps, one per (b,e) pair: two 1024-dot products
        int b = wid >> 2, e = wid & 3;
        float ac = 0.f, ar = 0.f;
        for (int i = lane; i < D_; i += 32) {
            float xv = g_xs[b*D_ + i];
            ac = fmaf(xv, w_gate[i*E_ + e], ac);
            ar = fmaf(xv, w_noise[i*E_ + e], ar);
        }
        #pragma unroll
        for (int o = 16; o > 0; o >>= 1) {
            ac += __shfl_xor_sync(0xffffffffu, ac, o);
            ar += __shfl_xor_sync(0xffffffffu, ar, o);
        }
        if (lane == 0) { s_clean[b][e] = ac; s_raw[b][e] = ar; }
    }
    __syncthreads();
    if (tid < B_) {
        int b = tid;
        float clean[E_], noisy[E_], sd[E_];
        #pragma unroll
        for (int e = 0; e < E_; e++) {
            clean[e] = s_clean[b][e];
            float r = s_raw[b][e];
            float sp = fmaxf(r, 0.f) + log1pf(expf(-fabsf(r)));  // stable softplus
            sd[e] = sp + 0.01f;
            noisy[e] = clean[e] + noise[b*E_ + e] * sd[e];
        }
        // top-3 of 4, descending, stable (lower index wins ties)
        int ord[3]; bool used[E_] = {false,false,false,false};
        for (int s = 0; s < 3; s++) {
            int best = -1;
            for (int e = 0; e < E_; e++)
                if (!used[e] && (best < 0 || noisy[e] > noisy[best])) best = e;
            used[best] = true; ord[s] = best;
        }
        float l0 = noisy[ord[0]], l1 = noisy[ord[1]], l2 = noisy[ord[2]];
        float e1 = expf(l1 - l0);
        float inv = 1.f / (1.f + e1);
        #pragma unroll
        for (int e = 0; e < E_; e++) s_gate[b][e] = 0.f;
        s_gate[b][ord[0]] = inv;
        s_gate[b][ord[1]] = e1 * inv;
        #pragma unroll
        for (int e = 0; e < E_; e++) {
            bool isin = noisy[e] > l2;
            float thr = isin ? l2 : l1;
            s_prob[b][e] = normcdff((clean[e] - thr) / sd[e]);
            g_gates[b*E_ + e] = s_gate[b][e];
        }
    }
    __syncthreads();
    if (tid == 0) {
        float cv[2];
        for (int which = 0; which < 2; which++) {
            float v[E_];
            for (int e = 0; e < E_; e++) {
                float s = 0.f;
                for (int b = 0; b < B_; b++)
                    s += which ? s_prob[b][e] : s_gate[b][e];
                v[e] = s;
            }
            float m = (v[0]+v[1]+v[2]+v[3]) * 0.25f;
            float var = 0.f;
            for (int e = 0; e < E_; e++) { float dd = v[e]-m; var += dd*dd; }
            var *= (1.0f / (E_ - 1));               // ddof=1
            cv[which] = var / (m*m + 1e-10f);
        }
        loss_out[0] = (cv[0] + cv[1]) * 0.01f;
    }
}

// ---------------- generic batched SGEMM: C[p] = A(e,b) @ W[e] (+bias)(+relu)
// M = S_ = 256 fixed. 128x128 block tile, BK=8, 256 threads, 8x8 microtile.
__global__ __launch_bounds__(256) void sgemm_kernel(
    const float* __restrict__ Abase, const float* __restrict__ Wbase,
    const float* __restrict__ biasbase, float* __restrict__ Cbase,
    int Kdim, int N,
    long strideAe, long strideAb, long strideWe, int doRelu)
{
    int p = blockIdx.z; int e = p / B_, b = p % B_;
    if (g_gates[b*E_ + e] == 0.f) return;
    const float* A = Abase + (size_t)e*strideAe + (size_t)b*strideAb;
    const float* W = Wbase + (size_t)e*strideWe;
    float* C = Cbase + (size_t)p*S_*N;

    __shared__ __align__(16) float As[8][128];
    __shared__ __align__(16) float Bs[8][128];

    int tid = threadIdx.x;
    int tx = tid & 15, ty = tid >> 4;
    int rowBase = blockIdx.x * 128;
    int colBase = blockIdx.y * 128;

    int ar = tid >> 1;           // 0..127
    int ac = (tid & 1) * 4;      // 0 or 4
    int br = tid >> 5;           // 0..7
    int bc = (tid & 31) * 4;     // 0..124

    float acc[8][8];
    #pragma unroll
    for (int i = 0; i < 8; i++)
        #pragma unroll
        for (int j = 0; j < 8; j++) acc[i][j] = 0.f;

    for (int kt = 0; kt < Kdim; kt += 8) {
        float4 av = *reinterpret_cast<const float4*>(&A[(size_t)(rowBase+ar)*Kdim + kt + ac]);
        As[ac+0][ar] = av.x; As[ac+1][ar] = av.y; As[ac+2][ar] = av.z; As[ac+3][ar] = av.w;
        float4 bv = *reinterpret_cast<const float4*>(&W[(size_t)(kt+br)*N + colBase + bc]);
        *reinterpret_cast<float4*>(&Bs[br][bc]) = bv;
        __syncthreads();
        #pragma unroll
        for (int k = 0; k < 8; k++) {
            float af[8], bf[8];
            float4 a0 = *reinterpret_cast<const float4*>(&As[k][ty*8]);
            float4 a1 = *reinterpret_cast<const float4*>(&As[k][ty*8+4]);
            af[0]=a0.x; af[1]=a0.y; af[2]=a0.z; af[3]=a0.w;
            af[4]=a1.x; af[5]=a1.y; af[6]=a1.z; af[7]=a1.w;
            float4 b0 = *reinterpret_cast<const float4*>(&Bs[k][tx*8]);
            float4 b1 = *reinterpret_cast<const float4*>(&Bs[k][tx*8+4]);
            bf[0]=b0.x; bf[1]=b0.y; bf[2]=b0.z; bf[3]=b0.w;
            bf[4]=b1.x; bf[5]=b1.y; bf[6]=b1.z; bf[7]=b1.w;
            #pragma unroll
            for (int i = 0; i < 8; i++)
                #pragma unroll
                for (int j = 0; j < 8; j++)
                    acc[i][j] = fmaf(af[i], bf[j], acc[i][j]);
        }
        __syncthreads();
    }
    const float* bias = biasbase ? biasbase + (size_t)e*N : nullptr;
    #pragma unroll
    for (int i = 0; i < 8; i++) {
        int row = rowBase + ty*8 + i;
        #pragma unroll
        for (int j = 0; j < 8; j += 4) {
            int col = colBase + tx*8 + j;
            float4 v;
            v.x = acc[i][j]; v.y = acc[i][j+1]; v.z = acc[i][j+2]; v.w = acc[i][j+3];
            if (bias) { v.x += bias[col]; v.y += bias[col+1]; v.z += bias[col+2]; v.w += bias[col+3]; }
            if (doRelu) {
                v.x = fmaxf(v.x, 0.f); v.y = fmaxf(v.y, 0.f);
                v.z = fmaxf(v.z, 0.f); v.w = fmaxf(v.w, 0.f);
            }
            *reinterpret_cast<float4*>(&C[(size_t)row*N + col]) = v;
        }
    }
}

// ---------------- fused causal attention (flash-style, per-thread row) -------
__global__ __launch_bounds__(256) void attn_kernel()
{
    int p = blockIdx.x, h = blockIdx.y;
    int e = p / B_, b = p % B_;
    if (g_gates[b*E_ + e] == 0.f) return;
    __shared__ __align__(16) float Ks[64][HD_];
    __shared__ __align__(16) float Vs[64][HD_];
    int qi = threadIdx.x;
    float qreg[HD_];
    {
        const float* qp = &g_q[((size_t)p*S_ + qi)*D_ + h*HD_];
        #pragma unroll
        for (int i = 0; i < HD_; i += 4) {
            float4 t = *reinterpret_cast<const float4*>(qp + i);
            qreg[i] = t.x; qreg[i+1] = t.y; qreg[i+2] = t.z; qreg[i+3] = t.w;
        }
    }
    float acc[HD_];
    #pragma unroll
    for (int i = 0; i < HD_; i++) acc[i] = 0.f;
    float m = -CUDART_INF_F, l = 0.f;

    for (int t = 0; t < S_/64; t++) {
        #pragma unroll
        for (int pass = 0; pass < 4; pass++) {
            int r = pass*16 + (threadIdx.x >> 4);
            int c = (threadIdx.x & 15) * 4;
            size_t off = ((size_t)p*S_ + t*64 + r)*D_ + h*HD_ + c;
            *reinterpret_cast<float4*>(&Ks[r][c]) = *reinterpret_cast<const float4*>(&g_k[off]);
            *reinterpret_cast<float4*>(&Vs[r][c]) = *reinterpret_cast<const float4*>(&g_v[off]);
        }
        __syncthreads();
        int kmax = qi - t*64;
        if (kmax > 63) kmax = 63;
        for (int kk = 0; kk <= kmax; kk++) {
            float s = 0.f;
            const float* kr = Ks[kk];
            #pragma unroll
            for (int i = 0; i < HD_; i++) s = fmaf(qreg[i], kr[i], s);
            s *= SCALE_;
            float mn = fmaxf(m, s);
            float corr = expf(m - mn);     // m=-inf -> 0
            float pw = expf(s - mn);
            l = l*corr + pw;
            const float* vr = Vs[kk];
            #pragma unroll
            for (int i = 0; i < HD_; i++) acc[i] = fmaf(acc[i], corr, pw*vr[i]);
            m = mn;
        }
        __syncthreads();
    }
    float invl = 1.f / l;
    float* op = &g_att[((size_t)p*S_ + qi)*D_ + h*HD_];
    #pragma unroll
    for (int i = 0; i < HD_; i += 4) {
        float4 t;
        t.x = acc[i]*invl; t.y = acc[i+1]*invl; t.z = acc[i+2]*invl; t.w = acc[i+3]*invl;
        *reinterpret_cast<float4*>(op + i) = t;
    }
}

// ---------------- block reduce (sum, sumsq), blockDim = 256 -----------------
__device__ __forceinline__ float2 block_reduce2(float a, float b)
{
    __shared__ float2 sh[9];
    int tid = threadIdx.x, lane = tid & 31, wid = tid >> 5;
    #pragma unroll
    for (int o = 16; o > 0; o >>= 1) {
        a += __shfl_xor_sync(0xffffffffu, a, o);
        b += __shfl_xor_sync(0xffffffffu, b, o);
    }
    if (lane == 0) sh[wid] = make_float2(a, b);
    __syncthreads();
    if (tid == 0) {
        float sa = 0.f, sb = 0.f;
        #pragma unroll
        for (int w = 0; w < 8; w++) { sa += sh[w].x; sb += sh[w].y; }
        sh[8] = make_float2(sa, sb);
    }
    __syncthreads();
    float2 r = sh[8];
    __syncthreads();
    return r;
}

// ---------------- h1 = LN(x + oproj) * g1 + be1 -----------------------------
__global__ __launch_bounds__(256) void addln_kernel(
    const float* __restrict__ xbase, const float* __restrict__ res,
    const float* __restrict__ gain, const float* __restrict__ beta,
    float* __restrict__ out)
{
    int p = blockIdx.x; int e = p / B_, b = p % B_;
    if (g_gates[b*E_ + e] == 0.f) return;
    int s = blockIdx.y, tid = threadIdx.x;
    const float* xr = xbase + ((size_t)b*S_ + s)*D_;
    const float* rr = res + ((size_t)p*S_ + s)*D_;
    float v[4]; float sum = 0.f, sq = 0.f;
    #pragma unroll
    for (int j = 0; j < 4; j++) {
        int i = tid + j*256;
        float t = xr[i] + rr[i];
        v[j] = t; sum += t; sq = fmaf(t, t, sq);
    }
    float2 r = block_reduce2(sum, sq);
    float mean = r.x * (1.f/D_);
    float var = r.y * (1.f/D_) - mean*mean;
    float rstd = rsqrtf(var + 1e-5f);
    float* orow = out + ((size_t)p*S_ + s)*D_;
    #pragma unroll
    for (int j = 0; j < 4; j++) {
        int i = tid + j*256;
        orow[i] = (v[j] - mean)*rstd*gain[e*D_ + i] + beta[e*D_ + i];
    }
}

// ---------------- y = sum_e gate * LN(h1 + ff2), eps-fill, + write ----------
__global__ __launch_bounds__(256) void final_kernel(
    const float* __restrict__ h1, const float* __restrict__ f2,
    const float* __restrict__ g2, const float* __restrict__ be2,
    float* __restrict__ y)
{
    int b = blockIdx.x, s = blockIdx.y, tid = threadIdx.x;
    float acc[4] = {0.f, 0.f, 0.f, 0.f};
    for (int e = 0; e < E_; e++) {
        float gv = g_gates[b*E_ + e];
        if (gv == 0.f) continue;                 // uniform across block
        int p = e*B_ + b;
        const float* hr = h1 + ((size_t)p*S_ + s)*D_;
        const float* fr = f2 + ((size_t)p*S_ + s)*D_;
        float v[4]; float sum = 0.f, sq = 0.f;
        #pragma unroll
        for (int j = 0; j < 4; j++) {
            int i = tid + j*256;
            float t = hr[i] + fr[i];
            v[j] = t; sum += t; sq = fmaf(t, t, sq);
        }
        float2 r = block_reduce2(sum, sq);
        float mean = r.x * (1.f/D_);
        float var = r.y * (1.f/D_) - mean*mean;
        float rstd = rsqrtf(var + 1e-5f);
        #pragma unroll
        for (int j = 0; j < 4; j++) {
            int i = tid + j*256;
            acc[j] += gv * ((v[j]-mean)*rstd*g2[e*D_+i] + be2[e*D_+i]);
        }
    }
    float* yr = y + ((size_t)b*S_ + s)*D_;
    #pragma unroll
    for (int j = 0; j < 4; j++) {
        int i = tid + j*256;
        float o = acc[j];
        if (o == 0.f) o = EPS_FILL_F;
        yr[i] = o;
    }
}

// ---------------- launch ----------------------------------------------------
extern "C" void kernel_launch(void* const* d_in, const int* in_sizes, int n_in,
                              void* d_out, int out_size)
{
    const float* x       = (const float*)d_in[0];
    const float* noise   = (const float*)d_in[2];
    const float* w_gate  = (const float*)d_in[3];
    const float* w_noise = (const float*)d_in[4];
    const float* Wq      = (const float*)d_in[5];
    const float* Wk      = (const float*)d_in[6];
    const float* Wv      = (const float*)d_in[7];
    const float* Wo      = (const float*)d_in[8];
    const float* W1      = (const float*)d_in[9];
    const float* b1      = (const float*)d_in[10];
    const float* W2      = (const float*)d_in[11];
    const float* b2      = (const float*)d_in[12];
    const float* g1      = (const float*)d_in[13];
    const float* be1     = (const float*)d_in[14];
    const float* g2      = (const float*)d_in[15];
    const float* be2     = (const float*)d_in[16];
    float* out = (float*)d_out;

    float *pQ, *pK, *pV, *pAtt, *pFF;
    cudaGetSymbolAddress((void**)&pQ,   g_q);
    cudaGetSymbolAddress((void**)&pK,   g_k);
    cudaGetSymbolAddress((void**)&pV,   g_v);
    cudaGetSymbolAddress((void**)&pAtt, g_att);
    cudaGetSymbolAddress((void**)&pFF,  g_ff);

    const long SD  = (long)S_*D_;
    const long BSD = (long)B_*S_*D_;

    sumx_kernel<<<dim3(D_/256, B_), 256>>>(x);
    gate_kernel<<<1, 1024>>>(w_gate, w_noise, noise, out + (size_t)B_*S_*D_);

    // QKV projections: A = x[b] (strideAe=0), W = W*[e]
    sgemm_kernel<<<dim3(2, D_/128, NPAIR), 256>>>(x, Wq, nullptr, pQ, D_, D_, 0, SD, (long)D_*D_, 0);
    sgemm_kernel<<<dim3(2, D_/128, NPAIR), 256>>>(x, Wk, nullptr, pK, D_, D_, 0, SD, (long)D_*D_, 0);
    sgemm_kernel<<<dim3(2, D_/128, NPAIR), 256>>>(x, Wv, nullptr, pV, D_, D_, 0, SD, (long)D_*D_, 0);

    attn_kernel<<<dim3(NPAIR, H_), 256>>>();

    // O projection: A = att[p], C -> reuse g_q
    sgemm_kernel<<<dim3(2, D_/128, NPAIR), 256>>>(pAtt, Wo, nullptr, pQ, D_, D_, BSD, SD, (long)D_*D_, 0);

    // h1 = LN(x + oproj) -> reuse g_k
    addln_kernel<<<dim3(NPAIR, S_), 256>>>(x, pQ, g1, be1, pK);

    // FFN1: relu(h1 @ W1 + b1) -> g_ff
    sgemm_kernel<<<dim3(2, FF_/128, NPAIR), 256>>>(pK, W1, b1, pFF, D_, FF_, BSD, SD, (long)D_*FF_, 1);

    // FFN2: g_ff @ W2 + b2 -> reuse g_v
    sgemm_kernel<<<dim3(2, D_/128, NPAIR), 256>>>(pFF, W2, b2, pV, FF_, D_, (long)B_*S_*FF_, (long)S_*FF_, (long)FF_*D_, 0);

    // y = sum_e gate * LN(h1 + ff2), eps-fill; loss already written
    final_kernel<<<dim3(B_, S_), 256>>>(pK, pV, g2, be2, out);
}

// round 3
// speedup vs baseline: 2.0154x; 2.0154x over previous
#include <cuda_runtime.h>
#include <cuda_bf16.h>
#include <math_constants.h>
#include <cstdint>

#define B_ 8
#define S_ 256
#define D_ 1024
#define H_ 16
#define E_ 4
#define FF_ 4096
#define HD_ 64
#define NPAIR (E_*B_)
#define SCALE_ 0.125f
#define EPS_FILL_F 2.2204460492503131e-16f
#define KCH 32
#define LDA 40   // padded row length (elements) for 128x32 bf16 tiles

// ---------------- scratch (device globals: no allocations allowed) ----------
__device__ float g_xs[B_*D_];
__device__ float g_gates[B_*E_];
// fp32 activations
__device__ float g_q[(size_t)NPAIR*S_*D_];
__device__ float g_k[(size_t)NPAIR*S_*D_];   // later reused as h1 (fp32)
__device__ float g_v[(size_t)NPAIR*S_*D_];   // later reused as ffn2 out (fp32)
// bf16 split activations
__device__ __nv_bfloat16 g_xh[(size_t)B_*S_*D_];
__device__ __nv_bfloat16 g_xl[(size_t)B_*S_*D_];
__device__ __nv_bfloat16 g_ath[(size_t)NPAIR*S_*D_];
__device__ __nv_bfloat16 g_atl[(size_t)NPAIR*S_*D_];
__device__ __nv_bfloat16 g_h1h[(size_t)NPAIR*S_*D_];
__device__ __nv_bfloat16 g_h1l[(size_t)NPAIR*S_*D_];
__device__ __nv_bfloat16 g_ffh[(size_t)NPAIR*S_*FF_];
__device__ __nv_bfloat16 g_ffl[(size_t)NPAIR*S_*FF_];
// transposed+split weights  [e][N][K]
__device__ __nv_bfloat16 g_wqTh[(size_t)E_*D_*D_];
__device__ __nv_bfloat16 g_wqTl[(size_t)E_*D_*D_];
__device__ __nv_bfloat16 g_wkTh[(size_t)E_*D_*D_];
__device__ __nv_bfloat16 g_wkTl[(size_t)E_*D_*D_];
__device__ __nv_bfloat16 g_wvTh[(size_t)E_*D_*D_];
__device__ __nv_bfloat16 g_wvTl[(size_t)E_*D_*D_];
__device__ __nv_bfloat16 g_woTh[(size_t)E_*D_*D_];
__device__ __nv_bfloat16 g_woTl[(size_t)E_*D_*D_];
__device__ __nv_bfloat16 g_w1Th[(size_t)E_*D_*FF_];
__device__ __nv_bfloat16 g_w1Tl[(size_t)E_*D_*FF_];
__device__ __nv_bfloat16 g_w2Th[(size_t)E_*D_*FF_];
__device__ __nv_bfloat16 g_w2Tl[(size_t)E_*D_*FF_];

// ---------------- helpers ----------------
__device__ __forceinline__ uint32_t smem_u32(const void* p){
    uint32_t a;
    asm("{ .reg .u64 t; cvta.to.shared.u64 t, %1; cvt.u32.u64 %0, t; }" : "=r"(a) : "l"(p));
    return a;
}
__device__ __forceinline__ void ldsm_x4(uint32_t (&r)[4], uint32_t addr){
    asm volatile("ldmatrix.sync.aligned.m8n8.x4.shared.b16 {%0,%1,%2,%3}, [%4];"
                 : "=r"(r[0]),"=r"(r[1]),"=r"(r[2]),"=r"(r[3]) : "r"(addr));
}
__device__ __forceinline__ void mma16816(float (&c)[4], const uint32_t (&a)[4], const uint32_t (&b)[2]){
    asm volatile("mma.sync.aligned.m16n8k16.row.col.f32.bf16.bf16.f32 "
                 "{%0,%1,%2,%3},{%4,%5,%6,%7},{%8,%9},{%0,%1,%2,%3};"
                 : "+f"(c[0]),"+f"(c[1]),"+f"(c[2]),"+f"(c[3])
                 : "r"(a[0]),"r"(a[1]),"r"(a[2]),"r"(a[3]),"r"(b[0]),"r"(b[1]));
}
__device__ __forceinline__ void split_bf16(float v, __nv_bfloat16& h, __nv_bfloat16& l){
    h = __float2bfloat16(v);
    l = __float2bfloat16(v - __bfloat162float(h));
}

// ---------------- xs = x.sum(axis=1) ----------------
__global__ void sumx_kernel(const float* __restrict__ x)
{
    int d = blockIdx.x*256 + threadIdx.x;
    int b = blockIdx.y;
    const float* xp = x + (size_t)b*S_*D_ + d;
    float acc = 0.f;
    #pragma unroll 4
    for (int s = 0; s < S_; s++) acc += xp[(size_t)s*D_];
    g_xs[b*D_ + d] = acc;
}

// ---------------- noisy top-k gating + aux loss ----------------
__global__ void gate_kernel(const float* __restrict__ w_gate,
                            const float* __restrict__ w_noise,
                            const float* __restrict__ noise,
                            float* __restrict__ loss_out)
{
    __shared__ float s_clean[B_][E_], s_raw[B_][E_], s_prob[B_][E_], s_gate[B_][E_];
    int tid = threadIdx.x;
    int wid = tid >> 5, lane = tid & 31;
    {
        int b = wid >> 2, e = wid & 3;
        float ac = 0.f, ar = 0.f;
        for (int i = lane; i < D_; i += 32) {
            float xv = g_xs[b*D_ + i];
            ac = fmaf(xv, w_gate[i*E_ + e], ac);
            ar = fmaf(xv, w_noise[i*E_ + e], ar);
        }
        #pragma unroll
        for (int o = 16; o > 0; o >>= 1) {
            ac += __shfl_xor_sync(0xffffffffu, ac, o);
            ar += __shfl_xor_sync(0xffffffffu, ar, o);
        }
        if (lane == 0) { s_clean[b][e] = ac; s_raw[b][e] = ar; }
    }
    __syncthreads();
    if (tid < B_) {
        int b = tid;
        float clean[E_], noisy[E_], sd[E_];
        #pragma unroll
        for (int e = 0; e < E_; e++) {
            clean[e] = s_clean[b][e];
            float r = s_raw[b][e];
            float sp = fmaxf(r, 0.f) + log1pf(expf(-fabsf(r)));
            sd[e] = sp + 0.01f;
            noisy[e] = clean[e] + noise[b*E_ + e] * sd[e];
        }
        int ord[3]; bool used[E_] = {false,false,false,false};
        for (int s = 0; s < 3; s++) {
            int best = -1;
            for (int e = 0; e < E_; e++)
                if (!used[e] && (best < 0 || noisy[e] > noisy[best])) best = e;
            used[best] = true; ord[s] = best;
        }
        float l0 = noisy[ord[0]], l1 = noisy[ord[1]], l2 = noisy[ord[2]];
        float e1 = expf(l1 - l0);
        float inv = 1.f / (1.f + e1);
        #pragma unroll
        for (int e = 0; e < E_; e++) s_gate[b][e] = 0.f;
        s_gate[b][ord[0]] = inv;
        s_gate[b][ord[1]] = e1 * inv;
        #pragma unroll
        for (int e = 0; e < E_; e++) {
            bool isin = noisy[e] > l2;
            float thr = isin ? l2 : l1;
            s_prob[b][e] = normcdff((clean[e] - thr) / sd[e]);
            g_gates[b*E_ + e] = s_gate[b][e];
        }
    }
    __syncthreads();
    if (tid == 0) {
        float cv[2];
        for (int which = 0; which < 2; which++) {
            float v[E_];
            for (int e = 0; e < E_; e++) {
                float s = 0.f;
                for (int b = 0; b < B_; b++)
                    s += which ? s_prob[b][e] : s_gate[b][e];
                v[e] = s;
            }
            float m = (v[0]+v[1]+v[2]+v[3]) * 0.25f;
            float var = 0.f;
            for (int e = 0; e < E_; e++) { float dd = v[e]-m; var += dd*dd; }
            var *= (1.0f / (E_ - 1));
            cv[which] = var / (m*m + 1e-10f);
        }
        loss_out[0] = (cv[0] + cv[1]) * 0.01f;
    }
}

// ---------------- weight transpose + bf16 split:  W[e][K][N] -> Wt[e][N][K] --
__global__ void transpose_split_kernel(const float* __restrict__ W,
                                       __nv_bfloat16* __restrict__ oh,
                                       __nv_bfloat16* __restrict__ ol,
                                       int Kd, int Nd)
{
    __shared__ float t[32][33];
    int e = blockIdx.z;
    const float* We = W + (size_t)e*Kd*Nd;
    size_t ob = (size_t)e*Kd*Nd;
    int k0 = blockIdx.y*32, n0 = blockIdx.x*32;
    int tx = threadIdx.x, ty = threadIdx.y;  // 32 x 8
    #pragma unroll
    for (int i = 0; i < 32; i += 8)
        t[ty+i][tx] = We[(size_t)(k0+ty+i)*Nd + n0 + tx];
    __syncthreads();
    #pragma unroll
    for (int i = 0; i < 32; i += 8) {
        float v = t[tx][ty+i];
        size_t o = ob + (size_t)(n0+ty+i)*Kd + k0 + tx;
        __nv_bfloat16 h, l; split_bf16(v, h, l);
        oh[o] = h; ol[o] = l;
    }
}

// ---------------- elementwise bf16 split of x -------------------------------
__global__ void splitx_kernel(const float* __restrict__ in,
                              __nv_bfloat16* __restrict__ oh,
                              __nv_bfloat16* __restrict__ ol)
{
    int i = blockIdx.x*256 + threadIdx.x;
    float v = in[i];
    __nv_bfloat16 h, l; split_bf16(v, h, l);
    oh[i] = h; ol[i] = l;
}

// ---------------- HMMA bf16 split-3 GEMM: C[p] = A(p) @ Wt(e)^T --------------
// A (hi/lo) K-major [rows,Kdim]; B = Wt (hi/lo) [e][N][Kdim] K-major.
// 128x128 CTA tile, 8 warps (2x4), warp tile 64x32, K-chunk 32.
__global__ __launch_bounds__(256) void tgemm_kernel(
    const __nv_bfloat16* __restrict__ Ah, const __nv_bfloat16* __restrict__ Al,
    const __nv_bfloat16* __restrict__ Bh, const __nv_bfloat16* __restrict__ Bl,
    const float* __restrict__ biasbase,
    float* __restrict__ outF,
    __nv_bfloat16* __restrict__ outHi, __nv_bfloat16* __restrict__ outLo,
    int Kdim, int N, long sAe, long sAb, int doRelu)
{
    int p = blockIdx.z, e = p >> 3, b = p & 7;
    if (g_gates[b*E_ + e] == 0.f) return;

    __shared__ __align__(16) __nv_bfloat16 sAh[128*LDA];
    __shared__ __align__(16) __nv_bfloat16 sAl[128*LDA];
    __shared__ __align__(16) __nv_bfloat16 sBh[128*LDA];
    __shared__ __align__(16) __nv_bfloat16 sBl[128*LDA];

    int tid = threadIdx.x, wid = tid >> 5, lane = tid & 31;
    int warpRow = wid >> 2;        // 0..1  (64 rows each)
    int warpCol = wid & 3;         // 0..3  (32 cols each)

    int rowBase = blockIdx.x * 128;
    int colBase = blockIdx.y * 128;

    const __nv_bfloat16* A_h = Ah + (size_t)e*sAe + (size_t)b*sAb + (size_t)rowBase*Kdim;
    const __nv_bfloat16* A_l = Al + (size_t)e*sAe + (size_t)b*sAb + (size_t)rowBase*Kdim;
    const __nv_bfloat16* B_h = Bh + ((size_t)e*N + colBase)*Kdim;
    const __nv_bfloat16* B_l = Bl + ((size_t)e*N + colBase)*Kdim;

    uint32_t sAh32 = smem_u32(sAh), sAl32 = smem_u32(sAl);
    uint32_t sBh32 = smem_u32(sBh), sBl32 = smem_u32(sBl);

    // per-thread ldmatrix base byte offsets (within tile)
    uint32_t aOff = (uint32_t)((lane & 15) * (LDA*2)) + ((lane >> 4) * 16);
    uint32_t bOff = (uint32_t)(((lane & 7) + ((lane >> 4) << 3)) * (LDA*2)) + (((lane >> 3) & 1) * 16);
    // warp bases
    uint32_t aWarp = (uint32_t)(warpRow * 64) * (LDA*2);
    uint32_t bWarp = (uint32_t)(warpCol * 32) * (LDA*2);

    // load indices: gid over 512 16B-vectors per operand tile
    int r0 = tid >> 1;                  // row for first vec (gid=tid*? ) -- see below
    // we use gid = i*256 + tid; r = gid>>2; c = gid&3

    float acc[4][4][4];
    #pragma unroll
    for (int i = 0; i < 4; i++)
        #pragma unroll
        for (int j = 0; j < 4; j++)
            #pragma unroll
            for (int q = 0; q < 4; q++) acc[i][j][q] = 0.f;

    int nCh = Kdim / KCH;
    for (int kt = 0; kt < nCh; kt++) {
        size_t koff = (size_t)kt * KCH;
        #pragma unroll
        for (int i = 0; i < 2; i++) {
            int gid = i*256 + tid;
            int r = gid >> 2, c = gid & 3;
            size_t goff = (size_t)r*Kdim + koff + (size_t)c*8;
            uint32_t so = (uint32_t)r*(LDA*2) + (uint32_t)c*16;
            *(uint4*)((char*)sAh + so) = *(const uint4*)(A_h + goff);
            *(uint4*)((char*)sAl + so) = *(const uint4*)(A_l + goff);
            *(uint4*)((char*)sBh + so) = *(const uint4*)(B_h + goff);
            *(uint4*)((char*)sBl + so) = *(const uint4*)(B_l + goff);
        }
        __syncthreads();

        #pragma unroll
        for (int k16 = 0; k16 < 2; k16++) {
            uint32_t kb = (uint32_t)k16 * 32;
            uint32_t a[4][4], bh[4][2], bl[4][2];
            // B fragments (hi & lo)
            #pragma unroll
            for (int np = 0; np < 2; np++) {
                uint32_t r4[4];
                ldsm_x4(r4, sBh32 + bWarp + bOff + np*(16*LDA*2) + kb);
                bh[2*np][0] = r4[0]; bh[2*np][1] = r4[1];
                bh[2*np+1][0] = r4[2]; bh[2*np+1][1] = r4[3];
                ldsm_x4(r4, sBl32 + bWarp + bOff + np*(16*LDA*2) + kb);
                bl[2*np][0] = r4[0]; bl[2*np][1] = r4[1];
                bl[2*np+1][0] = r4[2]; bl[2*np+1][1] = r4[3];
            }
            // A hi fragments
            #pragma unroll
            for (int mt = 0; mt < 4; mt++)
                ldsm_x4(a[mt], sAh32 + aWarp + aOff + mt*(16*LDA*2) + kb);
            // Ah*Bh, Ah*Bl
            #pragma unroll
            for (int mt = 0; mt < 4; mt++)
                #pragma unroll
                for (int nt = 0; nt < 4; nt++)
                    mma16816(acc[mt][nt], a[mt], bh[nt]);
            #pragma unroll
            for (int mt = 0; mt < 4; mt++)
                #pragma unroll
                for (int nt = 0; nt < 4; nt++)
                    mma16816(acc[mt][nt], a[mt], bl[nt]);
            // Al*Bh
            #pragma unroll
            for (int mt = 0; mt < 4; mt++)
                ldsm_x4(a[mt], sAl32 + aWarp + aOff + mt*(16*LDA*2) + kb);
            #pragma unroll
            for (int mt = 0; mt < 4; mt++)
                #pragma unroll
                for (int nt = 0; nt < 4; nt++)
                    mma16816(acc[mt][nt], a[mt], bh[nt]);
        }
        __syncthreads();
    }

    // ---------------- epilogue ----------------
    const float* bias = biasbase ? biasbase + (size_t)e*N : nullptr;
    int mWarp = rowBase + warpRow*64;
    int nWarp = colBase + warpCol*32;
    int rq = lane >> 2, cq = (lane & 3)*2;

    #pragma unroll
    for (int mt = 0; mt < 4; mt++) {
        #pragma unroll
        for (int nt = 0; nt < 4; nt++) {
            int col = nWarp + nt*8 + cq;
            float b0 = bias ? bias[col] : 0.f;
            float b1 = bias ? bias[col+1] : 0.f;
            #pragma unroll
            for (int half = 0; half < 2; half++) {
                int row = mWarp + mt*16 + rq + half*8;
                float v0 = acc[mt][nt][2*half+0] + b0;
                float v1 = acc[mt][nt][2*half+1] + b1;
                if (doRelu) { v0 = fmaxf(v0, 0.f); v1 = fmaxf(v1, 0.f); }
                size_t o = ((size_t)p*S_ + row)*N + col;
                if (outF) *(float2*)(outF + o) = make_float2(v0, v1);
                if (outHi) {
                    __nv_bfloat16 h0,l0,h1,l1;
                    split_bf16(v0, h0, l0); split_bf16(v1, h1, l1);
                    uint32_t hw = (uint32_t)__bfloat16_as_ushort(h0) | ((uint32_t)__bfloat16_as_ushort(h1) << 16);
                    uint32_t lw = (uint32_t)__bfloat16_as_ushort(l0) | ((uint32_t)__bfloat16_as_ushort(l1) << 16);
                    *(uint32_t*)(outHi + o) = hw;
                    *(uint32_t*)(outLo + o) = lw;
                }
            }
        }
    }
}

// ---------------- fused causal attention (writes bf16 hi/lo) ----------------
__global__ __launch_bounds__(256) void attn_kernel()
{
    int p = blockIdx.x, h = blockIdx.y;
    int e = p / B_, b = p % B_;
    if (g_gates[b*E_ + e] == 0.f) return;
    __shared__ __align__(16) float Ks[64][HD_];
    __shared__ __align__(16) float Vs[64][HD_];
    int qi = threadIdx.x;
    float qreg[HD_];
    {
        const float* qp = &g_q[((size_t)p*S_ + qi)*D_ + h*HD_];
        #pragma unroll
        for (int i = 0; i < HD_; i += 4) {
            float4 t = *reinterpret_cast<const float4*>(qp + i);
            qreg[i] = t.x; qreg[i+1] = t.y; qreg[i+2] = t.z; qreg[i+3] = t.w;
        }
    }
    float acc[HD_];
    #pragma unroll
    for (int i = 0; i < HD_; i++) acc[i] = 0.f;
    float m = -CUDART_INF_F, l = 0.f;

    for (int t = 0; t < S_/64; t++) {
        #pragma unroll
        for (int pass = 0; pass < 4; pass++) {
            int r = pass*16 + (threadIdx.x >> 4);
            int c = (threadIdx.x & 15) * 4;
            size_t off = ((size_t)p*S_ + t*64 + r)*D_ + h*HD_ + c;
            *reinterpret_cast<float4*>(&Ks[r][c]) = *reinterpret_cast<const float4*>(&g_k[off]);
            *reinterpret_cast<float4*>(&Vs[r][c]) = *reinterpret_cast<const float4*>(&g_v[off]);
        }
        __syncthreads();
        int kmax = qi - t*64;
        if (kmax > 63) kmax = 63;
        for (int kk = 0; kk <= kmax; kk++) {
            float s = 0.f;
            const float* kr = Ks[kk];
            #pragma unroll
            for (int i = 0; i < HD_; i++) s = fmaf(qreg[i], kr[i], s);
            s *= SCALE_;
            float mn = fmaxf(m, s);
            float corr = expf(m - mn);
            float pw = expf(s - mn);
            l = l*corr + pw;
            const float* vr = Vs[kk];
            #pragma unroll
            for (int i = 0; i < HD_; i++) acc[i] = fmaf(acc[i], corr, pw*vr[i]);
            m = mn;
        }
        __syncthreads();
    }
    float invl = 1.f / l;
    size_t ob = ((size_t)p*S_ + qi)*D_ + h*HD_;
    #pragma unroll
    for (int i = 0; i < HD_; i++) {
        float val = acc[i]*invl;
        __nv_bfloat16 hh, ll; split_bf16(val, hh, ll);
        g_ath[ob + i] = hh; g_atl[ob + i] = ll;
    }
}

// ---------------- block reduce (sum, sumsq), blockDim = 256 -----------------
__device__ __forceinline__ float2 block_reduce2(float a, float b)
{
    __shared__ float2 sh[9];
    int tid = threadIdx.x, lane = tid & 31, wid = tid >> 5;
    #pragma unroll
    for (int o = 16; o > 0; o >>= 1) {
        a += __shfl_xor_sync(0xffffffffu, a, o);
        b += __shfl_xor_sync(0xffffffffu, b, o);
    }
    if (lane == 0) sh[wid] = make_float2(a, b);
    __syncthreads();
    if (tid == 0) {
        float sa = 0.f, sb = 0.f;
        #pragma unroll
        for (int w = 0; w < 8; w++) { sa += sh[w].x; sb += sh[w].y; }
        sh[8] = make_float2(sa, sb);
    }
    __syncthreads();
    float2 r = sh[8];
    __syncthreads();
    return r;
}

// ---------------- h1 = LN(x + oproj)*g1+be1 : fp32 + bf16 split -------------
__global__ __launch_bounds__(256) void addln_kernel(
    const float* __restrict__ xbase, const float* __restrict__ res,
    const float* __restrict__ gain, const float* __restrict__ beta,
    float* __restrict__ out)
{
    int p = blockIdx.x; int e = p / B_, b = p % B_;
    if (g_gates[b*E_ + e] == 0.f) return;
    int s = blockIdx.y, tid = threadIdx.x;
    const float* xr = xbase + ((size_t)b*S_ + s)*D_;
    const float* rr = res + ((size_t)p*S_ + s)*D_;
    float v[4]; float sum = 0.f, sq = 0.f;
    #pragma unroll
    for (int j = 0; j < 4; j++) {
        int i = tid + j*256;
        float t = xr[i] + rr[i];
        v[j] = t; sum += t; sq = fmaf(t, t, sq);
    }
    float2 r = block_reduce2(sum, sq);
    float mean = r.x * (1.f/D_);
    float var = r.y * (1.f/D_) - mean*mean;
    float rstd = rsqrtf(var + 1e-5f);
    size_t ob = ((size_t)p*S_ + s)*D_;
    #pragma unroll
    for (int j = 0; j < 4; j++) {
        int i = tid + j*256;
        float o = (v[j] - mean)*rstd*gain[e*D_ + i] + beta[e*D_ + i];
        out[ob + i] = o;
        __nv_bfloat16 hh, ll; split_bf16(o, hh, ll);
        g_h1h[ob + i] = hh; g_h1l[ob + i] = ll;
    }
}

// ---------------- y = sum_e gate * LN(h1 + ff2), eps-fill -------------------
__global__ __launch_bounds__(256) void final_kernel(
    const float* __restrict__ h1, const float* __restrict__ f2,
    const float* __restrict__ g2, const float* __restrict__ be2,
    float* __restrict__ y)
{
    int b = blockIdx.x, s = blockIdx.y, tid = threadIdx.x;
    float acc[4] = {0.f, 0.f, 0.f, 0.f};
    for (int e = 0; e < E_; e++) {
        float gv = g_gates[b*E_ + e];
        if (gv == 0.f) continue;
        int p = e*B_ + b;
        const float* hr = h1 + ((size_t)p*S_ + s)*D_;
        const float* fr = f2 + ((size_t)p*S_ + s)*D_;
        float v[4]; float sum = 0.f, sq = 0.f;
        #pragma unroll
        for (int j = 0; j < 4; j++) {
            int i = tid + j*256;
            float t = hr[i] + fr[i];
            v[j] = t; sum += t; sq = fmaf(t, t, sq);
        }
        float2 r = block_reduce2(sum, sq);
        float mean = r.x * (1.f/D_);
        float var = r.y * (1.f/D_) - mean*mean;
        float rstd = rsqrtf(var + 1e-5f);
        #pragma unroll
        for (int j = 0; j < 4; j++) {
            int i = tid + j*256;
            acc[j] += gv * ((v[j]-mean)*rstd*g2[e*D_+i] + be2[e*D_+i]);
        }
    }
    float* yr = y + ((size_t)b*S_ + s)*D_;
    #pragma unroll
    for (int j = 0; j < 4; j++) {
        int i = tid + j*256;
        float o = acc[j];
        if (o == 0.f) o = EPS_FILL_F;
        yr[i] = o;
    }
}

// ---------------- launch ----------------------------------------------------
extern "C" void kernel_launch(void* const* d_in, const int* in_sizes, int n_in,
                              void* d_out, int out_size)
{
    const float* x       = (const float*)d_in[0];
    const float* noise   = (const float*)d_in[2];
    const float* w_gate  = (const float*)d_in[3];
    const float* w_noise = (const float*)d_in[4];
    const float* Wq      = (const float*)d_in[5];
    const float* Wk      = (const float*)d_in[6];
    const float* Wv      = (const float*)d_in[7];
    const float* Wo      = (const float*)d_in[8];
    const float* W1      = (const float*)d_in[9];
    const float* b1      = (const float*)d_in[10];
    const float* W2      = (const float*)d_in[11];
    const float* b2      = (const float*)d_in[12];
    const float* g1      = (const float*)d_in[13];
    const float* be1     = (const float*)d_in[14];
    const float* g2      = (const float*)d_in[15];
    const float* be2     = (const float*)d_in[16];
    float* out = (float*)d_out;

    float *pQ, *pK, *pV;
    __nv_bfloat16 *pXh, *pXl, *pAth, *pAtl, *pH1h, *pH1l, *pFFh, *pFFl;
    __nv_bfloat16 *pWqh, *pWql, *pWkh, *pWkl, *pWvh, *pWvl, *pWoh, *pWol;
    __nv_bfloat16 *pW1h, *pW1l, *pW2h, *pW2l;
    cudaGetSymbolAddress((void**)&pQ,   g_q);
    cudaGetSymbolAddress((void**)&pK,   g_k);
    cudaGetSymbolAddress((void**)&pV,   g_v);
    cudaGetSymbolAddress((void**)&pXh,  g_xh);
    cudaGetSymbolAddress((void**)&pXl,  g_xl);
    cudaGetSymbolAddress((void**)&pAth, g_ath);
    cudaGetSymbolAddress((void**)&pAtl, g_atl);
    cudaGetSymbolAddress((void**)&pH1h, g_h1h);
    cudaGetSymbolAddress((void**)&pH1l, g_h1l);
    cudaGetSymbolAddress((void**)&pFFh, g_ffh);
    cudaGetSymbolAddress((void**)&pFFl, g_ffl);
    cudaGetSymbolAddress((void**)&pWqh, g_wqTh);
    cudaGetSymbolAddress((void**)&pWql, g_wqTl);
    cudaGetSymbolAddress((void**)&pWkh, g_wkTh);
    cudaGetSymbolAddress((void**)&pWkl, g_wkTl);
    cudaGetSymbolAddress((void**)&pWvh, g_wvTh);
    cudaGetSymbolAddress((void**)&pWvl, g_wvTl);
    cudaGetSymbolAddress((void**)&pWoh, g_woTh);
    cudaGetSymbolAddress((void**)&pWol, g_woTl);
    cudaGetSymbolAddress((void**)&pW1h, g_w1Th);
    cudaGetSymbolAddress((void**)&pW1l, g_w1Tl);
    cudaGetSymbolAddress((void**)&pW2h, g_w2Th);
    cudaGetSymbolAddress((void**)&pW2l, g_w2Tl);

    const long SD  = (long)S_*D_;
    const long BSD = (long)B_*S_*D_;
    const long SF  = (long)S_*FF_;
    const long BSF = (long)B_*S_*FF_;

    // gating path
    sumx_kernel<<<dim3(D_/256, B_), 256>>>(x);
    gate_kernel<<<1, 1024>>>(w_gate, w_noise, noise, out + (size_t)B_*S_*D_);

    // weight transposes + splits
    transpose_split_kernel<<<dim3(D_/32,  D_/32, E_), dim3(32,8)>>>(Wq, pWqh, pWql, D_, D_);
    transpose_split_kernel<<<dim3(D_/32,  D_/32, E_), dim3(32,8)>>>(Wk, pWkh, pWkl, D_, D_);
    transpose_split_kernel<<<dim3(D_/32,  D_/32, E_), dim3(32,8)>>>(Wv, pWvh, pWvl, D_, D_);
    transpose_split_kernel<<<dim3(D_/32,  D_/32, E_), dim3(32,8)>>>(Wo, pWoh, pWol, D_, D_);
    transpose_split_kernel<<<dim3(FF_/32, D_/32, E_), dim3(32,8)>>>(W1, pW1h, pW1l, D_, FF_);
    transpose_split_kernel<<<dim3(D_/32, FF_/32, E_), dim3(32,8)>>>(W2, pW2h, pW2l, FF_, D_);

    // x split
    splitx_kernel<<<(B_*S_*D_)/256, 256>>>(x, pXh, pXl);

    // QKV projections (A = x hi/lo shared across experts)
    tgemm_kernel<<<dim3(2, D_/128, NPAIR), 256>>>(pXh, pXl, pWqh, pWql, nullptr, pQ, nullptr, nullptr, D_, D_, 0, SD, 0);
    tgemm_kernel<<<dim3(2, D_/128, NPAIR), 256>>>(pXh, pXl, pWkh, pWkl, nullptr, pK, nullptr, nullptr, D_, D_, 0, SD, 0);
    tgemm_kernel<<<dim3(2, D_/128, NPAIR), 256>>>(pXh, pXl, pWvh, pWvl, nullptr, pV, nullptr, nullptr, D_, D_, 0, SD, 0);

    // attention (fp32 in, writes bf16 hi/lo)
    attn_kernel<<<dim3(NPAIR, H_), 256>>>();

    // O projection -> fp32 (reuse g_q)
    tgemm_kernel<<<dim3(2, D_/128, NPAIR), 256>>>(pAth, pAtl, pWoh, pWol, nullptr, pQ, nullptr, nullptr, D_, D_, BSD, SD, 0);

    // h1 = LN(x + oproj): fp32 into g_k, split into g_h1h/l
    addln_kernel<<<dim3(NPAIR, S_), 256>>>(x, pQ, g1, be1, pK);

    // FFN1: relu(h1 @ W1 + b1) -> bf16 hi/lo
    tgemm_kernel<<<dim3(2, FF_/128, NPAIR), 256>>>(pH1h, pH1l, pW1h, pW1l, b1, nullptr, pFFh, pFFl, D_, FF_, BSD, SD, 1);

    // FFN2: ff @ W2 + b2 -> fp32 (reuse g_v)
    tgemm_kernel<<<dim3(2, D_/128, NPAIR), 256>>>(pFFh, pFFl, pW2h, pW2l, b2, pV, nullptr, nullptr, FF_, D_, BSF, SF, 0);

    // combine
    final_kernel<<<dim3(B_, S_), 256>>>(pK, pV, g2, be2, out);
}

// round 4
// speedup vs baseline: 2.1594x; 1.0715x over previous
#include <cuda_runtime.h>
#include <cuda_bf16.h>
#include <math_constants.h>
#include <cstdint>

#define B_ 8
#define S_ 256
#define D_ 1024
#define H_ 16
#define E_ 4
#define FF_ 4096
#define HD_ 64
#define NPAIR (E_*B_)
#define SCALE_ 0.125f
#define EPS_FILL_F 2.2204460492503131e-16f
#define KCH 32
#define LDA 40                    // padded row length (elements) for 128x32 bf16 tiles
#define TILE_B (128*LDA*2)        // 10240 bytes per operand tile
#define STAGE_B (4*TILE_B)        // 40960 bytes per stage
#define SMEM_GEMM (2*STAGE_B)     // 81920 bytes

// ---------------- scratch (device globals: no allocations allowed) ----------
__device__ float g_xs[B_*D_];
__device__ float g_gates[B_*E_];
__device__ float g_q[(size_t)NPAIR*S_*D_];
__device__ float g_k[(size_t)NPAIR*S_*D_];
__device__ float g_v[(size_t)NPAIR*S_*D_];
__device__ __nv_bfloat16 g_xh[(size_t)B_*S_*D_];
__device__ __nv_bfloat16 g_xl[(size_t)B_*S_*D_];
__device__ __nv_bfloat16 g_ath[(size_t)NPAIR*S_*D_];
__device__ __nv_bfloat16 g_atl[(size_t)NPAIR*S_*D_];
__device__ __nv_bfloat16 g_h1h[(size_t)NPAIR*S_*D_];
__device__ __nv_bfloat16 g_h1l[(size_t)NPAIR*S_*D_];
__device__ __nv_bfloat16 g_ffh[(size_t)NPAIR*S_*FF_];
__device__ __nv_bfloat16 g_ffl[(size_t)NPAIR*S_*FF_];
__device__ __nv_bfloat16 g_wqTh[(size_t)E_*D_*D_];
__device__ __nv_bfloat16 g_wqTl[(size_t)E_*D_*D_];
__device__ __nv_bfloat16 g_wkTh[(size_t)E_*D_*D_];
__device__ __nv_bfloat16 g_wkTl[(size_t)E_*D_*D_];
__device__ __nv_bfloat16 g_wvTh[(size_t)E_*D_*D_];
__device__ __nv_bfloat16 g_wvTl[(size_t)E_*D_*D_];
__device__ __nv_bfloat16 g_woTh[(size_t)E_*D_*D_];
__device__ __nv_bfloat16 g_woTl[(size_t)E_*D_*D_];
__device__ __nv_bfloat16 g_w1Th[(size_t)E_*D_*FF_];
__device__ __nv_bfloat16 g_w1Tl[(size_t)E_*D_*FF_];
__device__ __nv_bfloat16 g_w2Th[(size_t)E_*D_*FF_];
__device__ __nv_bfloat16 g_w2Tl[(size_t)E_*D_*FF_];

// ---------------- helpers ----------------
__device__ __forceinline__ uint32_t smem_u32(const void* p){
    uint32_t a;
    asm("{ .reg .u64 t; cvta.to.shared.u64 t, %1; cvt.u32.u64 %0, t; }" : "=r"(a) : "l"(p));
    return a;
}
__device__ __forceinline__ void ldsm_x4(uint32_t (&r)[4], uint32_t addr){
    asm volatile("ldmatrix.sync.aligned.m8n8.x4.shared.b16 {%0,%1,%2,%3}, [%4];"
                 : "=r"(r[0]),"=r"(r[1]),"=r"(r[2]),"=r"(r[3]) : "r"(addr));
}
__device__ __forceinline__ void mma16816(float (&c)[4], const uint32_t (&a)[4], const uint32_t (&b)[2]){
    asm volatile("mma.sync.aligned.m16n8k16.row.col.f32.bf16.bf16.f32 "
                 "{%0,%1,%2,%3},{%4,%5,%6,%7},{%8,%9},{%0,%1,%2,%3};"
                 : "+f"(c[0]),"+f"(c[1]),"+f"(c[2]),"+f"(c[3])
                 : "r"(a[0]),"r"(a[1]),"r"(a[2]),"r"(a[3]),"r"(b[0]),"r"(b[1]));
}
__device__ __forceinline__ void cp16(uint32_t s, const void* g){
    asm volatile("cp.async.cg.shared.global [%0], [%1], 16;" :: "r"(s), "l"(g));
}
__device__ __forceinline__ void split_bf16(float v, __nv_bfloat16& h, __nv_bfloat16& l){
    h = __float2bfloat16(v);
    l = __float2bfloat16(v - __bfloat162float(h));
}

// ---------------- xs = x.sum(axis=1) ----------------
__global__ void sumx_kernel(const float* __restrict__ x)
{
    int d = blockIdx.x*256 + threadIdx.x;
    int b = blockIdx.y;
    const float* xp = x + (size_t)b*S_*D_ + d;
    float acc = 0.f;
    #pragma unroll 4
    for (int s = 0; s < S_; s++) acc += xp[(size_t)s*D_];
    g_xs[b*D_ + d] = acc;
}

// ---------------- noisy top-k gating + aux loss ----------------
__global__ void gate_kernel(const float* __restrict__ w_gate,
                            const float* __restrict__ w_noise,
                            const float* __restrict__ noise,
                            float* __restrict__ loss_out)
{
    __shared__ float s_clean[B_][E_], s_raw[B_][E_], s_prob[B_][E_], s_gate[B_][E_];
    int tid = threadIdx.x;
    int wid = tid >> 5, lane = tid & 31;
    {
        int b = wid >> 2, e = wid & 3;
        float ac = 0.f, ar = 0.f;
        for (int i = lane; i < D_; i += 32) {
            float xv = g_xs[b*D_ + i];
            ac = fmaf(xv, w_gate[i*E_ + e], ac);
            ar = fmaf(xv, w_noise[i*E_ + e], ar);
        }
        #pragma unroll
        for (int o = 16; o > 0; o >>= 1) {
            ac += __shfl_xor_sync(0xffffffffu, ac, o);
            ar += __shfl_xor_sync(0xffffffffu, ar, o);
        }
        if (lane == 0) { s_clean[b][e] = ac; s_raw[b][e] = ar; }
    }
    __syncthreads();
    if (tid < B_) {
        int b = tid;
        float clean[E_], noisy[E_], sd[E_];
        #pragma unroll
        for (int e = 0; e < E_; e++) {
            clean[e] = s_clean[b][e];
            float r = s_raw[b][e];
            float sp = fmaxf(r, 0.f) + log1pf(expf(-fabsf(r)));
            sd[e] = sp + 0.01f;
            noisy[e] = clean[e] + noise[b*E_ + e] * sd[e];
        }
        int ord[3]; bool used[E_] = {false,false,false,false};
        for (int s = 0; s < 3; s++) {
            int best = -1;
            for (int e = 0; e < E_; e++)
                if (!used[e] && (best < 0 || noisy[e] > noisy[best])) best = e;
            used[best] = true; ord[s] = best;
        }
        float l0 = noisy[ord[0]], l1 = noisy[ord[1]], l2 = noisy[ord[2]];
        float e1 = expf(l1 - l0);
        float inv = 1.f / (1.f + e1);
        #pragma unroll
        for (int e = 0; e < E_; e++) s_gate[b][e] = 0.f;
        s_gate[b][ord[0]] = inv;
        s_gate[b][ord[1]] = e1 * inv;
        #pragma unroll
        for (int e = 0; e < E_; e++) {
            bool isin = noisy[e] > l2;
            float thr = isin ? l2 : l1;
            s_prob[b][e] = normcdff((clean[e] - thr) / sd[e]);
            g_gates[b*E_ + e] = s_gate[b][e];
        }
    }
    __syncthreads();
    if (tid == 0) {
        float cv[2];
        for (int which = 0; which < 2; which++) {
            float v[E_];
            for (int e = 0; e < E_; e++) {
                float s = 0.f;
                for (int b = 0; b < B_; b++)
                    s += which ? s_prob[b][e] : s_gate[b][e];
                v[e] = s;
            }
            float m = (v[0]+v[1]+v[2]+v[3]) * 0.25f;
            float var = 0.f;
            for (int e = 0; e < E_; e++) { float dd = v[e]-m; var += dd*dd; }
            var *= (1.0f / (E_ - 1));
            cv[which] = var / (m*m + 1e-10f);
        }
        loss_out[0] = (cv[0] + cv[1]) * 0.01f;
    }
}

// ---------------- weight transpose + bf16 split:  W[e][K][N] -> Wt[e][N][K] --
__global__ void transpose_split_kernel(const float* __restrict__ W,
                                       __nv_bfloat16* __restrict__ oh,
                                       __nv_bfloat16* __restrict__ ol,
                                       int Kd, int Nd)
{
    __shared__ float t[32][33];
    int e = blockIdx.z;
    const float* We = W + (size_t)e*Kd*Nd;
    size_t ob = (size_t)e*Kd*Nd;
    int k0 = blockIdx.y*32, n0 = blockIdx.x*32;
    int tx = threadIdx.x, ty = threadIdx.y;  // 32 x 8
    #pragma unroll
    for (int i = 0; i < 32; i += 8)
        t[ty+i][tx] = We[(size_t)(k0+ty+i)*Nd + n0 + tx];
    __syncthreads();
    #pragma unroll
    for (int i = 0; i < 32; i += 8) {
        float v = t[tx][ty+i];
        size_t o = ob + (size_t)(n0+ty+i)*Kd + k0 + tx;
        __nv_bfloat16 h, l; split_bf16(v, h, l);
        oh[o] = h; ol[o] = l;
    }
}

// ---------------- elementwise bf16 split of x -------------------------------
__global__ void splitx_kernel(const float* __restrict__ in,
                              __nv_bfloat16* __restrict__ oh,
                              __nv_bfloat16* __restrict__ ol)
{
    int i = blockIdx.x*256 + threadIdx.x;
    float v = in[i];
    __nv_bfloat16 h, l; split_bf16(v, h, l);
    oh[i] = h; ol[i] = l;
}

// ---------------- HMMA bf16 split-3 GEMM, cp.async 2-stage pipeline ----------
// Up to 3 weight groups (Q/K/V fused): sel = blockIdx.y / (N/128)
__global__ __launch_bounds__(256) void tgemm_kernel(
    const __nv_bfloat16* __restrict__ Ah, const __nv_bfloat16* __restrict__ Al,
    const __nv_bfloat16* __restrict__ Bh0, const __nv_bfloat16* __restrict__ Bl0,
    const __nv_bfloat16* __restrict__ Bh1, const __nv_bfloat16* __restrict__ Bl1,
    const __nv_bfloat16* __restrict__ Bh2, const __nv_bfloat16* __restrict__ Bl2,
    const float* __restrict__ biasbase,
    float* __restrict__ outF0, float* __restrict__ outF1, float* __restrict__ outF2,
    __nv_bfloat16* __restrict__ outHi, __nv_bfloat16* __restrict__ outLo,
    int Kdim, int N, long sAe, long sAb, int doRelu)
{
    int p = blockIdx.z, e = p >> 3, b = p & 7;
    if (g_gates[b*E_ + e] == 0.f) return;

    int nGC = N >> 7;
    int sel = blockIdx.y / nGC;
    int colBase = (blockIdx.y % nGC) * 128;
    const __nv_bfloat16* Bh = (sel == 0) ? Bh0 : (sel == 1) ? Bh1 : Bh2;
    const __nv_bfloat16* Bl = (sel == 0) ? Bl0 : (sel == 1) ? Bl1 : Bl2;
    float* outF = (sel == 0) ? outF0 : (sel == 1) ? outF1 : outF2;

    extern __shared__ char smem[];
    uint32_t sm = smem_u32(smem);

    int tid = threadIdx.x, wid = tid >> 5, lane = tid & 31;
    int warpRow = wid >> 2;        // 0..1  (64 rows each)
    int warpCol = wid & 3;         // 0..3  (32 cols each)
    int rowBase = blockIdx.x * 128;

    const __nv_bfloat16* A_h = Ah + (size_t)e*sAe + (size_t)b*sAb + (size_t)rowBase*Kdim;
    const __nv_bfloat16* A_l = Al + (size_t)e*sAe + (size_t)b*sAb + (size_t)rowBase*Kdim;
    const __nv_bfloat16* B_h = Bh + ((size_t)e*N + colBase)*Kdim;
    const __nv_bfloat16* B_l = Bl + ((size_t)e*N + colBase)*Kdim;

    // per-thread ldmatrix byte offsets
    uint32_t aOff = (uint32_t)((lane & 15) * (LDA*2)) + ((lane >> 4) * 16);
    uint32_t bOff = (uint32_t)(((lane & 7) + ((lane >> 4) << 3)) * (LDA*2)) + (((lane >> 3) & 1) * 16);
    uint32_t aWarp = (uint32_t)(warpRow * 64) * (LDA*2);
    uint32_t bWarp = (uint32_t)(warpCol * 32) * (LDA*2);

    // per-thread cp.async indices (2 vectors per tile per thread)
    int r0 = tid >> 2, c0v = tid & 3;          // gid = tid
    int r1 = (256 + tid) >> 2, c1v = tid & 3;  // gid = 256+tid
    uint32_t so0 = (uint32_t)r0*(LDA*2) + (uint32_t)c0v*16;
    uint32_t so1 = (uint32_t)r1*(LDA*2) + (uint32_t)c1v*16;

    float acc[4][4][4];
    #pragma unroll
    for (int i = 0; i < 4; i++)
        #pragma unroll
        for (int j = 0; j < 4; j++)
            #pragma unroll
            for (int q = 0; q < 4; q++) acc[i][j][q] = 0.f;

    int nCh = Kdim / KCH;

    auto load_stage = [&](int kt, int st){
        size_t koff = (size_t)kt * KCH;
        uint32_t sb = sm + (uint32_t)st*STAGE_B;
        size_t g0 = (size_t)r0*Kdim + koff + (size_t)c0v*8;
        size_t g1 = (size_t)r1*Kdim + koff + (size_t)c1v*8;
        cp16(sb + so0,            A_h + g0);
        cp16(sb + so1,            A_h + g1);
        cp16(sb + TILE_B + so0,   A_l + g0);
        cp16(sb + TILE_B + so1,   A_l + g1);
        cp16(sb + 2*TILE_B + so0, B_h + g0);
        cp16(sb + 2*TILE_B + so1, B_h + g1);
        cp16(sb + 3*TILE_B + so0, B_l + g0);
        cp16(sb + 3*TILE_B + so1, B_l + g1);
        asm volatile("cp.async.commit_group;");
    };

    load_stage(0, 0);
    for (int kt = 0; kt < nCh; kt++) {
        int st = kt & 1;
        if (kt + 1 < nCh) {
            load_stage(kt + 1, st ^ 1);
            asm volatile("cp.async.wait_group 1;");
        } else {
            asm volatile("cp.async.wait_group 0;");
        }
        __syncthreads();

        uint32_t sAh32 = sm + (uint32_t)st*STAGE_B;
        uint32_t sAl32 = sAh32 + TILE_B;
        uint32_t sBh32 = sAh32 + 2*TILE_B;
        uint32_t sBl32 = sAh32 + 3*TILE_B;

        #pragma unroll
        for (int k16 = 0; k16 < 2; k16++) {
            uint32_t kb = (uint32_t)k16 * 32;
            uint32_t a[4][4], bh[4][2], bl[4][2];
            #pragma unroll
            for (int np = 0; np < 2; np++) {
                uint32_t r4[4];
                ldsm_x4(r4, sBh32 + bWarp + bOff + np*(16*LDA*2) + kb);
                bh[2*np][0] = r4[0]; bh[2*np][1] = r4[1];
                bh[2*np+1][0] = r4[2]; bh[2*np+1][1] = r4[3];
                ldsm_x4(r4, sBl32 + bWarp + bOff + np*(16*LDA*2) + kb);
                bl[2*np][0] = r4[0]; bl[2*np][1] = r4[1];
                bl[2*np+1][0] = r4[2]; bl[2*np+1][1] = r4[3];
            }
            #pragma unroll
            for (int mt = 0; mt < 4; mt++)
                ldsm_x4(a[mt], sAh32 + aWarp + aOff + mt*(16*LDA*2) + kb);
            #pragma unroll
            for (int mt = 0; mt < 4; mt++)
                #pragma unroll
                for (int nt = 0; nt < 4; nt++)
                    mma16816(acc[mt][nt], a[mt], bh[nt]);
            #pragma unroll
            for (int mt = 0; mt < 4; mt++)
                #pragma unroll
                for (int nt = 0; nt < 4; nt++)
                    mma16816(acc[mt][nt], a[mt], bl[nt]);
            #pragma unroll
            for (int mt = 0; mt < 4; mt++)
                ldsm_x4(a[mt], sAl32 + aWarp + aOff + mt*(16*LDA*2) + kb);
            #pragma unroll
            for (int mt = 0; mt < 4; mt++)
                #pragma unroll
                for (int nt = 0; nt < 4; nt++)
                    mma16816(acc[mt][nt], a[mt], bh[nt]);
        }
        __syncthreads();
    }

    // ---------------- epilogue ----------------
    const float* bias = biasbase ? biasbase + (size_t)e*N : nullptr;
    int mWarp = rowBase + warpRow*64;
    int nWarp = colBase + warpCol*32;
    int rq = lane >> 2, cq = (lane & 3)*2;

    #pragma unroll
    for (int mt = 0; mt < 4; mt++) {
        #pragma unroll
        for (int nt = 0; nt < 4; nt++) {
            int col = nWarp + nt*8 + cq;
            float b0 = bias ? bias[col] : 0.f;
            float b1 = bias ? bias[col+1] : 0.f;
            #pragma unroll
            for (int half = 0; half < 2; half++) {
                int row = mWarp + mt*16 + rq + half*8;
                float v0 = acc[mt][nt][2*half+0] + b0;
                float v1 = acc[mt][nt][2*half+1] + b1;
                if (doRelu) { v0 = fmaxf(v0, 0.f); v1 = fmaxf(v1, 0.f); }
                size_t o = ((size_t)p*S_ + row)*N + col;
                if (outF) *(float2*)(outF + o) = make_float2(v0, v1);
                if (outHi) {
                    __nv_bfloat16 h0,l0,h1,l1;
                    split_bf16(v0, h0, l0); split_bf16(v1, h1, l1);
                    uint32_t hw = (uint32_t)__bfloat16_as_ushort(h0) | ((uint32_t)__bfloat16_as_ushort(h1) << 16);
                    uint32_t lw = (uint32_t)__bfloat16_as_ushort(l0) | ((uint32_t)__bfloat16_as_ushort(l1) << 16);
                    *(uint32_t*)(outHi + o) = hw;
                    *(uint32_t*)(outLo + o) = lw;
                }
            }
        }
    }
}

// ---------------- fused causal attention (writes bf16 hi/lo) ----------------
__global__ __launch_bounds__(256) void attn_kernel()
{
    int p = blockIdx.x, h = blockIdx.y;
    int e = p / B_, b = p % B_;
    if (g_gates[b*E_ + e] == 0.f) return;
    __shared__ __align__(16) float Ks[64][HD_];
    __shared__ __align__(16) float Vs[64][HD_];
    int qi = threadIdx.x;
    float qreg[HD_];
    {
        const float* qp = &g_q[((size_t)p*S_ + qi)*D_ + h*HD_];
        #pragma unroll
        for (int i = 0; i < HD_; i += 4) {
            float4 t = *reinterpret_cast<const float4*>(qp + i);
            qreg[i] = t.x; qreg[i+1] = t.y; qreg[i+2] = t.z; qreg[i+3] = t.w;
        }
    }
    float acc[HD_];
    #pragma unroll
    for (int i = 0; i < HD_; i++) acc[i] = 0.f;
    float m = -CUDART_INF_F, l = 0.f;

    for (int t = 0; t < S_/64; t++) {
        #pragma unroll
        for (int pass = 0; pass < 4; pass++) {
            int r = pass*16 + (threadIdx.x >> 4);
            int c = (threadIdx.x & 15) * 4;
            size_t off = ((size_t)p*S_ + t*64 + r)*D_ + h*HD_ + c;
            *reinterpret_cast<float4*>(&Ks[r][c]) = *reinterpret_cast<const float4*>(&g_k[off]);
            *reinterpret_cast<float4*>(&Vs[r][c]) = *reinterpret_cast<const float4*>(&g_v[off]);
        }
        __syncthreads();
        int kmax = qi - t*64;
        if (kmax > 63) kmax = 63;
        for (int kk = 0; kk <= kmax; kk++) {
            float s = 0.f;
            const float* kr = Ks[kk];
            #pragma unroll
            for (int i = 0; i < HD_; i++) s = fmaf(qreg[i], kr[i], s);
            s *= SCALE_;
            float mn = fmaxf(m, s);
            float corr = expf(m - mn);
            float pw = expf(s - mn);
            l = l*corr + pw;
            const float* vr = Vs[kk];
            #pragma unroll
            for (int i = 0; i < HD_; i++) acc[i] = fmaf(acc[i], corr, pw*vr[i]);
            m = mn;
        }
        __syncthreads();
    }
    float invl = 1.f / l;
    size_t ob = ((size_t)p*S_ + qi)*D_ + h*HD_;
    #pragma unroll
    for (int i = 0; i < HD_; i++) {
        float val = acc[i]*invl;
        __nv_bfloat16 hh, ll; split_bf16(val, hh, ll);
        g_ath[ob + i] = hh; g_atl[ob + i] = ll;
    }
}

// ---------------- block reduce (sum, sumsq), blockDim = 256 -----------------
__device__ __forceinline__ float2 block_reduce2(float a, float b)
{
    __shared__ float2 sh[9];
    int tid = threadIdx.x, lane = tid & 31, wid = tid >> 5;
    #pragma unroll
    for (int o = 16; o > 0; o >>= 1) {
        a += __shfl_xor_sync(0xffffffffu, a, o);
        b += __shfl_xor_sync(0xffffffffu, b, o);
    }
    if (lane == 0) sh[wid] = make_float2(a, b);
    __syncthreads();
    if (tid == 0) {
        float sa = 0.f, sb = 0.f;
        #pragma unroll
        for (int w = 0; w < 8; w++) { sa += sh[w].x; sb += sh[w].y; }
        sh[8] = make_float2(sa, sb);
    }
    __syncthreads();
    float2 r = sh[8];
    __syncthreads();
    return r;
}

// ---------------- h1 = LN(x + oproj)*g1+be1 : fp32 + bf16 split -------------
__global__ __launch_bounds__(256) void addln_kernel(
    const float* __restrict__ xbase, const float* __restrict__ res,
    const float* __restrict__ gain, const float* __restrict__ beta,
    float* __restrict__ out)
{
    int p = blockIdx.x; int e = p / B_, b = p % B_;
    if (g_gates[b*E_ + e] == 0.f) return;
    int s = blockIdx.y, tid = threadIdx.x;
    const float* xr = xbase + ((size_t)b*S_ + s)*D_;
    const float* rr = res + ((size_t)p*S_ + s)*D_;
    float v[4]; float sum = 0.f, sq = 0.f;
    #pragma unroll
    for (int j = 0; j < 4; j++) {
        int i = tid + j*256;
        float t = xr[i] + rr[i];
        v[j] = t; sum += t; sq = fmaf(t, t, sq);
    }
    float2 r = block_reduce2(sum, sq);
    float mean = r.x * (1.f/D_);
    float var = r.y * (1.f/D_) - mean*mean;
    float rstd = rsqrtf(var + 1e-5f);
    size_t ob = ((size_t)p*S_ + s)*D_;
    #pragma unroll
    for (int j = 0; j < 4; j++) {
        int i = tid + j*256;
        float o = (v[j] - mean)*rstd*gain[e*D_ + i] + beta[e*D_ + i];
        out[ob + i] = o;
        __nv_bfloat16 hh, ll; split_bf16(o, hh, ll);
        g_h1h[ob + i] = hh; g_h1l[ob + i] = ll;
    }
}

// ---------------- y = sum_e gate * LN(h1 + ff2), eps-fill -------------------
__global__ __launch_bounds__(256) void final_kernel(
    const float* __restrict__ h1, const float* __restrict__ f2,
    const float* __restrict__ g2, const float* __restrict__ be2,
    float* __restrict__ y)
{
    int b = blockIdx.x, s = blockIdx.y, tid = threadIdx.x;
    float acc[4] = {0.f, 0.f, 0.f, 0.f};
    for (int e = 0; e < E_; e++) {
        float gv = g_gates[b*E_ + e];
        if (gv == 0.f) continue;
        int p = e*B_ + b;
        const float* hr = h1 + ((size_t)p*S_ + s)*D_;
        const float* fr = f2 + ((size_t)p*S_ + s)*D_;
        float v[4]; float sum = 0.f, sq = 0.f;
        #pragma unroll
        for (int j = 0; j < 4; j++) {
            int i = tid + j*256;
            float t = hr[i] + fr[i];
            v[j] = t; sum += t; sq = fmaf(t, t, sq);
        }
        float2 r = block_reduce2(sum, sq);
        float mean = r.x * (1.f/D_);
        float var = r.y * (1.f/D_) - mean*mean;
        float rstd = rsqrtf(var + 1e-5f);
        #pragma unroll
        for (int j = 0; j < 4; j++) {
            int i = tid + j*256;
            acc[j] += gv * ((v[j]-mean)*rstd*g2[e*D_+i] + be2[e*D_+i]);
        }
    }
    float* yr = y + ((size_t)b*S_ + s)*D_;
    #pragma unroll
    for (int j = 0; j < 4; j++) {
        int i = tid + j*256;
        float o = acc[j];
        if (o == 0.f) o = EPS_FILL_F;
        yr[i] = o;
    }
}

// ---------------- launch ----------------------------------------------------
extern "C" void kernel_launch(void* const* d_in, const int* in_sizes, int n_in,
                              void* d_out, int out_size)
{
    const float* x       = (const float*)d_in[0];
    const float* noise   = (const float*)d_in[2];
    const float* w_gate  = (const float*)d_in[3];
    const float* w_noise = (const float*)d_in[4];
    const float* Wq      = (const float*)d_in[5];
    const float* Wk      = (const float*)d_in[6];
    const float* Wv      = (const float*)d_in[7];
    const float* Wo      = (const float*)d_in[8];
    const float* W1      = (const float*)d_in[9];
    const float* b1      = (const float*)d_in[10];
    const float* W2      = (const float*)d_in[11];
    const float* b2      = (const float*)d_in[12];
    const float* g1      = (const float*)d_in[13];
    const float* be1     = (const float*)d_in[14];
    const float* g2      = (const float*)d_in[15];
    const float* be2     = (const float*)d_in[16];
    float* out = (float*)d_out;

    float *pQ, *pK, *pV;
    __nv_bfloat16 *pXh, *pXl, *pAth, *pAtl, *pH1h, *pH1l, *pFFh, *pFFl;
    __nv_bfloat16 *pWqh, *pWql, *pWkh, *pWkl, *pWvh, *pWvl, *pWoh, *pWol;
    __nv_bfloat16 *pW1h, *pW1l, *pW2h, *pW2l;
    cudaGetSymbolAddress((void**)&pQ,   g_q);
    cudaGetSymbolAddress((void**)&pK,   g_k);
    cudaGetSymbolAddress((void**)&pV,   g_v);
    cudaGetSymbolAddress((void**)&pXh,  g_xh);
    cudaGetSymbolAddress((void**)&pXl,  g_xl);
    cudaGetSymbolAddress((void**)&pAth, g_ath);
    cudaGetSymbolAddress((void**)&pAtl, g_atl);
    cudaGetSymbolAddress((void**)&pH1h, g_h1h);
    cudaGetSymbolAddress((void**)&pH1l, g_h1l);
    cudaGetSymbolAddress((void**)&pFFh, g_ffh);
    cudaGetSymbolAddress((void**)&pFFl, g_ffl);
    cudaGetSymbolAddress((void**)&pWqh, g_wqTh);
    cudaGetSymbolAddress((void**)&pWql, g_wqTl);
    cudaGetSymbolAddress((void**)&pWkh, g_wkTh);
    cudaGetSymbolAddress((void**)&pWkl, g_wkTl);
    cudaGetSymbolAddress((void**)&pWvh, g_wvTh);
    cudaGetSymbolAddress((void**)&pWvl, g_wvTl);
    cudaGetSymbolAddress((void**)&pWoh, g_woTh);
    cudaGetSymbolAddress((void**)&pWol, g_woTl);
    cudaGetSymbolAddress((void**)&pW1h, g_w1Th);
    cudaGetSymbolAddress((void**)&pW1l, g_w1Tl);
    cudaGetSymbolAddress((void**)&pW2h, g_w2Th);
    cudaGetSymbolAddress((void**)&pW2l, g_w2Tl);

    cudaFuncSetAttribute(tgemm_kernel, cudaFuncAttributeMaxDynamicSharedMemorySize, SMEM_GEMM);

    const long SD  = (long)S_*D_;
    const long BSD = (long)B_*S_*D_;
    const long SF  = (long)S_*FF_;
    const long BSF = (long)B_*S_*FF_;

    // gating path
    sumx_kernel<<<dim3(D_/256, B_), 256>>>(x);
    gate_kernel<<<1, 1024>>>(w_gate, w_noise, noise, out + (size_t)B_*S_*D_);

    // weight transposes + splits
    transpose_split_kernel<<<dim3(D_/32,  D_/32, E_), dim3(32,8)>>>(Wq, pWqh, pWql, D_, D_);
    transpose_split_kernel<<<dim3(D_/32,  D_/32, E_), dim3(32,8)>>>(Wk, pWkh, pWkl, D_, D_);
    transpose_split_kernel<<<dim3(D_/32,  D_/32, E_), dim3(32,8)>>>(Wv, pWvh, pWvl, D_, D_);
    transpose_split_kernel<<<dim3(D_/32,  D_/32, E_), dim3(32,8)>>>(Wo, pWoh, pWol, D_, D_);
    transpose_split_kernel<<<dim3(FF_/32, D_/32, E_), dim3(32,8)>>>(W1, pW1h, pW1l, D_, FF_);
    transpose_split_kernel<<<dim3(D_/32, FF_/32, E_), dim3(32,8)>>>(W2, pW2h, pW2l, FF_, D_);

    // x split
    splitx_kernel<<<(B_*S_*D_)/256, 256>>>(x, pXh, pXl);

    // fused QKV projections: sel = blockIdx.y/8 picks {Wq,Wk,Wv} and {pQ,pK,pV}
    tgemm_kernel<<<dim3(2, 3*(D_/128), NPAIR), 256, SMEM_GEMM>>>(
        pXh, pXl, pWqh, pWql, pWkh, pWkl, pWvh, pWvl,
        nullptr, pQ, pK, pV, nullptr, nullptr, D_, D_, 0, SD, 0);

    // attention (fp32 in, writes bf16 hi/lo)
    attn_kernel<<<dim3(NPAIR, H_), 256>>>();

    // O projection -> fp32 (reuse g_q)
    tgemm_kernel<<<dim3(2, D_/128, NPAIR), 256, SMEM_GEMM>>>(
        pAth, pAtl, pWoh, pWol, pWoh, pWol, pWoh, pWol,
        nullptr, pQ, nullptr, nullptr, nullptr, nullptr, D_, D_, BSD, SD, 0);

    // h1 = LN(x + oproj): fp32 into g_k, split into g_h1h/l
    addln_kernel<<<dim3(NPAIR, S_), 256>>>(x, pQ, g1, be1, pK);

    // FFN1: relu(h1 @ W1 + b1) -> bf16 hi/lo
    tgemm_kernel<<<dim3(2, FF_/128, NPAIR), 256, SMEM_GEMM>>>(
        pH1h, pH1l, pW1h, pW1l, pW1h, pW1l, pW1h, pW1l,
        b1, nullptr, nullptr, nullptr, pFFh, pFFl, D_, FF_, BSD, SD, 1);

    // FFN2: ff @ W2 + b2 -> fp32 (reuse g_v)
    tgemm_kernel<<<dim3(2, D_/128, NPAIR), 256, SMEM_GEMM>>>(
        pFFh, pFFl, pW2h, pW2l, pW2h, pW2l, pW2h, pW2l,
        b2, pV, nullptr, nullptr, nullptr, nullptr, FF_, D_, BSF, SF, 0);

    // combine
    final_kernel<<<dim3(B_, S_), 256>>>(pK, pV, g2, be2, out);
}

// round 11
// speedup vs baseline: 3.9701x; 1.8385x over previous
#include <cuda_runtime.h>
#include <cuda_fp16.h>
#include <math_constants.h>
#include <cstdint>

#define B_ 8
#define S_ 256
#define D_ 1024
#define H_ 16
#define E_ 4
#define FF_ 4096
#define HD_ 64
#define NPAIR (E_*B_)
#define SCALE_ 0.125f
#define EPS_FILL_F 2.2204460492503131e-16f
#define KCH 32
#define LDA 40                    // padded row length (elements) for 128x32 fp16 tiles
#define TILE_B (128*LDA*2)        // 10240 bytes per operand tile
#define STAGE_B (2*TILE_B)        // 20480 bytes per stage (A + B)
#define SMEM_GEMM (2*STAGE_B)     // 40960 bytes

// ---------------- scratch (device globals: no allocations allowed) ----------
__device__ float g_xs[B_*D_];
__device__ float g_gates[B_*E_];
__device__ float g_q[(size_t)NPAIR*S_*D_];
__device__ float g_k[(size_t)NPAIR*S_*D_];   // later reused as h1 (fp32)
__device__ float g_v[(size_t)NPAIR*S_*D_];   // later reused as ffn2 out (fp32)
__device__ __half g_xh[(size_t)B_*S_*D_];
__device__ __half g_ath[(size_t)NPAIR*S_*D_];
__device__ __half g_h1h[(size_t)NPAIR*S_*D_];
__device__ __half g_ffh[(size_t)NPAIR*S_*FF_];
// transposed fp16 weights [e][N][K]
__device__ __half g_wqT[(size_t)E_*D_*D_];
__device__ __half g_wkT[(size_t)E_*D_*D_];
__device__ __half g_wvT[(size_t)E_*D_*D_];
__device__ __half g_woT[(size_t)E_*D_*D_];
__device__ __half g_w1T[(size_t)E_*D_*FF_];
__device__ __half g_w2T[(size_t)E_*D_*FF_];

// ---------------- helpers ----------------
__device__ __forceinline__ uint32_t smem_u32(const void* p){
    uint32_t a;
    asm("{ .reg .u64 t; cvta.to.shared.u64 t, %1; cvt.u32.u64 %0, t; }" : "=r"(a) : "l"(p));
    return a;
}
__device__ __forceinline__ void ldsm_x4(uint32_t (&r)[4], uint32_t addr){
    asm volatile("ldmatrix.sync.aligned.m8n8.x4.shared.b16 {%0,%1,%2,%3}, [%4];"
                 : "=r"(r[0]),"=r"(r[1]),"=r"(r[2]),"=r"(r[3]) : "r"(addr));
}
__device__ __forceinline__ void mma16816(float (&c)[4], const uint32_t (&a)[4], const uint32_t (&b)[2]){
    asm volatile("mma.sync.aligned.m16n8k16.row.col.f32.f16.f16.f32 "
                 "{%0,%1,%2,%3},{%4,%5,%6,%7},{%8,%9},{%0,%1,%2,%3};"
                 : "+f"(c[0]),"+f"(c[1]),"+f"(c[2]),"+f"(c[3])
                 : "r"(a[0]),"r"(a[1]),"r"(a[2]),"r"(a[3]),"r"(b[0]),"r"(b[1]));
}
__device__ __forceinline__ void cp16(uint32_t s, const void* g){
    asm volatile("cp.async.cg.shared.global [%0], [%1], 16;" :: "r"(s), "l"(g));
}

// ---------------- xs = x.sum(axis=1) ----------------
__global__ void sumx_kernel(const float* __restrict__ x)
{
    int d = blockIdx.x*256 + threadIdx.x;
    int b = blockIdx.y;
    const float* xp = x + (size_t)b*S_*D_ + d;
    float acc = 0.f;
    #pragma unroll 4
    for (int s = 0; s < S_; s++) acc += xp[(size_t)s*D_];
    g_xs[b*D_ + d] = acc;
}

// ---------------- noisy top-k gating + aux loss ----------------
__global__ void gate_kernel(const float* __restrict__ w_gate,
                            const float* __restrict__ w_noise,
                            const float* __restrict__ noise,
                            float* __restrict__ loss_out)
{
    __shared__ float s_clean[B_][E_], s_raw[B_][E_], s_prob[B_][E_], s_gate[B_][E_];
    int tid = threadIdx.x;
    int wid = tid >> 5, lane = tid & 31;
    {
        int b = wid >> 2, e = wid & 3;
        float ac = 0.f, ar = 0.f;
        for (int i = lane; i < D_; i += 32) {
            float xv = g_xs[b*D_ + i];
            ac = fmaf(xv, w_gate[i*E_ + e], ac);
            ar = fmaf(xv, w_noise[i*E_ + e], ar);
        }
        #pragma unroll
        for (int o = 16; o > 0; o >>= 1) {
            ac += __shfl_xor_sync(0xffffffffu, ac, o);
            ar += __shfl_xor_sync(0xffffffffu, ar, o);
        }
        if (lane == 0) { s_clean[b][e] = ac; s_raw[b][e] = ar; }
    }
    __syncthreads();
    if (tid < B_) {
        int b = tid;
        float clean[E_], noisy[E_], sd[E_];
        #pragma unroll
        for (int e = 0; e < E_; e++) {
            clean[e] = s_clean[b][e];
            float r = s_raw[b][e];
            float sp = fmaxf(r, 0.f) + log1pf(expf(-fabsf(r)));
            sd[e] = sp + 0.01f;
            noisy[e] = clean[e] + noise[b*E_ + e] * sd[e];
        }
        int ord[3]; bool used[E_] = {false,false,false,false};
        for (int s = 0; s < 3; s++) {
            int best = -1;
            for (int e = 0; e < E_; e++)
                if (!used[e] && (best < 0 || noisy[e] > noisy[best])) best = e;
            used[best] = true; ord[s] = best;
        }
        float l0 = noisy[ord[0]], l1 = noisy[ord[1]], l2 = noisy[ord[2]];
        float e1 = expf(l1 - l0);
        float inv = 1.f / (1.f + e1);
        #pragma unroll
        for (int e = 0; e < E_; e++) s_gate[b][e] = 0.f;
        s_gate[b][ord[0]] = inv;
        s_gate[b][ord[1]] = e1 * inv;
        #pragma unroll
        for (int e = 0; e < E_; e++) {
            bool isin = noisy[e] > l2;
            float thr = isin ? l2 : l1;
            s_prob[b][e] = normcdff((clean[e] - thr) / sd[e]);
            g_gates[b*E_ + e] = s_gate[b][e];
        }
    }
    __syncthreads();
    if (tid == 0) {
        float cv[2];
        for (int which = 0; which < 2; which++) {
            float v[E_];
            for (int e = 0; e < E_; e++) {
                float s = 0.f;
                for (int b = 0; b < B_; b++)
                    s += which ? s_prob[b][e] : s_gate[b][e];
                v[e] = s;
            }
            float m = (v[0]+v[1]+v[2]+v[3]) * 0.25f;
            float var = 0.f;
            for (int e = 0; e < E_; e++) { float dd = v[e]-m; var += dd*dd; }
            var *= (1.0f / (E_ - 1));
            cv[which] = var / (m*m + 1e-10f);
        }
        loss_out[0] = (cv[0] + cv[1]) * 0.01f;
    }
}

// ---------------- weight transpose to fp16:  W[e][K][N] -> Wt[e][N][K] ------
__global__ void transpose_h_kernel(const float* __restrict__ W,
                                   __half* __restrict__ o,
                                   int Kd, int Nd)
{
    __shared__ float t[32][33];
    int e = blockIdx.z;
    const float* We = W + (size_t)e*Kd*Nd;
    size_t ob = (size_t)e*Kd*Nd;
    int k0 = blockIdx.y*32, n0 = blockIdx.x*32;
    int tx = threadIdx.x, ty = threadIdx.y;  // 32 x 8
    #pragma unroll
    for (int i = 0; i < 32; i += 8)
        t[ty+i][tx] = We[(size_t)(k0+ty+i)*Nd + n0 + tx];
    __syncthreads();
    #pragma unroll
    for (int i = 0; i < 32; i += 8) {
        float v = t[tx][ty+i];
        o[ob + (size_t)(n0+ty+i)*Kd + k0 + tx] = __float2half_rn(v);
    }
}

// ---------------- elementwise fp16 convert of x -----------------------------
__global__ void convx_kernel(const float* __restrict__ in, __half* __restrict__ o)
{
    int i = blockIdx.x*256 + threadIdx.x;
    o[i] = __float2half_rn(in[i]);
}

// ---------------- HMMA fp16 GEMM, cp.async 2-stage pipeline ------------------
// Up to 3 weight groups (Q/K/V fused): sel = blockIdx.y / (N/128)
__global__ __launch_bounds__(256) void tgemm_kernel(
    const __half* __restrict__ A0,
    const __half* __restrict__ Bw0, const __half* __restrict__ Bw1, const __half* __restrict__ Bw2,
    const float* __restrict__ biasbase,
    float* __restrict__ outF0, float* __restrict__ outF1, float* __restrict__ outF2,
    __half* __restrict__ outH,
    int Kdim, int N, long sAe, long sAb, int doRelu)
{
    int p = blockIdx.z, e = p >> 3, b = p & 7;
    if (g_gates[b*E_ + e] == 0.f) return;

    int nGC = N >> 7;
    int sel = blockIdx.y / nGC;
    int colBase = (blockIdx.y % nGC) * 128;
    const __half* Bw = (sel == 0) ? Bw0 : (sel == 1) ? Bw1 : Bw2;
    float* outF = (sel == 0) ? outF0 : (sel == 1) ? outF1 : outF2;

    extern __shared__ char smem[];
    uint32_t sm = smem_u32(smem);

    int tid = threadIdx.x, wid = tid >> 5, lane = tid & 31;
    int warpRow = wid >> 2;        // 0..1  (64 rows each)
    int warpCol = wid & 3;         // 0..3  (32 cols each)
    int rowBase = blockIdx.x * 128;

    const __half* Aptr = A0 + (size_t)e*sAe + (size_t)b*sAb + (size_t)rowBase*Kdim;
    const __half* Bptr = Bw + ((size_t)e*N + colBase)*Kdim;

    // per-thread ldmatrix byte offsets
    uint32_t aOff = (uint32_t)((lane & 15) * (LDA*2)) + ((lane >> 4) * 16);
    uint32_t bOff = (uint32_t)(((lane & 7) + ((lane >> 4) << 3)) * (LDA*2)) + (((lane >> 3) & 1) * 16);
    uint32_t aWarp = (uint32_t)(warpRow * 64) * (LDA*2);
    uint32_t bWarp = (uint32_t)(warpCol * 32) * (LDA*2);

    // per-thread cp.async indices (2 vectors per tile per thread)
    int r0 = tid >> 2, c0v = tid & 3;
    int r1 = (256 + tid) >> 2, c1v = tid & 3;
    uint32_t so0 = (uint32_t)r0*(LDA*2) + (uint32_t)c0v*16;
    uint32_t so1 = (uint32_t)r1*(LDA*2) + (uint32_t)c1v*16;

    float acc[4][4][4];
    #pragma unroll
    for (int i = 0; i < 4; i++)
        #pragma unroll
        for (int j = 0; j < 4; j++)
            #pragma unroll
            for (int q = 0; q < 4; q++) acc[i][j][q] = 0.f;

    int nCh = Kdim / KCH;

    auto load_stage = [&](int kt, int st){
        size_t koff = (size_t)kt * KCH;
        uint32_t sb = sm + (uint32_t)st*STAGE_B;
        size_t g0 = (size_t)r0*Kdim + koff + (size_t)c0v*8;
        size_t g1 = (size_t)r1*Kdim + koff + (size_t)c1v*8;
        cp16(sb + so0,          Aptr + g0);
        cp16(sb + so1,          Aptr + g1);
        cp16(sb + TILE_B + so0, Bptr + g0);
        cp16(sb + TILE_B + so1, Bptr + g1);
        asm volatile("cp.async.commit_group;");
    };

    load_stage(0, 0);
    for (int kt = 0; kt < nCh; kt++) {
        int st = kt & 1;
        if (kt + 1 < nCh) {
            load_stage(kt + 1, st ^ 1);
            asm volatile("cp.async.wait_group 1;");
        } else {
            asm volatile("cp.async.wait_group 0;");
        }
        __syncthreads();

        uint32_t sA32 = sm + (uint32_t)st*STAGE_B;
        uint32_t sB32 = sA32 + TILE_B;

        #pragma unroll
        for (int k16 = 0; k16 < 2; k16++) {
            uint32_t kb = (uint32_t)k16 * 32;
            uint32_t a[4][4], bh[4][2];
            #pragma unroll
            for (int np = 0; np < 2; np++) {
                uint32_t r4[4];
                ldsm_x4(r4, sB32 + bWarp + bOff + np*(16*LDA*2) + kb);
                bh[2*np][0] = r4[0]; bh[2*np][1] = r4[1];
                bh[2*np+1][0] = r4[2]; bh[2*np+1][1] = r4[3];
            }
            #pragma unroll
            for (int mt = 0; mt < 4; mt++)
                ldsm_x4(a[mt], sA32 + aWarp + aOff + mt*(16*LDA*2) + kb);
            #pragma unroll
            for (int mt = 0; mt < 4; mt++)
                #pragma unroll
                for (int nt = 0; nt < 4; nt++)
                    mma16816(acc[mt][nt], a[mt], bh[nt]);
        }
        __syncthreads();
    }

    // ---------------- epilogue ----------------
    const float* bias = biasbase ? biasbase + (size_t)e*N : nullptr;
    int mWarp = rowBase + warpRow*64;
    int nWarp = colBase + warpCol*32;
    int rq = lane >> 2, cq = (lane & 3)*2;

    #pragma unroll
    for (int mt = 0; mt < 4; mt++) {
        #pragma unroll
        for (int nt = 0; nt < 4; nt++) {
            int col = nWarp + nt*8 + cq;
            float b0 = bias ? bias[col] : 0.f;
            float b1 = bias ? bias[col+1] : 0.f;
            #pragma unroll
            for (int half = 0; half < 2; half++) {
                int row = mWarp + mt*16 + rq + half*8;
                float v0 = acc[mt][nt][2*half+0] + b0;
                float v1 = acc[mt][nt][2*half+1] + b1;
                if (doRelu) { v0 = fmaxf(v0, 0.f); v1 = fmaxf(v1, 0.f); }
                size_t o = ((size_t)p*S_ + row)*N + col;
                if (outF) *(float2*)(outF + o) = make_float2(v0, v1);
                if (outH) {
                    __half2 hv = __floats2half2_rn(v0, v1);
                    *(__half2*)(outH + o) = hv;
                }
            }
        }
    }
}

// ---------------- fused causal attention (writes fp16) ----------------------
__global__ __launch_bounds__(256) void attn_kernel()
{
    int p = blockIdx.x, h = blockIdx.y;
    int e = p / B_, b = p % B_;
    if (g_gates[b*E_ + e] == 0.f) return;
    __shared__ __align__(16) float Ks[64][HD_];
    __shared__ __align__(16) float Vs[64][HD_];
    int qi = threadIdx.x;
    float qreg[HD_];
    {
        const float* qp = &g_q[((size_t)p*S_ + qi)*D_ + h*HD_];
        #pragma unroll
        for (int i = 0; i < HD_; i += 4) {
            float4 t = *reinterpret_cast<const float4*>(qp + i);
            qreg[i] = t.x; qreg[i+1] = t.y; qreg[i+2] = t.z; qreg[i+3] = t.w;
        }
    }
    float acc[HD_];
    #pragma unroll
    for (int i = 0; i < HD_; i++) acc[i] = 0.f;
    float m = -CUDART_INF_F, l = 0.f;

    for (int t = 0; t < S_/64; t++) {
        #pragma unroll
        for (int pass = 0; pass < 4; pass++) {
            int r = pass*16 + (threadIdx.x >> 4);
            int c = (threadIdx.x & 15) * 4;
            size_t off = ((size_t)p*S_ + t*64 + r)*D_ + h*HD_ + c;
            *reinterpret_cast<float4*>(&Ks[r][c]) = *reinterpret_cast<const float4*>(&g_k[off]);
            *reinterpret_cast<float4*>(&Vs[r][c]) = *reinterpret_cast<const float4*>(&g_v[off]);
        }
        __syncthreads();
        int kmax = qi - t*64;
        if (kmax > 63) kmax = 63;
        for (int kk = 0; kk <= kmax; kk++) {
            float s = 0.f;
            const float* kr = Ks[kk];
            #pragma unroll
            for (int i = 0; i < HD_; i++) s = fmaf(qreg[i], kr[i], s);
            s *= SCALE_;
            float mn = fmaxf(m, s);
            float corr = expf(m - mn);
            float pw = expf(s - mn);
            l = l*corr + pw;
            const float* vr = Vs[kk];
            #pragma unroll
            for (int i = 0; i < HD_; i++) acc[i] = fmaf(acc[i], corr, pw*vr[i]);
            m = mn;
        }
        __syncthreads();
    }
    float invl = 1.f / l;
    size_t ob = ((size_t)p*S_ + qi)*D_ + h*HD_;
    #pragma unroll
    for (int i = 0; i < HD_; i += 2) {
        __half2 hv = __floats2half2_rn(acc[i]*invl, acc[i+1]*invl);
        *(__half2*)(&g_ath[ob + i]) = hv;
    }
}

// ---------------- block reduce (sum, sumsq), blockDim = 256 -----------------
__device__ __forceinline__ float2 block_reduce2(float a, float b)
{
    __shared__ float2 sh[9];
    int tid = threadIdx.x, lane = tid & 31, wid = tid >> 5;
    #pragma unroll
    for (int o = 16; o > 0; o >>= 1) {
        a += __shfl_xor_sync(0xffffffffu, a, o);
        b += __shfl_xor_sync(0xffffffffu, b, o);
    }
    if (lane == 0) sh[wid] = make_float2(a, b);
    __syncthreads();
    if (tid == 0) {
        float sa = 0.f, sb = 0.f;
        #pragma unroll
        for (int w = 0; w < 8; w++) { sa += sh[w].x; sb += sh[w].y; }
        sh[8] = make_float2(sa, sb);
    }
    __syncthreads();
    float2 r = sh[8];
    __syncthreads();
    return r;
}

// ---------------- h1 = LN(x + oproj)*g1+be1 : fp32 + fp16 -------------------
__global__ __launch_bounds__(256) void addln_kernel(
    const float* __restrict__ xbase, const float* __restrict__ res,
    const float* __restrict__ gain, const float* __restrict__ beta,
    float* __restrict__ out)
{
    int p = blockIdx.x; int e = p / B_, b = p % B_;
    if (g_gates[b*E_ + e] == 0.f) return;
    int s = blockIdx.y, tid = threadIdx.x;
    const float* xr = xbase + ((size_t)b*S_ + s)*D_;
    const float* rr = res + ((size_t)p*S_ + s)*D_;
    float v[4]; float sum = 0.f, sq = 0.f;
    #pragma unroll
    for (int j = 0; j < 4; j++) {
        int i = tid + j*256;
        float t = xr[i] + rr[i];
        v[j] = t; sum += t; sq = fmaf(t, t, sq);
    }
    float2 r = block_reduce2(sum, sq);
    float mean = r.x * (1.f/D_);
    float var = r.y * (1.f/D_) - mean*mean;
    float rstd = rsqrtf(var + 1e-5f);
    size_t ob = ((size_t)p*S_ + s)*D_;
    #pragma unroll
    for (int j = 0; j < 4; j++) {
        int i = tid + j*256;
        float o = (v[j] - mean)*rstd*gain[e*D_ + i] + beta[e*D_ + i];
        out[ob + i] = o;
        g_h1h[ob + i] = __float2half_rn(o);
    }
}

// ---------------- y = sum_e gate * LN(h1 + ff2), eps-fill -------------------
__global__ __launch_bounds__(256) void final_kernel(
    const float* __restrict__ h1, const float* __restrict__ f2,
    const float* __restrict__ g2, const float* __restrict__ be2,
    float* __restrict__ y)
{
    int b = blockIdx.x, s = blockIdx.y, tid = threadIdx.x;
    float acc[4] = {0.f, 0.f, 0.f, 0.f};
    for (int e = 0; e < E_; e++) {
        float gv = g_gates[b*E_ + e];
        if (gv == 0.f) continue;
        int p = e*B_ + b;
        const float* hr = h1 + ((size_t)p*S_ + s)*D_;
        const float* fr = f2 + ((size_t)p*S_ + s)*D_;
        float v[4]; float sum = 0.f, sq = 0.f;
        #pragma unroll
        for (int j = 0; j < 4; j++) {
            int i = tid + j*256;
            float t = hr[i] + fr[i];
            v[j] = t; sum += t; sq = fmaf(t, t, sq);
        }
        float2 r = block_reduce2(sum, sq);
        float mean = r.x * (1.f/D_);
        float var = r.y * (1.f/D_) - mean*mean;
        float rstd = rsqrtf(var + 1e-5f);
        #pragma unroll
        for (int j = 0; j < 4; j++) {
            int i = tid + j*256;
            acc[j] += gv * ((v[j]-mean)*rstd*g2[e*D_+i] + be2[e*D_+i]);
        }
    }
    float* yr = y + ((size_t)b*S_ + s)*D_;
    #pragma unroll
    for (int j = 0; j < 4; j++) {
        int i = tid + j*256;
        float o = acc[j];
        if (o == 0.f) o = EPS_FILL_F;
        yr[i] = o;
    }
}

// ---------------- launch ----------------------------------------------------
extern "C" void kernel_launch(void* const* d_in, const int* in_sizes, int n_in,
                              void* d_out, int out_size)
{
    const float* x       = (const float*)d_in[0];
    const float* noise   = (const float*)d_in[2];
    const float* w_gate  = (const float*)d_in[3];
    const float* w_noise = (const float*)d_in[4];
    const float* Wq      = (const float*)d_in[5];
    const float* Wk      = (const float*)d_in[6];
    const float* Wv      = (const float*)d_in[7];
    const float* Wo      = (const float*)d_in[8];
    const float* W1      = (const float*)d_in[9];
    const float* b1      = (const float*)d_in[10];
    const float* W2      = (const float*)d_in[11];
    const float* b2      = (const float*)d_in[12];
    const float* g1      = (const float*)d_in[13];
    const float* be1     = (const float*)d_in[14];
    const float* g2      = (const float*)d_in[15];
    const float* be2     = (const float*)d_in[16];
    float* out = (float*)d_out;

    float *pQ, *pK, *pV;
    __half *pXh, *pAth, *pH1h, *pFFh;
    __half *pWq, *pWk, *pWv, *pWo, *pW1, *pW2;
    cudaGetSymbolAddress((void**)&pQ,   g_q);
    cudaGetSymbolAddress((void**)&pK,   g_k);
    cudaGetSymbolAddress((void**)&pV,   g_v);
    cudaGetSymbolAddress((void**)&pXh,  g_xh);
    cudaGetSymbolAddress((void**)&pAth, g_ath);
    cudaGetSymbolAddress((void**)&pH1h, g_h1h);
    cudaGetSymbolAddress((void**)&pFFh, g_ffh);
    cudaGetSymbolAddress((void**)&pWq,  g_wqT);
    cudaGetSymbolAddress((void**)&pWk,  g_wkT);
    cudaGetSymbolAddress((void**)&pWv,  g_wvT);
    cudaGetSymbolAddress((void**)&pWo,  g_woT);
    cudaGetSymbolAddress((void**)&pW1,  g_w1T);
    cudaGetSymbolAddress((void**)&pW2,  g_w2T);

    cudaFuncSetAttribute(tgemm_kernel, cudaFuncAttributeMaxDynamicSharedMemorySize, SMEM_GEMM);

    const long SD  = (long)S_*D_;
    const long BSD = (long)B_*S_*D_;
    const long SF  = (long)S_*FF_;
    const long BSF = (long)B_*S_*FF_;

    // gating path
    sumx_kernel<<<dim3(D_/256, B_), 256>>>(x);
    gate_kernel<<<1, 1024>>>(w_gate, w_noise, noise, out + (size_t)B_*S_*D_);

    // weight transposes (fp32 -> fp16, [e][N][K])
    transpose_h_kernel<<<dim3(D_/32,  D_/32, E_), dim3(32,8)>>>(Wq, pWq, D_, D_);
    transpose_h_kernel<<<dim3(D_/32,  D_/32, E_), dim3(32,8)>>>(Wk, pWk, D_, D_);
    transpose_h_kernel<<<dim3(D_/32,  D_/32, E_), dim3(32,8)>>>(Wv, pWv, D_, D_);
    transpose_h_kernel<<<dim3(D_/32,  D_/32, E_), dim3(32,8)>>>(Wo, pWo, D_, D_);
    transpose_h_kernel<<<dim3(FF_/32, D_/32, E_), dim3(32,8)>>>(W1, pW1, D_, FF_);
    transpose_h_kernel<<<dim3(D_/32, FF_/32, E_), dim3(32,8)>>>(W2, pW2, FF_, D_);

    // x convert
    convx_kernel<<<(B_*S_*D_)/256, 256>>>(x, pXh);

    // fused QKV projections: sel = blockIdx.y/8 picks {Wq,Wk,Wv} and {pQ,pK,pV}
    tgemm_kernel<<<dim3(2, 3*(D_/128), NPAIR), 256, SMEM_GEMM>>>(
        pXh, pWq, pWk, pWv,
        nullptr, pQ, pK, pV, nullptr, D_, D_, 0, SD, 0);

    // attention (fp32 in, writes fp16)
    attn_kernel<<<dim3(NPAIR, H_), 256>>>();

    // O projection -> fp32 (reuse g_q)
    tgemm_kernel<<<dim3(2, D_/128, NPAIR), 256, SMEM_GEMM>>>(
        pAth, pWo, pWo, pWo,
        nullptr, pQ, nullptr, nullptr, nullptr, D_, D_, BSD, SD, 0);

    // h1 = LN(x + oproj): fp32 into g_k, fp16 into g_h1h
    addln_kernel<<<dim3(NPAIR, S_), 256>>>(x, pQ, g1, be1, pK);

    // FFN1: relu(h1 @ W1 + b1) -> fp16
    tgemm_kernel<<<dim3(2, FF_/128, NPAIR), 256, SMEM_GEMM>>>(
        pH1h, pW1, pW1, pW1,
        b1, nullptr, nullptr, nullptr, pFFh, D_, FF_, BSD, SD, 1);

    // FFN2: ff @ W2 + b2 -> fp32 (reuse g_v)
    tgemm_kernel<<<dim3(2, D_/128, NPAIR), 256, SMEM_GEMM>>>(
        pFFh, pW2, pW2, pW2,
        b2, pV, nullptr, nullptr, nullptr, FF_, D_, BSF, SF, 0);

    // combine
    final_kernel<<<dim3(B_, S_), 256>>>(pK, pV, g2, be2, out);
}

// round 14
// speedup vs baseline: 4.0850x; 1.0289x over previous
#include <cuda_runtime.h>
#include <cuda_fp16.h>
#include <math_constants.h>
#include <cstdint>

#define B_ 8
#define S_ 256
#define D_ 1024
#define H_ 16
#define E_ 4
#define FF_ 4096
#define HD_ 64
#define NPAIR (E_*B_)
#define SCALE_ 0.125f
#define EPS_FILL_F 2.2204460492503131e-16f
#define KCH 32
#define LDA 40                    // padded row length (elements) for 128x32 fp16 tiles
#define TILE_B (128*LDA*2)        // 10240 bytes per operand tile
#define STAGE_B (2*TILE_B)        // 20480 bytes per stage (A + B)
#define SMEM_GEMM (2*STAGE_B)     // 40960 bytes

// ---------------- scratch (device globals: no allocations allowed) ----------
__device__ float g_xs[B_*D_];
__device__ float g_gates[B_*E_];
__device__ float g_q[(size_t)NPAIR*S_*D_];
__device__ float g_k[(size_t)NPAIR*S_*D_];   // later reused as h1 (fp32)
__device__ float g_v[(size_t)NPAIR*S_*D_];   // later reused as ffn2 out (fp32)
__device__ __half g_xh[(size_t)B_*S_*D_];
__device__ __half g_ath[(size_t)NPAIR*S_*D_];
__device__ __half g_h1h[(size_t)NPAIR*S_*D_];
__device__ __half g_ffh[(size_t)NPAIR*S_*FF_];
// transposed fp16 weights [e][N][K]
__device__ __half g_wqT[(size_t)E_*D_*D_];
__device__ __half g_wkT[(size_t)E_*D_*D_];
__device__ __half g_wvT[(size_t)E_*D_*D_];
__device__ __half g_woT[(size_t)E_*D_*D_];
__device__ __half g_w1T[(size_t)E_*D_*FF_];
__device__ __half g_w2T[(size_t)E_*D_*FF_];

// ---------------- helpers ----------------
__device__ __forceinline__ uint32_t smem_u32(const void* p){
    uint32_t a;
    asm("{ .reg .u64 t; cvta.to.shared.u64 t, %1; cvt.u32.u64 %0, t; }" : "=r"(a) : "l"(p));
    return a;
}
__device__ __forceinline__ void ldsm_x4(uint32_t (&r)[4], uint32_t addr){
    asm volatile("ldmatrix.sync.aligned.m8n8.x4.shared.b16 {%0,%1,%2,%3}, [%4];"
                 : "=r"(r[0]),"=r"(r[1]),"=r"(r[2]),"=r"(r[3]) : "r"(addr));
}
__device__ __forceinline__ void mma16816(float (&c)[4], const uint32_t (&a)[4], const uint32_t (&b)[2]){
    asm volatile("mma.sync.aligned.m16n8k16.row.col.f32.f16.f16.f32 "
                 "{%0,%1,%2,%3},{%4,%5,%6,%7},{%8,%9},{%0,%1,%2,%3};"
                 : "+f"(c[0]),"+f"(c[1]),"+f"(c[2]),"+f"(c[3])
                 : "r"(a[0]),"r"(a[1]),"r"(a[2]),"r"(a[3]),"r"(b[0]),"r"(b[1]));
}
__device__ __forceinline__ void cp16(uint32_t s, const void* g){
    asm volatile("cp.async.cg.shared.global [%0], [%1], 16;" :: "r"(s), "l"(g));
}

// ---------------- xs = x.sum(axis=1) ----------------
__global__ void sumx_kernel(const float* __restrict__ x)
{
    int d = blockIdx.x*256 + threadIdx.x;
    int b = blockIdx.y;
    const float* xp = x + (size_t)b*S_*D_ + d;
    float acc = 0.f;
    #pragma unroll 4
    for (int s = 0; s < S_; s++) acc += xp[(size_t)s*D_];
    g_xs[b*D_ + d] = acc;
}

// ---------------- noisy top-k gating + aux loss ----------------
__global__ void gate_kernel(const float* __restrict__ w_gate,
                            const float* __restrict__ w_noise,
                            const float* __restrict__ noise,
                            float* __restrict__ loss_out)
{
    __shared__ float s_clean[B_][E_], s_raw[B_][E_], s_prob[B_][E_], s_gate[B_][E_];
    int tid = threadIdx.x;
    int wid = tid >> 5, lane = tid & 31;
    {
        int b = wid >> 2, e = wid & 3;
        float ac = 0.f, ar = 0.f;
        for (int i = lane; i < D_; i += 32) {
            float xv = g_xs[b*D_ + i];
            ac = fmaf(xv, w_gate[i*E_ + e], ac);
            ar = fmaf(xv, w_noise[i*E_ + e], ar);
        }
        #pragma unroll
        for (int o = 16; o > 0; o >>= 1) {
            ac += __shfl_xor_sync(0xffffffffu, ac, o);
            ar += __shfl_xor_sync(0xffffffffu, ar, o);
        }
        if (lane == 0) { s_clean[b][e] = ac; s_raw[b][e] = ar; }
    }
    __syncthreads();
    if (tid < B_) {
        int b = tid;
        float clean[E_], noisy[E_], sd[E_];
        #pragma unroll
        for (int e = 0; e < E_; e++) {
            clean[e] = s_clean[b][e];
            float r = s_raw[b][e];
            float sp = fmaxf(r, 0.f) + log1pf(expf(-fabsf(r)));
            sd[e] = sp + 0.01f;
            noisy[e] = clean[e] + noise[b*E_ + e] * sd[e];
        }
        int ord[3]; bool used[E_] = {false,false,false,false};
        for (int s = 0; s < 3; s++) {
            int best = -1;
            for (int e = 0; e < E_; e++)
                if (!used[e] && (best < 0 || noisy[e] > noisy[best])) best = e;
            used[best] = true; ord[s] = best;
        }
        float l0 = noisy[ord[0]], l1 = noisy[ord[1]], l2 = noisy[ord[2]];
        float e1 = expf(l1 - l0);
        float inv = 1.f / (1.f + e1);
        #pragma unroll
        for (int e = 0; e < E_; e++) s_gate[b][e] = 0.f;
        s_gate[b][ord[0]] = inv;
        s_gate[b][ord[1]] = e1 * inv;
        #pragma unroll
        for (int e = 0; e < E_; e++) {
            bool isin = noisy[e] > l2;
            float thr = isin ? l2 : l1;
            s_prob[b][e] = normcdff((clean[e] - thr) / sd[e]);
            g_gates[b*E_ + e] = s_gate[b][e];
        }
    }
    __syncthreads();
    if (tid == 0) {
        float cv[2];
        for (int which = 0; which < 2; which++) {
            float v[E_];
            for (int e = 0; e < E_; e++) {
                float s = 0.f;
                for (int b = 0; b < B_; b++)
                    s += which ? s_prob[b][e] : s_gate[b][e];
                v[e] = s;
            }
            float m = (v[0]+v[1]+v[2]+v[3]) * 0.25f;
            float var = 0.f;
            for (int e = 0; e < E_; e++) { float dd = v[e]-m; var += dd*dd; }
            var *= (1.0f / (E_ - 1));
            cv[which] = var / (m*m + 1e-10f);
        }
        loss_out[0] = (cv[0] + cv[1]) * 0.01f;
    }
}

// ---------------- weight transpose to fp16:  W[e][K][N] -> Wt[e][N][K] ------
__global__ void transpose_h_kernel(const float* __restrict__ W,
                                   __half* __restrict__ o,
                                   int Kd, int Nd)
{
    __shared__ float t[32][33];
    int e = blockIdx.z;
    const float* We = W + (size_t)e*Kd*Nd;
    size_t ob = (size_t)e*Kd*Nd;
    int k0 = blockIdx.y*32, n0 = blockIdx.x*32;
    int tx = threadIdx.x, ty = threadIdx.y;  // 32 x 8
    #pragma unroll
    for (int i = 0; i < 32; i += 8)
        t[ty+i][tx] = We[(size_t)(k0+ty+i)*Nd + n0 + tx];
    __syncthreads();
    #pragma unroll
    for (int i = 0; i < 32; i += 8) {
        float v = t[tx][ty+i];
        o[ob + (size_t)(n0+ty+i)*Kd + k0 + tx] = __float2half_rn(v);
    }
}

// ---------------- elementwise fp16 convert of x -----------------------------
__global__ void convx_kernel(const float* __restrict__ in, __half* __restrict__ o)
{
    int i = blockIdx.x*256 + threadIdx.x;
    o[i] = __float2half_rn(in[i]);
}

// ---------------- HMMA fp16 GEMM, cp.async 2-stage pipeline ------------------
// Up to 3 weight groups (Q/K/V fused): sel = blockIdx.y / (N/128)
__global__ __launch_bounds__(256) void tgemm_kernel(
    const __half* __restrict__ A0,
    const __half* __restrict__ Bw0, const __half* __restrict__ Bw1, const __half* __restrict__ Bw2,
    const float* __restrict__ biasbase,
    float* __restrict__ outF0, float* __restrict__ outF1, float* __restrict__ outF2,
    __half* __restrict__ outH,
    int Kdim, int N, long sAe, long sAb, int doRelu)
{
    int p = blockIdx.z, e = p >> 3, b = p & 7;
    if (g_gates[b*E_ + e] == 0.f) return;

    int nGC = N >> 7;
    int sel = blockIdx.y / nGC;
    int colBase = (blockIdx.y % nGC) * 128;
    const __half* Bw = (sel == 0) ? Bw0 : (sel == 1) ? Bw1 : Bw2;
    float* outF = (sel == 0) ? outF0 : (sel == 1) ? outF1 : outF2;

    extern __shared__ char smem[];
    uint32_t sm = smem_u32(smem);

    int tid = threadIdx.x, wid = tid >> 5, lane = tid & 31;
    int warpRow = wid >> 2;        // 0..1  (64 rows each)
    int warpCol = wid & 3;         // 0..3  (32 cols each)
    int rowBase = blockIdx.x * 128;

    const __half* Aptr = A0 + (size_t)e*sAe + (size_t)b*sAb + (size_t)rowBase*Kdim;
    const __half* Bptr = Bw + ((size_t)e*N + colBase)*Kdim;

    // per-thread ldmatrix byte offsets
    uint32_t aOff = (uint32_t)((lane & 15) * (LDA*2)) + ((lane >> 4) * 16);
    uint32_t bOff = (uint32_t)(((lane & 7) + ((lane >> 4) << 3)) * (LDA*2)) + (((lane >> 3) & 1) * 16);
    uint32_t aWarp = (uint32_t)(warpRow * 64) * (LDA*2);
    uint32_t bWarp = (uint32_t)(warpCol * 32) * (LDA*2);

    // per-thread cp.async indices (2 vectors per tile per thread)
    int r0 = tid >> 2, c0v = tid & 3;
    int r1 = (256 + tid) >> 2, c1v = tid & 3;
    uint32_t so0 = (uint32_t)r0*(LDA*2) + (uint32_t)c0v*16;
    uint32_t so1 = (uint32_t)r1*(LDA*2) + (uint32_t)c1v*16;

    float acc[4][4][4];
    #pragma unroll
    for (int i = 0; i < 4; i++)
        #pragma unroll
        for (int j = 0; j < 4; j++)
            #pragma unroll
            for (int q = 0; q < 4; q++) acc[i][j][q] = 0.f;

    int nCh = Kdim / KCH;

    auto load_stage = [&](int kt, int st){
        size_t koff = (size_t)kt * KCH;
        uint32_t sb = sm + (uint32_t)st*STAGE_B;
        size_t g0 = (size_t)r0*Kdim + koff + (size_t)c0v*8;
        size_t g1 = (size_t)r1*Kdim + koff + (size_t)c1v*8;
        cp16(sb + so0,          Aptr + g0);
        cp16(sb + so1,          Aptr + g1);
        cp16(sb + TILE_B + so0, Bptr + g0);
        cp16(sb + TILE_B + so1, Bptr + g1);
        asm volatile("cp.async.commit_group;");
    };

    load_stage(0, 0);
    for (int kt = 0; kt < nCh; kt++) {
        int st = kt & 1;
        if (kt + 1 < nCh) {
            load_stage(kt + 1, st ^ 1);
            asm volatile("cp.async.wait_group 1;");
        } else {
            asm volatile("cp.async.wait_group 0;");
        }
        __syncthreads();

        uint32_t sA32 = sm + (uint32_t)st*STAGE_B;
        uint32_t sB32 = sA32 + TILE_B;

        #pragma unroll
        for (int k16 = 0; k16 < 2; k16++) {
            uint32_t kb = (uint32_t)k16 * 32;
            uint32_t a[4][4], bh[4][2];
            #pragma unroll
            for (int np = 0; np < 2; np++) {
                uint32_t r4[4];
                ldsm_x4(r4, sB32 + bWarp + bOff + np*(16*LDA*2) + kb);
                bh[2*np][0] = r4[0]; bh[2*np][1] = r4[1];
                bh[2*np+1][0] = r4[2]; bh[2*np+1][1] = r4[3];
            }
            #pragma unroll
            for (int mt = 0; mt < 4; mt++)
                ldsm_x4(a[mt], sA32 + aWarp + aOff + mt*(16*LDA*2) + kb);
            #pragma unroll
            for (int mt = 0; mt < 4; mt++)
                #pragma unroll
                for (int nt = 0; nt < 4; nt++)
                    mma16816(acc[mt][nt], a[mt], bh[nt]);
        }
        __syncthreads();
    }

    // ---------------- epilogue ----------------
    const float* bias = biasbase ? biasbase + (size_t)e*N : nullptr;
    int mWarp = rowBase + warpRow*64;
    int nWarp = colBase + warpCol*32;
    int rq = lane >> 2, cq = (lane & 3)*2;

    #pragma unroll
    for (int mt = 0; mt < 4; mt++) {
        #pragma unroll
        for (int nt = 0; nt < 4; nt++) {
            int col = nWarp + nt*8 + cq;
            float b0 = bias ? bias[col] : 0.f;
            float b1 = bias ? bias[col+1] : 0.f;
            #pragma unroll
            for (int half = 0; half < 2; half++) {
                int row = mWarp + mt*16 + rq + half*8;
                float v0 = acc[mt][nt][2*half+0] + b0;
                float v1 = acc[mt][nt][2*half+1] + b1;
                if (doRelu) { v0 = fmaxf(v0, 0.f); v1 = fmaxf(v1, 0.f); }
                size_t o = ((size_t)p*S_ + row)*N + col;
                if (outF) *(float2*)(outF + o) = make_float2(v0, v1);
                if (outH) {
                    __half2 hv = __floats2half2_rn(v0, v1);
                    *(__half2*)(outH + o) = hv;
                }
            }
        }
    }
}

// ---------------- fused causal attention (2 threads per query) ---------------
__global__ __launch_bounds__(256) void attn_kernel()
{
    int p = blockIdx.x, h = blockIdx.y;
    int e = p / B_, b = p % B_;
    if (g_gates[b*E_ + e] == 0.f) return;
    __shared__ __align__(16) float Ks[64][72];
    __shared__ __align__(16) float Vs[64][72];
    int tid = threadIdx.x;
    int lane = tid & 31;
    unsigned pmask = 3u << (lane & 30);   // pair mask: lanes {2i, 2i+1} only
    int q = blockIdx.z*128 + (tid >> 1);
    int hf = tid & 1;
    int cb = hf * 36;    // halves stored at cols 0..31 and 36..67 (bank-skewed)

    float qreg[32];
    {
        const float* qp = &g_q[((size_t)p*S_ + q)*D_ + h*HD_ + hf*32];
        #pragma unroll
        for (int i = 0; i < 32; i += 4) {
            float4 t = *reinterpret_cast<const float4*>(qp + i);
            qreg[i] = t.x; qreg[i+1] = t.y; qreg[i+2] = t.z; qreg[i+3] = t.w;
        }
    }
    float acc[32];
    #pragma unroll
    for (int i = 0; i < 32; i++) acc[i] = 0.f;
    float m = -CUDART_INF_F, l = 0.f;

    int ntile = (blockIdx.z == 0) ? 2 : 4;
    for (int t = 0; t < ntile; t++) {
        #pragma unroll
        for (int pass = 0; pass < 4; pass++) {
            int r = pass*16 + (tid >> 4);
            int c = (tid & 15) * 4;
            int cs = c + ((c >= 32) ? 4 : 0);
            size_t off = ((size_t)p*S_ + t*64 + r)*D_ + h*HD_ + c;
            *reinterpret_cast<float4*>(&Ks[r][cs]) = *reinterpret_cast<const float4*>(&g_k[off]);
            *reinterpret_cast<float4*>(&Vs[r][cs]) = *reinterpret_cast<const float4*>(&g_v[off]);
        }
        __syncthreads();
        int kmax = q - t*64;
        if (kmax > 63) kmax = 63;
        for (int kk = 0; kk <= kmax; kk++) {
            const float* kr = &Ks[kk][cb];
            float d0 = 0.f, d1 = 0.f, d2 = 0.f, d3 = 0.f;
            #pragma unroll
            for (int i = 0; i < 32; i += 4) {
                d0 = fmaf(qreg[i+0], kr[i+0], d0);
                d1 = fmaf(qreg[i+1], kr[i+1], d1);
                d2 = fmaf(qreg[i+2], kr[i+2], d2);
                d3 = fmaf(qreg[i+3], kr[i+3], d3);
            }
            float s = (d0 + d1) + (d2 + d3);
            s += __shfl_xor_sync(pmask, s, 1);     // pair-convergent: same q, same kmax
            s *= SCALE_;
            float mn = fmaxf(m, s);
            float corr = __expf(m - mn);
            float pw = __expf(s - mn);
            l = l*corr + pw;
            const float* vr = &Vs[kk][cb];
            #pragma unroll
            for (int i = 0; i < 32; i++) acc[i] = fmaf(acc[i], corr, pw*vr[i]);
            m = mn;
        }
        __syncthreads();
    }
    float invl = 1.f / l;
    size_t ob = ((size_t)p*S_ + q)*D_ + h*HD_ + hf*32;
    #pragma unroll
    for (int i = 0; i < 32; i += 2) {
        __half2 hv = __floats2half2_rn(acc[i]*invl, acc[i+1]*invl);
        *(__half2*)(&g_ath[ob + i]) = hv;
    }
}

// ---------------- block reduce (sum, sumsq), blockDim = 256 -----------------
__device__ __forceinline__ float2 block_reduce2(float a, float b)
{
    __shared__ float2 sh[9];
    int tid = threadIdx.x, lane = tid & 31, wid = tid >> 5;
    #pragma unroll
    for (int o = 16; o > 0; o >>= 1) {
        a += __shfl_xor_sync(0xffffffffu, a, o);
        b += __shfl_xor_sync(0xffffffffu, b, o);
    }
    if (lane == 0) sh[wid] = make_float2(a, b);
    __syncthreads();
    if (tid == 0) {
        float sa = 0.f, sb = 0.f;
        #pragma unroll
        for (int w = 0; w < 8; w++) { sa += sh[w].x; sb += sh[w].y; }
        sh[8] = make_float2(sa, sb);
    }
    __syncthreads();
    float2 r = sh[8];
    __syncthreads();
    return r;
}

// ---------------- h1 = LN(x + oproj)*g1+be1 : fp32 + fp16 -------------------
__global__ __launch_bounds__(256) void addln_kernel(
    const float* __restrict__ xbase, const float* __restrict__ res,
    const float* __restrict__ gain, const float* __restrict__ beta,
    float* __restrict__ out)
{
    int p = blockIdx.x; int e = p / B_, b = p % B_;
    if (g_gates[b*E_ + e] == 0.f) return;
    int s = blockIdx.y, tid = threadIdx.x;
    const float* xr = xbase + ((size_t)b*S_ + s)*D_;
    const float* rr = res + ((size_t)p*S_ + s)*D_;
    float v[4]; float sum = 0.f, sq = 0.f;
    #pragma unroll
    for (int j = 0; j < 4; j++) {
        int i = tid + j*256;
        float t = xr[i] + rr[i];
        v[j] = t; sum += t; sq = fmaf(t, t, sq);
    }
    float2 r = block_reduce2(sum, sq);
    float mean = r.x * (1.f/D_);
    float var = r.y * (1.f/D_) - mean*mean;
    float rstd = rsqrtf(var + 1e-5f);
    size_t ob = ((size_t)p*S_ + s)*D_;
    #pragma unroll
    for (int j = 0; j < 4; j++) {
        int i = tid + j*256;
        float o = (v[j] - mean)*rstd*gain[e*D_ + i] + beta[e*D_ + i];
        out[ob + i] = o;
        g_h1h[ob + i] = __float2half_rn(o);
    }
}

// ---------------- y = sum_e gate * LN(h1 + ff2), eps-fill -------------------
__global__ __launch_bounds__(256) void final_kernel(
    const float* __restrict__ h1, const float* __restrict__ f2,
    const float* __restrict__ g2, const float* __restrict__ be2,
    float* __restrict__ y)
{
    int b = blockIdx.x, s = blockIdx.y, tid = threadIdx.x;
    float acc[4] = {0.f, 0.f, 0.f, 0.f};
    for (int e = 0; e < E_; e++) {
        float gv = g_gates[b*E_ + e];
        if (gv == 0.f) continue;
        int p = e*B_ + b;
        const float* hr = h1 + ((size_t)p*S_ + s)*D_;
        const float* fr = f2 + ((size_t)p*S_ + s)*D_;
        float v[4]; float sum = 0.f, sq = 0.f;
        #pragma unroll
        for (int j = 0; j < 4; j++) {
            int i = tid + j*256;
            float t = hr[i] + fr[i];
            v[j] = t; sum += t; sq = fmaf(t, t, sq);
        }
        float2 r = block_reduce2(sum, sq);
        float mean = r.x * (1.f/D_);
        float var = r.y * (1.f/D_) - mean*mean;
        float rstd = rsqrtf(var + 1e-5f);
        #pragma unroll
        for (int j = 0; j < 4; j++) {
            int i = tid + j*256;
            acc[j] += gv * ((v[j]-mean)*rstd*g2[e*D_+i] + be2[e*D_+i]);
        }
    }
    float* yr = y + ((size_t)b*S_ + s)*D_;
    #pragma unroll
    for (int j = 0; j < 4; j++) {
        int i = tid + j*256;
        float o = acc[j];
        if (o == 0.f) o = EPS_FILL_F;
        yr[i] = o;
    }
}

// ---------------- launch ----------------------------------------------------
extern "C" void kernel_launch(void* const* d_in, const int* in_sizes, int n_in,
                              void* d_out, int out_size)
{
    const float* x       = (const float*)d_in[0];
    const float* noise   = (const float*)d_in[2];
    const float* w_gate  = (const float*)d_in[3];
    const float* w_noise = (const float*)d_in[4];
    const float* Wq      = (const float*)d_in[5];
    const float* Wk      = (const float*)d_in[6];
    const float* Wv      = (const float*)d_in[7];
    const float* Wo      = (const float*)d_in[8];
    const float* W1      = (const float*)d_in[9];
    const float* b1      = (const float*)d_in[10];
    const float* W2      = (const float*)d_in[11];
    const float* b2      = (const float*)d_in[12];
    const float* g1      = (const float*)d_in[13];
    const float* be1     = (const float*)d_in[14];
    const float* g2      = (const float*)d_in[15];
    const float* be2     = (const float*)d_in[16];
    float* out = (float*)d_out;

    float *pQ, *pK, *pV;
    __half *pXh, *pAth, *pH1h, *pFFh;
    __half *pWq, *pWk, *pWv, *pWo, *pW1, *pW2;
    cudaGetSymbolAddress((void**)&pQ,   g_q);
    cudaGetSymbolAddress((void**)&pK,   g_k);
    cudaGetSymbolAddress((void**)&pV,   g_v);
    cudaGetSymbolAddress((void**)&pXh,  g_xh);
    cudaGetSymbolAddress((void**)&pAth, g_ath);
    cudaGetSymbolAddress((void**)&pH1h, g_h1h);
    cudaGetSymbolAddress((void**)&pFFh, g_ffh);
    cudaGetSymbolAddress((void**)&pWq,  g_wqT);
    cudaGetSymbolAddress((void**)&pWk,  g_wkT);
    cudaGetSymbolAddress((void**)&pWv,  g_wvT);
    cudaGetSymbolAddress((void**)&pWo,  g_woT);
    cudaGetSymbolAddress((void**)&pW1,  g_w1T);
    cudaGetSymbolAddress((void**)&pW2,  g_w2T);

    cudaFuncSetAttribute(tgemm_kernel, cudaFuncAttributeMaxDynamicSharedMemorySize, SMEM_GEMM);

    const long SD  = (long)S_*D_;
    const long BSD = (long)B_*S_*D_;
    const long SF  = (long)S_*FF_;
    const long BSF = (long)B_*S_*FF_;

    // gating path
    sumx_kernel<<<dim3(D_/256, B_), 256>>>(x);
    gate_kernel<<<1, 1024>>>(w_gate, w_noise, noise, out + (size_t)B_*S_*D_);

    // weight transposes (fp32 -> fp16, [e][N][K])
    transpose_h_kernel<<<dim3(D_/32,  D_/32, E_), dim3(32,8)>>>(Wq, pWq, D_, D_);
    transpose_h_kernel<<<dim3(D_/32,  D_/32, E_), dim3(32,8)>>>(Wk, pWk, D_, D_);
    transpose_h_kernel<<<dim3(D_/32,  D_/32, E_), dim3(32,8)>>>(Wv, pWv, D_, D_);
    transpose_h_kernel<<<dim3(D_/32,  D_/32, E_), dim3(32,8)>>>(Wo, pWo, D_, D_);
    transpose_h_kernel<<<dim3(FF_/32, D_/32, E_), dim3(32,8)>>>(W1, pW1, D_, FF_);
    transpose_h_kernel<<<dim3(D_/32, FF_/32, E_), dim3(32,8)>>>(W2, pW2, FF_, D_);

    // x convert
    convx_kernel<<<(B_*S_*D_)/256, 256>>>(x, pXh);

    // fused QKV projections: sel = blockIdx.y/8 picks {Wq,Wk,Wv} and {pQ,pK,pV}
    tgemm_kernel<<<dim3(2, 3*(D_/128), NPAIR), 256, SMEM_GEMM>>>(
        pXh, pWq, pWk, pWv,
        nullptr, pQ, pK, pV, nullptr, D_, D_, 0, SD, 0);

    // attention (fp32 in, writes fp16), 2 CTAs per (p,h)
    attn_kernel<<<dim3(NPAIR, H_, 2), 256>>>();

    // O projection -> fp32 (reuse g_q)
    tgemm_kernel<<<dim3(2, D_/128, NPAIR), 256, SMEM_GEMM>>>(
        pAth, pWo, pWo, pWo,
        nullptr, pQ, nullptr, nullptr, nullptr, D_, D_, BSD, SD, 0);

    // h1 = LN(x + oproj): fp32 into g_k, fp16 into g_h1h
    addln_kernel<<<dim3(NPAIR, S_), 256>>>(x, pQ, g1, be1, pK);

    // FFN1: relu(h1 @ W1 + b1) -> fp16
    tgemm_kernel<<<dim3(2, FF_/128, NPAIR), 256, SMEM_GEMM>>>(
        pH1h, pW1, pW1, pW1,
        b1, nullptr, nullptr, nullptr, pFFh, D_, FF_, BSD, SD, 1);

    // FFN2: ff @ W2 + b2 -> fp32 (reuse g_v)
    tgemm_kernel<<<dim3(2, D_/128, NPAIR), 256, SMEM_GEMM>>>(
        pFFh, pW2, pW2, pW2,
        b2, pV, nullptr, nullptr, nullptr, FF_, D_, BSF, SF, 0);

    // combine
    final_kernel<<<dim3(B_, S_), 256>>>(pK, pV, g2, be2, out);
}

// round 15
// speedup vs baseline: 4.6645x; 1.1419x over previous
#include <cuda_runtime.h>
#include <cuda_fp16.h>
#include <math_constants.h>
#include <cstdint>

#define B_ 8
#define S_ 256
#define D_ 1024
#define H_ 16
#define E_ 4
#define FF_ 4096
#define HD_ 64
#define NPAIR (E_*B_)
#define SCALE_ 0.125f
#define EPS_FILL_F 2.2204460492503131e-16f
#define KCH 32
#define LDA 40                        // padded A row (halves) for 128x32 tiles
#define ATILE_B (128*LDA*2)           // 10240 bytes
#define BTILE_B (32*272)              // 8704 bytes ([K=32][N=128] fp16, 272B padded rows)
#define STAGE_B (ATILE_B + BTILE_B)   // 18944
#define SMEM_GEMM (2*STAGE_B)         // 37888

// ---------------- scratch (device globals: no allocations allowed) ----------
__device__ float g_xs[B_*D_];
__device__ float g_gates[B_*E_];
__device__ float g_q[(size_t)NPAIR*S_*D_];
__device__ float g_k[(size_t)NPAIR*S_*D_];   // later reused as h1 (fp32)
__device__ float g_v[(size_t)NPAIR*S_*D_];   // later reused as ffn2 out (fp32)
__device__ __half g_xh[(size_t)B_*S_*D_];
__device__ __half g_ath[(size_t)NPAIR*S_*D_];
__device__ __half g_h1h[(size_t)NPAIR*S_*D_];
__device__ __half g_ffh[(size_t)NPAIR*S_*FF_];
// fp16 weights, ORIGINAL layout [e][K][N]
__device__ __half g_wqH[(size_t)E_*D_*D_];
__device__ __half g_wkH[(size_t)E_*D_*D_];
__device__ __half g_wvH[(size_t)E_*D_*D_];
__device__ __half g_woH[(size_t)E_*D_*D_];
__device__ __half g_w1H[(size_t)E_*D_*FF_];
__device__ __half g_w2H[(size_t)E_*D_*FF_];

// ---------------- helpers ----------------
__device__ __forceinline__ uint32_t smem_u32(const void* p){
    uint32_t a;
    asm("{ .reg .u64 t; cvta.to.shared.u64 t, %1; cvt.u32.u64 %0, t; }" : "=r"(a) : "l"(p));
    return a;
}
__device__ __forceinline__ void ldsm_x4(uint32_t (&r)[4], uint32_t addr){
    asm volatile("ldmatrix.sync.aligned.m8n8.x4.shared.b16 {%0,%1,%2,%3}, [%4];"
                 : "=r"(r[0]),"=r"(r[1]),"=r"(r[2]),"=r"(r[3]) : "r"(addr));
}
__device__ __forceinline__ void ldsm_x4_t(uint32_t (&r)[4], uint32_t addr){
    asm volatile("ldmatrix.sync.aligned.m8n8.x4.trans.shared.b16 {%0,%1,%2,%3}, [%4];"
                 : "=r"(r[0]),"=r"(r[1]),"=r"(r[2]),"=r"(r[3]) : "r"(addr));
}
__device__ __forceinline__ void mma16816(float (&c)[4], const uint32_t (&a)[4], const uint32_t (&b)[2]){
    asm volatile("mma.sync.aligned.m16n8k16.row.col.f32.f16.f16.f32 "
                 "{%0,%1,%2,%3},{%4,%5,%6,%7},{%8,%9},{%0,%1,%2,%3};"
                 : "+f"(c[0]),"+f"(c[1]),"+f"(c[2]),"+f"(c[3])
                 : "r"(a[0]),"r"(a[1]),"r"(a[2]),"r"(a[3]),"r"(b[0]),"r"(b[1]));
}
__device__ __forceinline__ void cp16(uint32_t s, const void* g){
    asm volatile("cp.async.cg.shared.global [%0], [%1], 16;" :: "r"(s), "l"(g));
}

// ---------------- xs = x.sum(axis=1) ----------------
__global__ void sumx_kernel(const float* __restrict__ x)
{
    int d = blockIdx.x*256 + threadIdx.x;
    int b = blockIdx.y;
    const float* xp = x + (size_t)b*S_*D_ + d;
    float acc = 0.f;
    #pragma unroll 4
    for (int s = 0; s < S_; s++) acc += xp[(size_t)s*D_];
    g_xs[b*D_ + d] = acc;
}

// ---------------- noisy top-k gating + aux loss ----------------
__global__ void gate_kernel(const float* __restrict__ w_gate,
                            const float* __restrict__ w_noise,
                            const float* __restrict__ noise,
                            float* __restrict__ loss_out)
{
    __shared__ float s_clean[B_][E_], s_raw[B_][E_], s_prob[B_][E_], s_gate[B_][E_];
    int tid = threadIdx.x;
    int wid = tid >> 5, lane = tid & 31;
    {
        int b = wid >> 2, e = wid & 3;
        float ac = 0.f, ar = 0.f;
        for (int i = lane; i < D_; i += 32) {
            float xv = g_xs[b*D_ + i];
            ac = fmaf(xv, w_gate[i*E_ + e], ac);
            ar = fmaf(xv, w_noise[i*E_ + e], ar);
        }
        #pragma unroll
        for (int o = 16; o > 0; o >>= 1) {
            ac += __shfl_xor_sync(0xffffffffu, ac, o);
            ar += __shfl_xor_sync(0xffffffffu, ar, o);
        }
        if (lane == 0) { s_clean[b][e] = ac; s_raw[b][e] = ar; }
    }
    __syncthreads();
    if (tid < B_) {
        int b = tid;
        float clean[E_], noisy[E_], sd[E_];
        #pragma unroll
        for (int e = 0; e < E_; e++) {
            clean[e] = s_clean[b][e];
            float r = s_raw[b][e];
            float sp = fmaxf(r, 0.f) + log1pf(expf(-fabsf(r)));
            sd[e] = sp + 0.01f;
            noisy[e] = clean[e] + noise[b*E_ + e] * sd[e];
        }
        int ord[3]; bool used[E_] = {false,false,false,false};
        for (int s = 0; s < 3; s++) {
            int best = -1;
            for (int e = 0; e < E_; e++)
                if (!used[e] && (best < 0 || noisy[e] > noisy[best])) best = e;
            used[best] = true; ord[s] = best;
        }
        float l0 = noisy[ord[0]], l1 = noisy[ord[1]], l2 = noisy[ord[2]];
        float e1 = expf(l1 - l0);
        float inv = 1.f / (1.f + e1);
        #pragma unroll
        for (int e = 0; e < E_; e++) s_gate[b][e] = 0.f;
        s_gate[b][ord[0]] = inv;
        s_gate[b][ord[1]] = e1 * inv;
        #pragma unroll
        for (int e = 0; e < E_; e++) {
            bool isin = noisy[e] > l2;
            float thr = isin ? l2 : l1;
            s_prob[b][e] = normcdff((clean[e] - thr) / sd[e]);
            g_gates[b*E_ + e] = s_gate[b][e];
        }
    }
    __syncthreads();
    if (tid == 0) {
        float cv[2];
        for (int which = 0; which < 2; which++) {
            float v[E_];
            for (int e = 0; e < E_; e++) {
                float s = 0.f;
                for (int b = 0; b < B_; b++)
                    s += which ? s_prob[b][e] : s_gate[b][e];
                v[e] = s;
            }
            float m = (v[0]+v[1]+v[2]+v[3]) * 0.25f;
            float var = 0.f;
            for (int e = 0; e < E_; e++) { float dd = v[e]-m; var += dd*dd; }
            var *= (1.0f / (E_ - 1));
            cv[which] = var / (m*m + 1e-10f);
        }
        loss_out[0] = (cv[0] + cv[1]) * 0.01f;
    }
}

// ---------------- single coalesced fp32->fp16 convert (weights + x) ---------
#define BWD (E_*D_*D_/2048)     // blocks per DxD weight
#define BWF (E_*D_*FF_/2048)    // blocks per DxFF weight
#define BX  (B_*S_*D_/2048)     // blocks for x
#define NCONV_BLOCKS (4*BWD + 2*BWF + BX)

__global__ void convert_all_kernel(const float* __restrict__ Wq, const float* __restrict__ Wk,
                                   const float* __restrict__ Wv, const float* __restrict__ Wo,
                                   const float* __restrict__ W1, const float* __restrict__ W2,
                                   const float* __restrict__ x)
{
    int blk = blockIdx.x;
    const float* src; __half* dst;
    if      (blk < 1*BWD)       { src = Wq; dst = g_wqH; }
    else if (blk < 2*BWD)       { src = Wk; dst = g_wkH; blk -= 1*BWD; }
    else if (blk < 3*BWD)       { src = Wv; dst = g_wvH; blk -= 2*BWD; }
    else if (blk < 4*BWD)       { src = Wo; dst = g_woH; blk -= 3*BWD; }
    else if (blk < 4*BWD+BWF)   { src = W1; dst = g_w1H; blk -= 4*BWD; }
    else if (blk < 4*BWD+2*BWF) { src = W2; dst = g_w2H; blk -= 4*BWD+BWF; }
    else                        { src = x;  dst = g_xh;  blk -= 4*BWD+2*BWF; }
    size_t i = ((size_t)blk*256 + threadIdx.x)*8;
    float4 a = *(const float4*)(src + i);
    float4 c = *(const float4*)(src + i + 4);
    __half2 h0 = __floats2half2_rn(a.x, a.y), h1 = __floats2half2_rn(a.z, a.w);
    __half2 h2 = __floats2half2_rn(c.x, c.y), h3 = __floats2half2_rn(c.z, c.w);
    uint4 o;
    o.x = *reinterpret_cast<uint32_t*>(&h0);
    o.y = *reinterpret_cast<uint32_t*>(&h1);
    o.z = *reinterpret_cast<uint32_t*>(&h2);
    o.w = *reinterpret_cast<uint32_t*>(&h3);
    *reinterpret_cast<uint4*>(dst + i) = o;
}

// ---------------- HMMA fp16 GEMM, cp.async 2-stage, B from [K][N] layout -----
// Up to 3 weight groups (Q/K/V fused): sel = blockIdx.y / (N/128)
__global__ __launch_bounds__(256) void tgemm_kernel(
    const __half* __restrict__ A0,
    const __half* __restrict__ Bw0, const __half* __restrict__ Bw1, const __half* __restrict__ Bw2,
    const float* __restrict__ biasbase,
    float* __restrict__ outF0, float* __restrict__ outF1, float* __restrict__ outF2,
    __half* __restrict__ outH,
    int Kdim, int N, long sAe, long sAb, int doRelu)
{
    int p = blockIdx.z, e = p >> 3, b = p & 7;
    if (g_gates[b*E_ + e] == 0.f) return;

    int nGC = N >> 7;
    int sel = blockIdx.y / nGC;
    int colBase = (blockIdx.y % nGC) * 128;
    const __half* Bw = (sel == 0) ? Bw0 : (sel == 1) ? Bw1 : Bw2;
    float* outF = (sel == 0) ? outF0 : (sel == 1) ? outF1 : outF2;

    extern __shared__ char smem[];
    uint32_t sm = smem_u32(smem);

    int tid = threadIdx.x, wid = tid >> 5, lane = tid & 31;
    int warpRow = wid >> 2;        // 0..1  (64 rows each)
    int warpCol = wid & 3;         // 0..3  (32 cols each)
    int rowBase = blockIdx.x * 128;

    const __half* Aptr = A0 + (size_t)e*sAe + (size_t)b*sAb + (size_t)rowBase*Kdim;
    const __half* Bptr = Bw + (size_t)e*((size_t)Kdim*N) + colBase;   // [K][N] layout

    // A ldmatrix byte offsets (row-major, non-trans)
    uint32_t aOff = (uint32_t)((lane & 15) * (LDA*2)) + ((lane >> 4) * 16);
    uint32_t aWarp = (uint32_t)(warpRow * 64) * (LDA*2);
    // B ldmatrix.trans lane base: matrices (k0-7,n0-7),(k8-15,n0-7),(k0-7,n8-15),(k8-15,n8-15)
    int mlane = lane >> 3, rlane = lane & 7;
    uint32_t bTransBase = (uint32_t)(((mlane & 1)*8 + rlane) * 272 + (mlane >> 1) * 16);
    uint32_t nWb = (uint32_t)(warpCol * 32) * 2;   // warp's n-range byte offset

    // cp.async indices
    int r0 = tid >> 2, c0v = tid & 3;              // A: 2 vecs (128x32 tile)
    int r1 = (256 + tid) >> 2, c1v = tid & 3;
    uint32_t soA0 = (uint32_t)r0*(LDA*2) + (uint32_t)c0v*16;
    uint32_t soA1 = (uint32_t)r1*(LDA*2) + (uint32_t)c1v*16;
    int rB = tid >> 4, cB = tid & 15;              // B: 2 vecs (32x128 tile, 256B rows + pad)
    uint32_t soB = (uint32_t)rB*272 + (uint32_t)cB*16;

    float acc[4][4][4];
    #pragma unroll
    for (int i = 0; i < 4; i++)
        #pragma unroll
        for (int j = 0; j < 4; j++)
            #pragma unroll
            for (int q = 0; q < 4; q++) acc[i][j][q] = 0.f;

    int nCh = Kdim / KCH;

    auto load_stage = [&](int kt, int st){
        size_t koff = (size_t)kt * KCH;
        uint32_t sb = sm + (uint32_t)st*STAGE_B;
        size_t gA0 = (size_t)r0*Kdim + koff + (size_t)c0v*8;
        size_t gA1 = (size_t)r1*Kdim + koff + (size_t)c1v*8;
        cp16(sb + soA0, Aptr + gA0);
        cp16(sb + soA1, Aptr + gA1);
        cp16(sb + ATILE_B + soB,          Bptr + (koff + rB)*(size_t)N + cB*8);
        cp16(sb + ATILE_B + soB + 16*272, Bptr + (koff + rB + 16)*(size_t)N + cB*8);
        asm volatile("cp.async.commit_group;");
    };

    load_stage(0, 0);
    for (int kt = 0; kt < nCh; kt++) {
        int st = kt & 1;
        if (kt + 1 < nCh) {
            load_stage(kt + 1, st ^ 1);
            asm volatile("cp.async.wait_group 1;");
        } else {
            asm volatile("cp.async.wait_group 0;");
        }
        __syncthreads();

        uint32_t sA32 = sm + (uint32_t)st*STAGE_B;
        uint32_t sB32 = sA32 + ATILE_B;

        #pragma unroll
        for (int k16 = 0; k16 < 2; k16++) {
            uint32_t kbA = (uint32_t)k16 * 32;          // A: 16 halves
            uint32_t kbB = (uint32_t)k16 * (16*272);    // B: 16 k-rows
            uint32_t a[4][4], bh[4][2];
            #pragma unroll
            for (int j = 0; j < 2; j++) {
                uint32_t r4[4];
                ldsm_x4_t(r4, sB32 + kbB + bTransBase + nWb + (uint32_t)j*32);
                bh[2*j][0]   = r4[0]; bh[2*j][1]   = r4[1];
                bh[2*j+1][0] = r4[2]; bh[2*j+1][1] = r4[3];
            }
            #pragma unroll
            for (int mt = 0; mt < 4; mt++)
                ldsm_x4(a[mt], sA32 + aWarp + aOff + mt*(16*LDA*2) + kbA);
            #pragma unroll
            for (int mt = 0; mt < 4; mt++)
                #pragma unroll
                for (int nt = 0; nt < 4; nt++)
                    mma16816(acc[mt][nt], a[mt], bh[nt]);
        }
        __syncthreads();
    }

    // ---------------- epilogue ----------------
    const float* bias = biasbase ? biasbase + (size_t)e*N : nullptr;
    int mWarp = rowBase + warpRow*64;
    int nWarp = colBase + warpCol*32;
    int rq = lane >> 2, cq = (lane & 3)*2;

    #pragma unroll
    for (int mt = 0; mt < 4; mt++) {
        #pragma unroll
        for (int nt = 0; nt < 4; nt++) {
            int col = nWarp + nt*8 + cq;
            float b0 = bias ? bias[col] : 0.f;
            float b1 = bias ? bias[col+1] : 0.f;
            #pragma unroll
            for (int half = 0; half < 2; half++) {
                int row = mWarp + mt*16 + rq + half*8;
                float v0 = acc[mt][nt][2*half+0] + b0;
                float v1 = acc[mt][nt][2*half+1] + b1;
                if (doRelu) { v0 = fmaxf(v0, 0.f); v1 = fmaxf(v1, 0.f); }
                size_t o = ((size_t)p*S_ + row)*N + col;
                if (outF) *(float2*)(outF + o) = make_float2(v0, v1);
                if (outH) {
                    __half2 hv = __floats2half2_rn(v0, v1);
                    *(__half2*)(outH + o) = hv;
                }
            }
        }
    }
}

// ---------------- fused causal attention (2 threads per query) ---------------
__global__ __launch_bounds__(256) void attn_kernel()
{
    int p = blockIdx.x, h = blockIdx.y;
    int e = p / B_, b = p % B_;
    if (g_gates[b*E_ + e] == 0.f) return;
    __shared__ __align__(16) float Ks[64][72];
    __shared__ __align__(16) float Vs[64][72];
    int tid = threadIdx.x;
    int lane = tid & 31;
    unsigned pmask = 3u << (lane & 30);   // pair mask: lanes {2i, 2i+1} only
    int q = blockIdx.z*128 + (tid >> 1);
    int hf = tid & 1;
    int cb = hf * 36;    // halves stored at cols 0..31 and 36..67 (bank-skewed)

    float qreg[32];
    {
        const float* qp = &g_q[((size_t)p*S_ + q)*D_ + h*HD_ + hf*32];
        #pragma unroll
        for (int i = 0; i < 32; i += 4) {
            float4 t = *reinterpret_cast<const float4*>(qp + i);
            qreg[i] = t.x; qreg[i+1] = t.y; qreg[i+2] = t.z; qreg[i+3] = t.w;
        }
    }
    float acc[32];
    #pragma unroll
    for (int i = 0; i < 32; i++) acc[i] = 0.f;
    float m = -CUDART_INF_F, l = 0.f;

    int ntile = (blockIdx.z == 0) ? 2 : 4;
    for (int t = 0; t < ntile; t++) {
        #pragma unroll
        for (int pass = 0; pass < 4; pass++) {
            int r = pass*16 + (tid >> 4);
            int c = (tid & 15) * 4;
            int cs = c + ((c >= 32) ? 4 : 0);
            size_t off = ((size_t)p*S_ + t*64 + r)*D_ + h*HD_ + c;
            *reinterpret_cast<float4*>(&Ks[r][cs]) = *reinterpret_cast<const float4*>(&g_k[off]);
            *reinterpret_cast<float4*>(&Vs[r][cs]) = *reinterpret_cast<const float4*>(&g_v[off]);
        }
        __syncthreads();
        int kmax = q - t*64;
        if (kmax > 63) kmax = 63;
        for (int kk = 0; kk <= kmax; kk++) {
            const float* kr = &Ks[kk][cb];
            float d0 = 0.f, d1 = 0.f, d2 = 0.f, d3 = 0.f;
            #pragma unroll
            for (int i = 0; i < 32; i += 4) {
                d0 = fmaf(qreg[i+0], kr[i+0], d0);
                d1 = fmaf(qreg[i+1], kr[i+1], d1);
                d2 = fmaf(qreg[i+2], kr[i+2], d2);
                d3 = fmaf(qreg[i+3], kr[i+3], d3);
            }
            float s = (d0 + d1) + (d2 + d3);
            s += __shfl_xor_sync(pmask, s, 1);     // pair-convergent: same q, same kmax
            s *= SCALE_;
            float mn = fmaxf(m, s);
            float corr = __expf(m - mn);
            float pw = __expf(s - mn);
            l = l*corr + pw;
            const float* vr = &Vs[kk][cb];
            #pragma unroll
            for (int i = 0; i < 32; i++) acc[i] = fmaf(acc[i], corr, pw*vr[i]);
            m = mn;
        }
        __syncthreads();
    }
    float invl = 1.f / l;
    size_t ob = ((size_t)p*S_ + q)*D_ + h*HD_ + hf*32;
    #pragma unroll
    for (int i = 0; i < 32; i += 2) {
        __half2 hv = __floats2half2_rn(acc[i]*invl, acc[i+1]*invl);
        *(__half2*)(&g_ath[ob + i]) = hv;
    }
}

// ---------------- block reduce (sum, sumsq), blockDim = 256 -----------------
__device__ __forceinline__ float2 block_reduce2(float a, float b)
{
    __shared__ float2 sh[9];
    int tid = threadIdx.x, lane = tid & 31, wid = tid >> 5;
    #pragma unroll
    for (int o = 16; o > 0; o >>= 1) {
        a += __shfl_xor_sync(0xffffffffu, a, o);
        b += __shfl_xor_sync(0xffffffffu, b, o);
    }
    if (lane == 0) sh[wid] = make_float2(a, b);
    __syncthreads();
    if (tid == 0) {
        float sa = 0.f, sb = 0.f;
        #pragma unroll
        for (int w = 0; w < 8; w++) { sa += sh[w].x; sb += sh[w].y; }
        sh[8] = make_float2(sa, sb);
    }
    __syncthreads();
    float2 r = sh[8];
    __syncthreads();
    return r;
}

// ---------------- h1 = LN(x + oproj)*g1+be1 : fp32 + fp16 -------------------
__global__ __launch_bounds__(256) void addln_kernel(
    const float* __restrict__ xbase, const float* __restrict__ res,
    const float* __restrict__ gain, const float* __restrict__ beta,
    float* __restrict__ out)
{
    int p = blockIdx.x; int e = p / B_, b = p % B_;
    if (g_gates[b*E_ + e] == 0.f) return;
    int s = blockIdx.y, tid = threadIdx.x;
    const float* xr = xbase + ((size_t)b*S_ + s)*D_;
    const float* rr = res + ((size_t)p*S_ + s)*D_;
    float v[4]; float sum = 0.f, sq = 0.f;
    #pragma unroll
    for (int j = 0; j < 4; j++) {
        int i = tid + j*256;
        float t = xr[i] + rr[i];
        v[j] = t; sum += t; sq = fmaf(t, t, sq);
    }
    float2 r = block_reduce2(sum, sq);
    float mean = r.x * (1.f/D_);
    float var = r.y * (1.f/D_) - mean*mean;
    float rstd = rsqrtf(var + 1e-5f);
    size_t ob = ((size_t)p*S_ + s)*D_;
    #pragma unroll
    for (int j = 0; j < 4; j++) {
        int i = tid + j*256;
        float o = (v[j] - mean)*rstd*gain[e*D_ + i] + beta[e*D_ + i];
        out[ob + i] = o;
        g_h1h[ob + i] = __float2half_rn(o);
    }
}

// ---------------- y = sum_e gate * LN(h1 + ff2), eps-fill -------------------
__global__ __launch_bounds__(256) void final_kernel(
    const float* __restrict__ h1, const float* __restrict__ f2,
    const float* __restrict__ g2, const float* __restrict__ be2,
    float* __restrict__ y)
{
    int b = blockIdx.x, s = blockIdx.y, tid = threadIdx.x;
    float acc[4] = {0.f, 0.f, 0.f, 0.f};
    for (int e = 0; e < E_; e++) {
        float gv = g_gates[b*E_ + e];
        if (gv == 0.f) continue;
        int p = e*B_ + b;
        const float* hr = h1 + ((size_t)p*S_ + s)*D_;
        const float* fr = f2 + ((size_t)p*S_ + s)*D_;
        float v[4]; float sum = 0.f, sq = 0.f;
        #pragma unroll
        for (int j = 0; j < 4; j++) {
            int i = tid + j*256;
            float t = hr[i] + fr[i];
            v[j] = t; sum += t; sq = fmaf(t, t, sq);
        }
        float2 r = block_reduce2(sum, sq);
        float mean = r.x * (1.f/D_);
        float var = r.y * (1.f/D_) - mean*mean;
        float rstd = rsqrtf(var + 1e-5f);
        #pragma unroll
        for (int j = 0; j < 4; j++) {
            int i = tid + j*256;
            acc[j] += gv * ((v[j]-mean)*rstd*g2[e*D_+i] + be2[e*D_+i]);
        }
    }
    float* yr = y + ((size_t)b*S_ + s)*D_;
    #pragma unroll
    for (int j = 0; j < 4; j++) {
        int i = tid + j*256;
        float o = acc[j];
        if (o == 0.f) o = EPS_FILL_F;
        yr[i] = o;
    }
}

// ---------------- launch ----------------------------------------------------
extern "C" void kernel_launch(void* const* d_in, const int* in_sizes, int n_in,
                              void* d_out, int out_size)
{
    const float* x       = (const float*)d_in[0];
    const float* noise   = (const float*)d_in[2];
    const float* w_gate  = (const float*)d_in[3];
    const float* w_noise = (const float*)d_in[4];
    const float* Wq      = (const float*)d_in[5];
    const float* Wk      = (const float*)d_in[6];
    const float* Wv      = (const float*)d_in[7];
    const float* Wo      = (const float*)d_in[8];
    const float* W1      = (const float*)d_in[9];
    const float* b1      = (const float*)d_in[10];
    const float* W2      = (const float*)d_in[11];
    const float* b2      = (const float*)d_in[12];
    const float* g1      = (const float*)d_in[13];
    const float* be1     = (const float*)d_in[14];
    const float* g2      = (const float*)d_in[15];
    const float* be2     = (const float*)d_in[16];
    float* out = (float*)d_out;

    float *pQ, *pK, *pV;
    __half *pXh, *pAth, *pH1h, *pFFh;
    __half *pWq, *pWk, *pWv, *pWo, *pW1, *pW2;
    cudaGetSymbolAddress((void**)&pQ,   g_q);
    cudaGetSymbolAddress((void**)&pK,   g_k);
    cudaGetSymbolAddress((void**)&pV,   g_v);
    cudaGetSymbolAddress((void**)&pXh,  g_xh);
    cudaGetSymbolAddress((void**)&pAth, g_ath);
    cudaGetSymbolAddress((void**)&pH1h, g_h1h);
    cudaGetSymbolAddress((void**)&pFFh, g_ffh);
    cudaGetSymbolAddress((void**)&pWq,  g_wqH);
    cudaGetSymbolAddress((void**)&pWk,  g_wkH);
    cudaGetSymbolAddress((void**)&pWv,  g_wvH);
    cudaGetSymbolAddress((void**)&pWo,  g_woH);
    cudaGetSymbolAddress((void**)&pW1,  g_w1H);
    cudaGetSymbolAddress((void**)&pW2,  g_w2H);

    cudaFuncSetAttribute(tgemm_kernel, cudaFuncAttributeMaxDynamicSharedMemorySize, SMEM_GEMM);

    const long SD  = (long)S_*D_;
    const long BSD = (long)B_*S_*D_;
    const long SF  = (long)S_*FF_;
    const long BSF = (long)B_*S_*FF_;

    // gating path
    sumx_kernel<<<dim3(D_/256, B_), 256>>>(x);
    gate_kernel<<<1, 1024>>>(w_gate, w_noise, noise, out + (size_t)B_*S_*D_);

    // single coalesced convert: all 6 weights + x -> fp16 (original [K][N] layouts)
    convert_all_kernel<<<NCONV_BLOCKS, 256>>>(Wq, Wk, Wv, Wo, W1, W2, x);

    // fused QKV projections: sel = blockIdx.y/8 picks {Wq,Wk,Wv} and {pQ,pK,pV}
    tgemm_kernel<<<dim3(2, 3*(D_/128), NPAIR), 256, SMEM_GEMM>>>(
        pXh, pWq, pWk, pWv,
        nullptr, pQ, pK, pV, nullptr, D_, D_, 0, SD, 0);

    // attention (fp32 in, writes fp16), 2 CTAs per (p,h)
    attn_kernel<<<dim3(NPAIR, H_, 2), 256>>>();

    // O projection -> fp32 (reuse g_q)
    tgemm_kernel<<<dim3(2, D_/128, NPAIR), 256, SMEM_GEMM>>>(
        pAth, pWo, pWo, pWo,
        nullptr, pQ, nullptr, nullptr, nullptr, D_, D_, BSD, SD, 0);

    // h1 = LN(x + oproj): fp32 into g_k, fp16 into g_h1h
    addln_kernel<<<dim3(NPAIR, S_), 256>>>(x, pQ, g1, be1, pK);

    // FFN1: relu(h1 @ W1 + b1) -> fp16
    tgemm_kernel<<<dim3(2, FF_/128, NPAIR), 256, SMEM_GEMM>>>(
        pH1h, pW1, pW1, pW1,
        b1, nullptr, nullptr, nullptr, pFFh, D_, FF_, BSD, SD, 1);

    // FFN2: ff @ W2 + b2 -> fp32 (reuse g_v)
    tgemm_kernel<<<dim3(2, D_/128, NPAIR), 256, SMEM_GEMM>>>(
        pFFh, pW2, pW2, pW2,
        b2, pV, nullptr, nullptr, nullptr, FF_, D_, BSF, SF, 0);

    // combine
    final_kernel<<<dim3(B_, S_), 256>>>(pK, pV, g2, be2, out);
}

// round 16
// speedup vs baseline: 4.8249x; 1.0344x over previous
#include <cuda_runtime.h>
#include <cuda_fp16.h>
#include <math_constants.h>
#include <cstdint>

#define B_ 8
#define S_ 256
#define D_ 1024
#define H_ 16
#define E_ 4
#define FF_ 4096
#define HD_ 64
#define NPAIR (E_*B_)
#define SCALE_ 0.125f
#define EPS_FILL_F 2.2204460492503131e-16f
#define KCH 32
#define LDA 40                        // padded A row (halves) for 128x32 tiles
#define ATILE_B (128*LDA*2)           // 10240 bytes
#define BTILE_B (32*272)              // 8704 bytes ([K=32][N=128] fp16, 272B padded rows)
#define STAGE_B (ATILE_B + BTILE_B)   // 18944
#define NSTAGE 3
#define SMEM_GEMM (NSTAGE*STAGE_B)    // 56832

// ---------------- scratch (device globals: no allocations allowed) ----------
__device__ float g_xs[B_*D_];
__device__ float g_gates[B_*E_];
__device__ float g_q[(size_t)NPAIR*S_*D_];
__device__ float g_k[(size_t)NPAIR*S_*D_];   // later reused as h1 (fp32)
__device__ float g_v[(size_t)NPAIR*S_*D_];   // later reused as ffn2 out (fp32)
__device__ __half g_xh[(size_t)B_*S_*D_];
__device__ __half g_ath[(size_t)NPAIR*S_*D_];
__device__ __half g_h1h[(size_t)NPAIR*S_*D_];
__device__ __half g_ffh[(size_t)NPAIR*S_*FF_];
// fp16 weights, ORIGINAL layout [e][K][N]
__device__ __half g_wqH[(size_t)E_*D_*D_];
__device__ __half g_wkH[(size_t)E_*D_*D_];
__device__ __half g_wvH[(size_t)E_*D_*D_];
__device__ __half g_woH[(size_t)E_*D_*D_];
__device__ __half g_w1H[(size_t)E_*D_*FF_];
__device__ __half g_w2H[(size_t)E_*D_*FF_];

// ---------------- helpers ----------------
__device__ __forceinline__ uint32_t smem_u32(const void* p){
    uint32_t a;
    asm("{ .reg .u64 t; cvta.to.shared.u64 t, %1; cvt.u32.u64 %0, t; }" : "=r"(a) : "l"(p));
    return a;
}
__device__ __forceinline__ void ldsm_x4(uint32_t (&r)[4], uint32_t addr){
    asm volatile("ldmatrix.sync.aligned.m8n8.x4.shared.b16 {%0,%1,%2,%3}, [%4];"
                 : "=r"(r[0]),"=r"(r[1]),"=r"(r[2]),"=r"(r[3]) : "r"(addr));
}
__device__ __forceinline__ void ldsm_x4_t(uint32_t (&r)[4], uint32_t addr){
    asm volatile("ldmatrix.sync.aligned.m8n8.x4.trans.shared.b16 {%0,%1,%2,%3}, [%4];"
                 : "=r"(r[0]),"=r"(r[1]),"=r"(r[2]),"=r"(r[3]) : "r"(addr));
}
__device__ __forceinline__ void mma16816(float (&c)[4], const uint32_t (&a)[4], const uint32_t (&b)[2]){
    asm volatile("mma.sync.aligned.m16n8k16.row.col.f32.f16.f16.f32 "
                 "{%0,%1,%2,%3},{%4,%5,%6,%7},{%8,%9},{%0,%1,%2,%3};"
                 : "+f"(c[0]),"+f"(c[1]),"+f"(c[2]),"+f"(c[3])
                 : "r"(a[0]),"r"(a[1]),"r"(a[2]),"r"(a[3]),"r"(b[0]),"r"(b[1]));
}
__device__ __forceinline__ void cp16(uint32_t s, const void* g){
    asm volatile("cp.async.cg.shared.global [%0], [%1], 16;" :: "r"(s), "l"(g));
}

// ---------------- xs = x.sum(axis=1) ----------------
__global__ void sumx_kernel(const float* __restrict__ x)
{
    int d = blockIdx.x*256 + threadIdx.x;
    int b = blockIdx.y;
    const float* xp = x + (size_t)b*S_*D_ + d;
    float acc = 0.f;
    #pragma unroll 4
    for (int s = 0; s < S_; s++) acc += xp[(size_t)s*D_];
    g_xs[b*D_ + d] = acc;
}

// ---------------- noisy top-k gating + aux loss ----------------
__global__ void gate_kernel(const float* __restrict__ w_gate,
                            const float* __restrict__ w_noise,
                            const float* __restrict__ noise,
                            float* __restrict__ loss_out)
{
    __shared__ float s_clean[B_][E_], s_raw[B_][E_], s_prob[B_][E_], s_gate[B_][E_];
    int tid = threadIdx.x;
    int wid = tid >> 5, lane = tid & 31;
    {
        int b = wid >> 2, e = wid & 3;
        float ac = 0.f, ar = 0.f;
        for (int i = lane; i < D_; i += 32) {
            float xv = g_xs[b*D_ + i];
            ac = fmaf(xv, w_gate[i*E_ + e], ac);
            ar = fmaf(xv, w_noise[i*E_ + e], ar);
        }
        #pragma unroll
        for (int o = 16; o > 0; o >>= 1) {
            ac += __shfl_xor_sync(0xffffffffu, ac, o);
            ar += __shfl_xor_sync(0xffffffffu, ar, o);
        }
        if (lane == 0) { s_clean[b][e] = ac; s_raw[b][e] = ar; }
    }
    __syncthreads();
    if (tid < B_) {
        int b = tid;
        float clean[E_], noisy[E_], sd[E_];
        #pragma unroll
        for (int e = 0; e < E_; e++) {
            clean[e] = s_clean[b][e];
            float r = s_raw[b][e];
            float sp = fmaxf(r, 0.f) + log1pf(expf(-fabsf(r)));
            sd[e] = sp + 0.01f;
            noisy[e] = clean[e] + noise[b*E_ + e] * sd[e];
        }
        int ord[3]; bool used[E_] = {false,false,false,false};
        for (int s = 0; s < 3; s++) {
            int best = -1;
            for (int e = 0; e < E_; e++)
                if (!used[e] && (best < 0 || noisy[e] > noisy[best])) best = e;
            used[best] = true; ord[s] = best;
        }
        float l0 = noisy[ord[0]], l1 = noisy[ord[1]], l2 = noisy[ord[2]];
        float e1 = expf(l1 - l0);
        float inv = 1.f / (1.f + e1);
        #pragma unroll
        for (int e = 0; e < E_; e++) s_gate[b][e] = 0.f;
        s_gate[b][ord[0]] = inv;
        s_gate[b][ord[1]] = e1 * inv;
        #pragma unroll
        for (int e = 0; e < E_; e++) {
            bool isin = noisy[e] > l2;
            float thr = isin ? l2 : l1;
            s_prob[b][e] = normcdff((clean[e] - thr) / sd[e]);
            g_gates[b*E_ + e] = s_gate[b][e];
        }
    }
    __syncthreads();
    if (tid == 0) {
        float cv[2];
        for (int which = 0; which < 2; which++) {
            float v[E_];
            for (int e = 0; e < E_; e++) {
                float s = 0.f;
                for (int b = 0; b < B_; b++)
                    s += which ? s_prob[b][e] : s_gate[b][e];
                v[e] = s;
            }
            float m = (v[0]+v[1]+v[2]+v[3]) * 0.25f;
            float var = 0.f;
            for (int e = 0; e < E_; e++) { float dd = v[e]-m; var += dd*dd; }
            var *= (1.0f / (E_ - 1));
            cv[which] = var / (m*m + 1e-10f);
        }
        loss_out[0] = (cv[0] + cv[1]) * 0.01f;
    }
}

// ---------------- single coalesced fp32->fp16 convert (weights + x) ---------
#define BWD (E_*D_*D_/2048)     // blocks per DxD weight
#define BWF (E_*D_*FF_/2048)    // blocks per DxFF weight
#define BX  (B_*S_*D_/2048)     // blocks for x
#define NCONV_BLOCKS (4*BWD + 2*BWF + BX)

__global__ void convert_all_kernel(const float* __restrict__ Wq, const float* __restrict__ Wk,
                                   const float* __restrict__ Wv, const float* __restrict__ Wo,
                                   const float* __restrict__ W1, const float* __restrict__ W2,
                                   const float* __restrict__ x)
{
    int blk = blockIdx.x;
    const float* src; __half* dst;
    if      (blk < 1*BWD)       { src = Wq; dst = g_wqH; }
    else if (blk < 2*BWD)       { src = Wk; dst = g_wkH; blk -= 1*BWD; }
    else if (blk < 3*BWD)       { src = Wv; dst = g_wvH; blk -= 2*BWD; }
    else if (blk < 4*BWD)       { src = Wo; dst = g_woH; blk -= 3*BWD; }
    else if (blk < 4*BWD+BWF)   { src = W1; dst = g_w1H; blk -= 4*BWD; }
    else if (blk < 4*BWD+2*BWF) { src = W2; dst = g_w2H; blk -= 4*BWD+BWF; }
    else                        { src = x;  dst = g_xh;  blk -= 4*BWD+2*BWF; }
    size_t i = ((size_t)blk*256 + threadIdx.x)*8;
    float4 a = *(const float4*)(src + i);
    float4 c = *(const float4*)(src + i + 4);
    __half2 h0 = __floats2half2_rn(a.x, a.y), h1 = __floats2half2_rn(a.z, a.w);
    __half2 h2 = __floats2half2_rn(c.x, c.y), h3 = __floats2half2_rn(c.z, c.w);
    uint4 o;
    o.x = *reinterpret_cast<uint32_t*>(&h0);
    o.y = *reinterpret_cast<uint32_t*>(&h1);
    o.z = *reinterpret_cast<uint32_t*>(&h2);
    o.w = *reinterpret_cast<uint32_t*>(&h3);
    *reinterpret_cast<uint4*>(dst + i) = o;
}

// ---------------- HMMA fp16 GEMM, cp.async 3-stage, B from [K][N] layout -----
// Up to 3 weight groups (Q/K/V fused): sel = blockIdx.y / (N/128)
__global__ __launch_bounds__(256) void tgemm_kernel(
    const __half* __restrict__ A0,
    const __half* __restrict__ Bw0, const __half* __restrict__ Bw1, const __half* __restrict__ Bw2,
    const float* __restrict__ biasbase,
    float* __restrict__ outF0, float* __restrict__ outF1, float* __restrict__ outF2,
    __half* __restrict__ outH,
    int Kdim, int N, long sAe, long sAb, int doRelu)
{
    int p = blockIdx.z, e = p >> 3, b = p & 7;
    if (g_gates[b*E_ + e] == 0.f) return;

    int nGC = N >> 7;
    int sel = blockIdx.y / nGC;
    int colBase = (blockIdx.y % nGC) * 128;
    const __half* Bw = (sel == 0) ? Bw0 : (sel == 1) ? Bw1 : Bw2;
    float* outF = (sel == 0) ? outF0 : (sel == 1) ? outF1 : outF2;

    extern __shared__ char smem[];
    uint32_t sm = smem_u32(smem);

    int tid = threadIdx.x, wid = tid >> 5, lane = tid & 31;
    int warpRow = wid >> 2;        // 0..1  (64 rows each)
    int warpCol = wid & 3;         // 0..3  (32 cols each)
    int rowBase = blockIdx.x * 128;

    const __half* Aptr = A0 + (size_t)e*sAe + (size_t)b*sAb + (size_t)rowBase*Kdim;
    const __half* Bptr = Bw + (size_t)e*((size_t)Kdim*N) + colBase;   // [K][N] layout

    // A ldmatrix byte offsets (row-major, non-trans)
    uint32_t aOff = (uint32_t)((lane & 15) * (LDA*2)) + ((lane >> 4) * 16);
    uint32_t aWarp = (uint32_t)(warpRow * 64) * (LDA*2);
    // B ldmatrix.trans lane base: matrices (k0-7,n0-7),(k8-15,n0-7),(k0-7,n8-15),(k8-15,n8-15)
    int mlane = lane >> 3, rlane = lane & 7;
    uint32_t bTransBase = (uint32_t)(((mlane & 1)*8 + rlane) * 272 + (mlane >> 1) * 16);
    uint32_t nWb = (uint32_t)(warpCol * 32) * 2;   // warp's n-range byte offset

    // cp.async indices
    int r0 = tid >> 2, c0v = tid & 3;              // A: 2 vecs (128x32 tile)
    int r1 = (256 + tid) >> 2, c1v = tid & 3;
    uint32_t soA0 = (uint32_t)r0*(LDA*2) + (uint32_t)c0v*16;
    uint32_t soA1 = (uint32_t)r1*(LDA*2) + (uint32_t)c1v*16;
    int rB = tid >> 4, cB = tid & 15;              // B: 2 vecs (32x128 tile, 256B rows + pad)
    uint32_t soB = (uint32_t)rB*272 + (uint32_t)cB*16;

    float acc[4][4][4];
    #pragma unroll
    for (int i = 0; i < 4; i++)
        #pragma unroll
        for (int j = 0; j < 4; j++)
            #pragma unroll
            for (int q = 0; q < 4; q++) acc[i][j][q] = 0.f;

    int nCh = Kdim / KCH;

    auto load_stage = [&](int kt, int st){
        size_t koff = (size_t)kt * KCH;
        uint32_t sb = sm + (uint32_t)st*STAGE_B;
        size_t gA0 = (size_t)r0*Kdim + koff + (size_t)c0v*8;
        size_t gA1 = (size_t)r1*Kdim + koff + (size_t)c1v*8;
        cp16(sb + soA0, Aptr + gA0);
        cp16(sb + soA1, Aptr + gA1);
        cp16(sb + ATILE_B + soB,          Bptr + (koff + rB)*(size_t)N + cB*8);
        cp16(sb + ATILE_B + soB + 16*272, Bptr + (koff + rB + 16)*(size_t)N + cB*8);
        asm volatile("cp.async.commit_group;");
    };

    // 3-stage pipeline: one __syncthreads per chunk.
    load_stage(0, 0);
    if (nCh > 1) load_stage(1, 1);
    for (int kt = 0; kt < nCh; kt++) {
        int st = kt % NSTAGE;
        if (kt + 1 < nCh) {
            asm volatile("cp.async.wait_group 1;");
        } else {
            asm volatile("cp.async.wait_group 0;");
        }
        // Barrier: (a) load kt visible to all warps, (b) all warps done with
        // compute kt-1 so its buffer ((kt+2)%3) may be overwritten below.
        __syncthreads();
        if (kt + 2 < nCh) load_stage(kt + 2, (kt + 2) % NSTAGE);

        uint32_t sA32 = sm + (uint32_t)st*STAGE_B;
        uint32_t sB32 = sA32 + ATILE_B;

        #pragma unroll
        for (int k16 = 0; k16 < 2; k16++) {
            uint32_t kbA = (uint32_t)k16 * 32;          // A: 16 halves
            uint32_t kbB = (uint32_t)k16 * (16*272);    // B: 16 k-rows
            uint32_t a[4][4], bh[4][2];
            #pragma unroll
            for (int j = 0; j < 2; j++) {
                uint32_t r4[4];
                ldsm_x4_t(r4, sB32 + kbB + bTransBase + nWb + (uint32_t)j*32);
                bh[2*j][0]   = r4[0]; bh[2*j][1]   = r4[1];
                bh[2*j+1][0] = r4[2]; bh[2*j+1][1] = r4[3];
            }
            #pragma unroll
            for (int mt = 0; mt < 4; mt++)
                ldsm_x4(a[mt], sA32 + aWarp + aOff + mt*(16*LDA*2) + kbA);
            #pragma unroll
            for (int mt = 0; mt < 4; mt++)
                #pragma unroll
                for (int nt = 0; nt < 4; nt++)
                    mma16816(acc[mt][nt], a[mt], bh[nt]);
        }
    }

    // ---------------- epilogue ----------------
    const float* bias = biasbase ? biasbase + (size_t)e*N : nullptr;
    int mWarp = rowBase + warpRow*64;
    int nWarp = colBase + warpCol*32;
    int rq = lane >> 2, cq = (lane & 3)*2;

    #pragma unroll
    for (int mt = 0; mt < 4; mt++) {
        #pragma unroll
        for (int nt = 0; nt < 4; nt++) {
            int col = nWarp + nt*8 + cq;
            float b0 = bias ? bias[col] : 0.f;
            float b1 = bias ? bias[col+1] : 0.f;
            #pragma unroll
            for (int half = 0; half < 2; half++) {
                int row = mWarp + mt*16 + rq + half*8;
                float v0 = acc[mt][nt][2*half+0] + b0;
                float v1 = acc[mt][nt][2*half+1] + b1;
                if (doRelu) { v0 = fmaxf(v0, 0.f); v1 = fmaxf(v1, 0.f); }
                size_t o = ((size_t)p*S_ + row)*N + col;
                if (outF) *(float2*)(outF + o) = make_float2(v0, v1);
                if (outH) {
                    __half2 hv = __floats2half2_rn(v0, v1);
                    *(__half2*)(outH + o) = hv;
                }
            }
        }
    }
}

// ---------------- fused causal attention (2 threads per query) ---------------
__global__ __launch_bounds__(256) void attn_kernel()
{
    int p = blockIdx.x, h = blockIdx.y;
    int e = p / B_, b = p % B_;
    if (g_gates[b*E_ + e] == 0.f) return;
    __shared__ __align__(16) float Ks[64][72];
    __shared__ __align__(16) float Vs[64][72];
    int tid = threadIdx.x;
    int lane = tid & 31;
    unsigned pmask = 3u << (lane & 30);   // pair mask: lanes {2i, 2i+1} only
    int q = blockIdx.z*128 + (tid >> 1);
    int hf = tid & 1;
    int cb = hf * 36;    // halves stored at cols 0..31 and 36..67 (bank-skewed)

    float qreg[32];
    {
        const float* qp = &g_q[((size_t)p*S_ + q)*D_ + h*HD_ + hf*32];
        #pragma unroll
        for (int i = 0; i < 32; i += 4) {
            float4 t = *reinterpret_cast<const float4*>(qp + i);
            qreg[i] = t.x; qreg[i+1] = t.y; qreg[i+2] = t.z; qreg[i+3] = t.w;
        }
    }
    float acc[32];
    #pragma unroll
    for (int i = 0; i < 32; i++) acc[i] = 0.f;
    float m = -CUDART_INF_F, l = 0.f;

    int ntile = (blockIdx.z == 0) ? 2 : 4;
    for (int t = 0; t < ntile; t++) {
        #pragma unroll
        for (int pass = 0; pass < 4; pass++) {
            int r = pass*16 + (tid >> 4);
            int c = (tid & 15) * 4;
            int cs = c + ((c >= 32) ? 4 : 0);
            size_t off = ((size_t)p*S_ + t*64 + r)*D_ + h*HD_ + c;
            *reinterpret_cast<float4*>(&Ks[r][cs]) = *reinterpret_cast<const float4*>(&g_k[off]);
            *reinterpret_cast<float4*>(&Vs[r][cs]) = *reinterpret_cast<const float4*>(&g_v[off]);
        }
        __syncthreads();
        int kmax = q - t*64;
        if (kmax > 63) kmax = 63;
        for (int kk = 0; kk <= kmax; kk++) {
            const float* kr = &Ks[kk][cb];
            float d0 = 0.f, d1 = 0.f, d2 = 0.f, d3 = 0.f;
            #pragma unroll
            for (int i = 0; i < 32; i += 4) {
                d0 = fmaf(qreg[i+0], kr[i+0], d0);
                d1 = fmaf(qreg[i+1], kr[i+1], d1);
                d2 = fmaf(qreg[i+2], kr[i+2], d2);
                d3 = fmaf(qreg[i+3], kr[i+3], d3);
            }
            float s = (d0 + d1) + (d2 + d3);
            s += __shfl_xor_sync(pmask, s, 1);     // pair-convergent: same q, same kmax
            s *= SCALE_;
            float mn = fmaxf(m, s);
            float corr = __expf(m - mn);
            float pw = __expf(s - mn);
            l = l*corr + pw;
            const float* vr = &Vs[kk][cb];
            #pragma unroll
            for (int i = 0; i < 32; i++) acc[i] = fmaf(acc[i], corr, pw*vr[i]);
            m = mn;
        }
        __syncthreads();
    }
    float invl = 1.f / l;
    size_t ob = ((size_t)p*S_ + q)*D_ + h*HD_ + hf*32;
    #pragma unroll
    for (int i = 0; i < 32; i += 2) {
        __half2 hv = __floats2half2_rn(acc[i]*invl, acc[i+1]*invl);
        *(__half2*)(&g_ath[ob + i]) = hv;
    }
}

// ---------------- block reduce (sum, sumsq), blockDim = 256 -----------------
__device__ __forceinline__ float2 block_reduce2(float a, float b)
{
    __shared__ float2 sh[9];
    int tid = threadIdx.x, lane = tid & 31, wid = tid >> 5;
    #pragma unroll
    for (int o = 16; o > 0; o >>= 1) {
        a += __shfl_xor_sync(0xffffffffu, a, o);
        b += __shfl_xor_sync(0xffffffffu, b, o);
    }
    if (lane == 0) sh[wid] = make_float2(a, b);
    __syncthreads();
    if (tid == 0) {
        float sa = 0.f, sb = 0.f;
        #pragma unroll
        for (int w = 0; w < 8; w++) { sa += sh[w].x; sb += sh[w].y; }
        sh[8] = make_float2(sa, sb);
    }
    __syncthreads();
    float2 r = sh[8];
    __syncthreads();
    return r;
}

// ---------------- h1 = LN(x + oproj)*g1+be1 : fp32 + fp16 -------------------
__global__ __launch_bounds__(256) void addln_kernel(
    const float* __restrict__ xbase, const float* __restrict__ res,
    const float* __restrict__ gain, const float* __restrict__ beta,
    float* __restrict__ out)
{
    int p = blockIdx.x; int e = p / B_, b = p % B_;
    if (g_gates[b*E_ + e] == 0.f) return;
    int s = blockIdx.y, tid = threadIdx.x;
    const float* xr = xbase + ((size_t)b*S_ + s)*D_;
    const float* rr = res + ((size_t)p*S_ + s)*D_;
    float v[4]; float sum = 0.f, sq = 0.f;
    #pragma unroll
    for (int j = 0; j < 4; j++) {
        int i = tid + j*256;
        float t = xr[i] + rr[i];
        v[j] = t; sum += t; sq = fmaf(t, t, sq);
    }
    float2 r = block_reduce2(sum, sq);
    float mean = r.x * (1.f/D_);
    float var = r.y * (1.f/D_) - mean*mean;
    float rstd = rsqrtf(var + 1e-5f);
    size_t ob = ((size_t)p*S_ + s)*D_;
    #pragma unroll
    for (int j = 0; j < 4; j++) {
        int i = tid + j*256;
        float o = (v[j] - mean)*rstd*gain[e*D_ + i] + beta[e*D_ + i];
        out[ob + i] = o;
        g_h1h[ob + i] = __float2half_rn(o);
    }
}

// ---------------- y = sum_e gate * LN(h1 + ff2), eps-fill -------------------
__global__ __launch_bounds__(256) void final_kernel(
    const float* __restrict__ h1, const float* __restrict__ f2,
    const float* __restrict__ g2, const float* __restrict__ be2,
    float* __restrict__ y)
{
    int b = blockIdx.x, s = blockIdx.y, tid = threadIdx.x;
    float acc[4] = {0.f, 0.f, 0.f, 0.f};
    for (int e = 0; e < E_; e++) {
        float gv = g_gates[b*E_ + e];
        if (gv == 0.f) continue;
        int p = e*B_ + b;
        const float* hr = h1 + ((size_t)p*S_ + s)*D_;
        const float* fr = f2 + ((size_t)p*S_ + s)*D_;
        float v[4]; float sum = 0.f, sq = 0.f;
        #pragma unroll
        for (int j = 0; j < 4; j++) {
            int i = tid + j*256;
            float t = hr[i] + fr[i];
            v[j] = t; sum += t; sq = fmaf(t, t, sq);
        }
        float2 r = block_reduce2(sum, sq);
        float mean = r.x * (1.f/D_);
        float var = r.y * (1.f/D_) - mean*mean;
        float rstd = rsqrtf(var + 1e-5f);
        #pragma unroll
        for (int j = 0; j < 4; j++) {
            int i = tid + j*256;
            acc[j] += gv * ((v[j]-mean)*rstd*g2[e*D_+i] + be2[e*D_+i]);
        }
    }
    float* yr = y + ((size_t)b*S_ + s)*D_;
    #pragma unroll
    for (int j = 0; j < 4; j++) {
        int i = tid + j*256;
        float o = acc[j];
        if (o == 0.f) o = EPS_FILL_F;
        yr[i] = o;
    }
}

// ---------------- launch ----------------------------------------------------
extern "C" void kernel_launch(void* const* d_in, const int* in_sizes, int n_in,
                              void* d_out, int out_size)
{
    const float* x       = (const float*)d_in[0];
    const float* noise   = (const float*)d_in[2];
    const float* w_gate  = (const float*)d_in[3];
    const float* w_noise = (const float*)d_in[4];
    const float* Wq      = (const float*)d_in[5];
    const float* Wk      = (const float*)d_in[6];
    const float* Wv      = (const float*)d_in[7];
    const float* Wo      = (const float*)d_in[8];
    const float* W1      = (const float*)d_in[9];
    const float* b1      = (const float*)d_in[10];
    const float* W2      = (const float*)d_in[11];
    const float* b2      = (const float*)d_in[12];
    const float* g1      = (const float*)d_in[13];
    const float* be1     = (const float*)d_in[14];
    const float* g2      = (const float*)d_in[15];
    const float* be2     = (const float*)d_in[16];
    float* out = (float*)d_out;

    float *pQ, *pK, *pV;
    __half *pXh, *pAth, *pH1h, *pFFh;
    __half *pWq, *pWk, *pWv, *pWo, *pW1, *pW2;
    cudaGetSymbolAddress((void**)&pQ,   g_q);
    cudaGetSymbolAddress((void**)&pK,   g_k);
    cudaGetSymbolAddress((void**)&pV,   g_v);
    cudaGetSymbolAddress((void**)&pXh,  g_xh);
    cudaGetSymbolAddress((void**)&pAth, g_ath);
    cudaGetSymbolAddress((void**)&pH1h, g_h1h);
    cudaGetSymbolAddress((void**)&pFFh, g_ffh);
    cudaGetSymbolAddress((void**)&pWq,  g_wqH);
    cudaGetSymbolAddress((void**)&pWk,  g_wkH);
    cudaGetSymbolAddress((void**)&pWv,  g_wvH);
    cudaGetSymbolAddress((void**)&pWo,  g_woH);
    cudaGetSymbolAddress((void**)&pW1,  g_w1H);
    cudaGetSymbolAddress((void**)&pW2,  g_w2H);

    cudaFuncSetAttribute(tgemm_kernel, cudaFuncAttributeMaxDynamicSharedMemorySize, SMEM_GEMM);

    const long SD  = (long)S_*D_;
    const long BSD = (long)B_*S_*D_;
    const long SF  = (long)S_*FF_;
    const long BSF = (long)B_*S_*FF_;

    // gating path
    sumx_kernel<<<dim3(D_/256, B_), 256>>>(x);
    gate_kernel<<<1, 1024>>>(w_gate, w_noise, noise, out + (size_t)B_*S_*D_);

    // single coalesced convert: all 6 weights + x -> fp16 (original [K][N] layouts)
    convert_all_kernel<<<NCONV_BLOCKS, 256>>>(Wq, Wk, Wv, Wo, W1, W2, x);

    // fused QKV projections: sel = blockIdx.y/8 picks {Wq,Wk,Wv} and {pQ,pK,pV}
    tgemm_kernel<<<dim3(2, 3*(D_/128), NPAIR), 256, SMEM_GEMM>>>(
        pXh, pWq, pWk, pWv,
        nullptr, pQ, pK, pV, nullptr, D_, D_, 0, SD, 0);

    // attention (fp32 in, writes fp16), 2 CTAs per (p,h)
    attn_kernel<<<dim3(NPAIR, H_, 2), 256>>>();

    // O projection -> fp32 (reuse g_q)
    tgemm_kernel<<<dim3(2, D_/128, NPAIR), 256, SMEM_GEMM>>>(
        pAth, pWo, pWo, pWo,
        nullptr, pQ, nullptr, nullptr, nullptr, D_, D_, BSD, SD, 0);

    // h1 = LN(x + oproj): fp32 into g_k, fp16 into g_h1h
    addln_kernel<<<dim3(NPAIR, S_), 256>>>(x, pQ, g1, be1, pK);

    // FFN1: relu(h1 @ W1 + b1) -> fp16
    tgemm_kernel<<<dim3(2, FF_/128, NPAIR), 256, SMEM_GEMM>>>(
        pH1h, pW1, pW1, pW1,
        b1, nullptr, nullptr, nullptr, pFFh, D_, FF_, BSD, SD, 1);

    // FFN2: ff @ W2 + b2 -> fp32 (reuse g_v)
    tgemm_kernel<<<dim3(2, D_/128, NPAIR), 256, SMEM_GEMM>>>(
        pFFh, pW2, pW2, pW2,
        b2, pV, nullptr, nullptr, nullptr, FF_, D_, BSF, SF, 0);

    // combine
    final_kernel<<<dim3(B_, S_), 256>>>(pK, pV, g2, be2, out);
}

// round 17
// speedup vs baseline: 4.9221x; 1.0201x over previous
#include <cuda_runtime.h>
#include <cuda_fp16.h>
#include <math_constants.h>
#include <cstdint>

#define B_ 8
#define S_ 256
#define D_ 1024
#define H_ 16
#define E_ 4
#define FF_ 4096
#define HD_ 64
#define NPAIR (E_*B_)
#define SCALE_ 0.125f
#define EPS_FILL_F 2.2204460492503131e-16f
#define KCH 64
#define LDA 72                        // padded A row (halves) for 128x64 tiles (144B rows)
#define ATILE_B (128*LDA*2)           // 18432 bytes
#define BTILE_B (64*272)              // 17408 bytes ([K=64][N=128] fp16, 272B padded rows)
#define STAGE_B (ATILE_B + BTILE_B)   // 35840
#define NSTAGE 3
#define SMEM_GEMM (NSTAGE*STAGE_B)    // 107520

// ---------------- scratch (device globals: no allocations allowed) ----------
__device__ float g_xs[B_*D_];
__device__ float g_gates[B_*E_];
__device__ float g_q[(size_t)NPAIR*S_*D_];
__device__ float g_k[(size_t)NPAIR*S_*D_];   // later reused as h1 (fp32)
__device__ float g_v[(size_t)NPAIR*S_*D_];   // later reused as ffn2 out (fp32)
__device__ __half g_xh[(size_t)B_*S_*D_];
__device__ __half g_ath[(size_t)NPAIR*S_*D_];
__device__ __half g_h1h[(size_t)NPAIR*S_*D_];
__device__ __half g_ffh[(size_t)NPAIR*S_*FF_];
// fp16 weights, ORIGINAL layout [e][K][N]
__device__ __half g_wqH[(size_t)E_*D_*D_];
__device__ __half g_wkH[(size_t)E_*D_*D_];
__device__ __half g_wvH[(size_t)E_*D_*D_];
__device__ __half g_woH[(size_t)E_*D_*D_];
__device__ __half g_w1H[(size_t)E_*D_*FF_];
__device__ __half g_w2H[(size_t)E_*D_*FF_];

// ---------------- helpers ----------------
__device__ __forceinline__ uint32_t smem_u32(const void* p){
    uint32_t a;
    asm("{ .reg .u64 t; cvta.to.shared.u64 t, %1; cvt.u32.u64 %0, t; }" : "=r"(a) : "l"(p));
    return a;
}
__device__ __forceinline__ void ldsm_x4(uint32_t (&r)[4], uint32_t addr){
    asm volatile("ldmatrix.sync.aligned.m8n8.x4.shared.b16 {%0,%1,%2,%3}, [%4];"
                 : "=r"(r[0]),"=r"(r[1]),"=r"(r[2]),"=r"(r[3]) : "r"(addr));
}
__device__ __forceinline__ void ldsm_x4_t(uint32_t (&r)[4], uint32_t addr){
    asm volatile("ldmatrix.sync.aligned.m8n8.x4.trans.shared.b16 {%0,%1,%2,%3}, [%4];"
                 : "=r"(r[0]),"=r"(r[1]),"=r"(r[2]),"=r"(r[3]) : "r"(addr));
}
__device__ __forceinline__ void mma16816(float (&c)[4], const uint32_t (&a)[4], const uint32_t (&b)[2]){
    asm volatile("mma.sync.aligned.m16n8k16.row.col.f32.f16.f16.f32 "
                 "{%0,%1,%2,%3},{%4,%5,%6,%7},{%8,%9},{%0,%1,%2,%3};"
                 : "+f"(c[0]),"+f"(c[1]),"+f"(c[2]),"+f"(c[3])
                 : "r"(a[0]),"r"(a[1]),"r"(a[2]),"r"(a[3]),"r"(b[0]),"r"(b[1]));
}
__device__ __forceinline__ void cp16(uint32_t s, const void* g){
    asm volatile("cp.async.cg.shared.global [%0], [%1], 16;" :: "r"(s), "l"(g));
}

// ---------------- xs = x.sum(axis=1) ----------------
__global__ void sumx_kernel(const float* __restrict__ x)
{
    int d = blockIdx.x*256 + threadIdx.x;
    int b = blockIdx.y;
    const float* xp = x + (size_t)b*S_*D_ + d;
    float acc = 0.f;
    #pragma unroll 4
    for (int s = 0; s < S_; s++) acc += xp[(size_t)s*D_];
    g_xs[b*D_ + d] = acc;
}

// ---------------- noisy top-k gating + aux loss ----------------
__global__ void gate_kernel(const float* __restrict__ w_gate,
                            const float* __restrict__ w_noise,
                            const float* __restrict__ noise,
                            float* __restrict__ loss_out)
{
    __shared__ float s_clean[B_][E_], s_raw[B_][E_], s_prob[B_][E_], s_gate[B_][E_];
    int tid = threadIdx.x;
    int wid = tid >> 5, lane = tid & 31;
    {
        int b = wid >> 2, e = wid & 3;
        float ac = 0.f, ar = 0.f;
        for (int i = lane; i < D_; i += 32) {
            float xv = g_xs[b*D_ + i];
            ac = fmaf(xv, w_gate[i*E_ + e], ac);
            ar = fmaf(xv, w_noise[i*E_ + e], ar);
        }
        #pragma unroll
        for (int o = 16; o > 0; o >>= 1) {
            ac += __shfl_xor_sync(0xffffffffu, ac, o);
            ar += __shfl_xor_sync(0xffffffffu, ar, o);
        }
        if (lane == 0) { s_clean[b][e] = ac; s_raw[b][e] = ar; }
    }
    __syncthreads();
    if (tid < B_) {
        int b = tid;
        float clean[E_], noisy[E_], sd[E_];
        #pragma unroll
        for (int e = 0; e < E_; e++) {
            clean[e] = s_clean[b][e];
            float r = s_raw[b][e];
            float sp = fmaxf(r, 0.f) + log1pf(expf(-fabsf(r)));
            sd[e] = sp + 0.01f;
            noisy[e] = clean[e] + noise[b*E_ + e] * sd[e];
        }
        int ord[3]; bool used[E_] = {false,false,false,false};
        for (int s = 0; s < 3; s++) {
            int best = -1;
            for (int e = 0; e < E_; e++)
                if (!used[e] && (best < 0 || noisy[e] > noisy[best])) best = e;
            used[best] = true; ord[s] = best;
        }
        float l0 = noisy[ord[0]], l1 = noisy[ord[1]], l2 = noisy[ord[2]];
        float e1 = expf(l1 - l0);
        float inv = 1.f / (1.f + e1);
        #pragma unroll
        for (int e = 0; e < E_; e++) s_gate[b][e] = 0.f;
        s_gate[b][ord[0]] = inv;
        s_gate[b][ord[1]] = e1 * inv;
        #pragma unroll
        for (int e = 0; e < E_; e++) {
            bool isin = noisy[e] > l2;
            float thr = isin ? l2 : l1;
            s_prob[b][e] = normcdff((clean[e] - thr) / sd[e]);
            g_gates[b*E_ + e] = s_gate[b][e];
        }
    }
    __syncthreads();
    if (tid == 0) {
        float cv[2];
        for (int which = 0; which < 2; which++) {
            float v[E_];
            for (int e = 0; e < E_; e++) {
                float s = 0.f;
                for (int b = 0; b < B_; b++)
                    s += which ? s_prob[b][e] : s_gate[b][e];
                v[e] = s;
            }
            float m = (v[0]+v[1]+v[2]+v[3]) * 0.25f;
            float var = 0.f;
            for (int e = 0; e < E_; e++) { float dd = v[e]-m; var += dd*dd; }
            var *= (1.0f / (E_ - 1));
            cv[which] = var / (m*m + 1e-10f);
        }
        loss_out[0] = (cv[0] + cv[1]) * 0.01f;
    }
}

// ---------------- single coalesced fp32->fp16 convert (weights + x) ---------
#define BWD (E_*D_*D_/2048)     // blocks per DxD weight
#define BWF (E_*D_*FF_/2048)    // blocks per DxFF weight
#define BX  (B_*S_*D_/2048)     // blocks for x
#define NCONV_BLOCKS (4*BWD + 2*BWF + BX)

__global__ void convert_all_kernel(const float* __restrict__ Wq, const float* __restrict__ Wk,
                                   const float* __restrict__ Wv, const float* __restrict__ Wo,
                                   const float* __restrict__ W1, const float* __restrict__ W2,
                                   const float* __restrict__ x)
{
    int blk = blockIdx.x;
    const float* src; __half* dst;
    if      (blk < 1*BWD)       { src = Wq; dst = g_wqH; }
    else if (blk < 2*BWD)       { src = Wk; dst = g_wkH; blk -= 1*BWD; }
    else if (blk < 3*BWD)       { src = Wv; dst = g_wvH; blk -= 2*BWD; }
    else if (blk < 4*BWD)       { src = Wo; dst = g_woH; blk -= 3*BWD; }
    else if (blk < 4*BWD+BWF)   { src = W1; dst = g_w1H; blk -= 4*BWD; }
    else if (blk < 4*BWD+2*BWF) { src = W2; dst = g_w2H; blk -= 4*BWD+BWF; }
    else                        { src = x;  dst = g_xh;  blk -= 4*BWD+2*BWF; }
    size_t i = ((size_t)blk*256 + threadIdx.x)*8;
    float4 a = *(const float4*)(src + i);
    float4 c = *(const float4*)(src + i + 4);
    __half2 h0 = __floats2half2_rn(a.x, a.y), h1 = __floats2half2_rn(a.z, a.w);
    __half2 h2 = __floats2half2_rn(c.x, c.y), h3 = __floats2half2_rn(c.z, c.w);
    uint4 o;
    o.x = *reinterpret_cast<uint32_t*>(&h0);
    o.y = *reinterpret_cast<uint32_t*>(&h1);
    o.z = *reinterpret_cast<uint32_t*>(&h2);
    o.w = *reinterpret_cast<uint32_t*>(&h3);
    *reinterpret_cast<uint4*>(dst + i) = o;
}

// ---------------- HMMA fp16 GEMM, cp.async 3-stage, KCH=64, B in [K][N] ------
// Up to 3 weight groups (Q/K/V fused): sel = blockIdx.y / (N/128)
__global__ __launch_bounds__(256) void tgemm_kernel(
    const __half* __restrict__ A0,
    const __half* __restrict__ Bw0, const __half* __restrict__ Bw1, const __half* __restrict__ Bw2,
    const float* __restrict__ biasbase,
    float* __restrict__ outF0, float* __restrict__ outF1, float* __restrict__ outF2,
    __half* __restrict__ outH,
    int Kdim, int N, long sAe, long sAb, int doRelu)
{
    int p = blockIdx.z, e = p >> 3, b = p & 7;
    if (g_gates[b*E_ + e] == 0.f) return;

    int nGC = N >> 7;
    int sel = blockIdx.y / nGC;
    int colBase = (blockIdx.y % nGC) * 128;
    const __half* Bw = (sel == 0) ? Bw0 : (sel == 1) ? Bw1 : Bw2;
    float* outF = (sel == 0) ? outF0 : (sel == 1) ? outF1 : outF2;

    extern __shared__ char smem[];
    uint32_t sm = smem_u32(smem);

    int tid = threadIdx.x, wid = tid >> 5, lane = tid & 31;
    int warpRow = wid >> 2;        // 0..1  (64 rows each)
    int warpCol = wid & 3;         // 0..3  (32 cols each)
    int rowBase = blockIdx.x * 128;

    const __half* Aptr = A0 + (size_t)e*sAe + (size_t)b*sAb + (size_t)rowBase*Kdim;
    const __half* Bptr = Bw + (size_t)e*((size_t)Kdim*N) + colBase;   // [K][N] layout

    // A ldmatrix byte offsets (row-major, non-trans), rows of LDA*2 = 144B
    uint32_t aOff = (uint32_t)((lane & 15) * (LDA*2)) + ((lane >> 4) * 16);
    uint32_t aWarp = (uint32_t)(warpRow * 64) * (LDA*2);
    // B ldmatrix.trans lane base: matrices (k0-7,n0-7),(k8-15,n0-7),(k0-7,n8-15),(k8-15,n8-15)
    int mlane = lane >> 3, rlane = lane & 7;
    uint32_t bTransBase = (uint32_t)(((mlane & 1)*8 + rlane) * 272 + (mlane >> 1) * 16);
    uint32_t nWb = (uint32_t)(warpCol * 32) * 2;   // warp's n-range byte offset

    // cp.async indices: A 128x64 halves = 1024 vec16 (4/thread); B 64x128 = 1024 vec16 (4/thread)
    int rA = tid >> 3, cA = tid & 7;               // + j*32 rows
    uint32_t soA = (uint32_t)rA*(LDA*2) + (uint32_t)cA*16;
    int rB = tid >> 4, cB = tid & 15;              // + j*16 rows
    uint32_t soB = (uint32_t)rB*272 + (uint32_t)cB*16;

    float acc[4][4][4];
    #pragma unroll
    for (int i = 0; i < 4; i++)
        #pragma unroll
        for (int j = 0; j < 4; j++)
            #pragma unroll
            for (int q = 0; q < 4; q++) acc[i][j][q] = 0.f;

    int nCh = Kdim / KCH;

    auto load_stage = [&](int kt, int st){
        size_t koff = (size_t)kt * KCH;
        uint32_t sb = sm + (uint32_t)st*STAGE_B;
        #pragma unroll
        for (int j = 0; j < 4; j++) {
            // A: rows rA + j*32
            cp16(sb + soA + (uint32_t)j*32*(LDA*2),
                 Aptr + (size_t)(rA + j*32)*Kdim + koff + (size_t)cA*8);
            // B: rows rB + j*16
            cp16(sb + ATILE_B + soB + (uint32_t)j*16*272,
                 Bptr + (koff + rB + j*16)*(size_t)N + cB*8);
        }
        asm volatile("cp.async.commit_group;");
    };

    // 3-stage pipeline, one __syncthreads per 64-wide chunk.
    load_stage(0, 0);
    if (nCh > 1) load_stage(1, 1);
    for (int kt = 0; kt < nCh; kt++) {
        int st = kt % NSTAGE;
        if (kt + 1 < nCh) {
            asm volatile("cp.async.wait_group 1;");
        } else {
            asm volatile("cp.async.wait_group 0;");
        }
        // Barrier: (a) load kt visible to all warps, (b) all warps done with
        // compute kt-1 so its buffer ((kt+2)%3) may be overwritten below.
        __syncthreads();
        if (kt + 2 < nCh) load_stage(kt + 2, (kt + 2) % NSTAGE);

        uint32_t sA32 = sm + (uint32_t)st*STAGE_B;
        uint32_t sB32 = sA32 + ATILE_B;

        #pragma unroll
        for (int k16 = 0; k16 < 4; k16++) {
            uint32_t kbA = (uint32_t)k16 * 32;          // A: 16 halves
            uint32_t kbB = (uint32_t)k16 * (16*272);    // B: 16 k-rows
            uint32_t a[4][4], bh[4][2];
            #pragma unroll
            for (int j = 0; j < 2; j++) {
                uint32_t r4[4];
                ldsm_x4_t(r4, sB32 + kbB + bTransBase + nWb + (uint32_t)j*32);
                bh[2*j][0]   = r4[0]; bh[2*j][1]   = r4[1];
                bh[2*j+1][0] = r4[2]; bh[2*j+1][1] = r4[3];
            }
            #pragma unroll
            for (int mt = 0; mt < 4; mt++)
                ldsm_x4(a[mt], sA32 + aWarp + aOff + mt*(16*LDA*2) + kbA);
            #pragma unroll
            for (int mt = 0; mt < 4; mt++)
                #pragma unroll
                for (int nt = 0; nt < 4; nt++)
                    mma16816(acc[mt][nt], a[mt], bh[nt]);
        }
    }

    // ---------------- epilogue ----------------
    const float* bias = biasbase ? biasbase + (size_t)e*N : nullptr;
    int mWarp = rowBase + warpRow*64;
    int nWarp = colBase + warpCol*32;
    int rq = lane >> 2, cq = (lane & 3)*2;

    #pragma unroll
    for (int mt = 0; mt < 4; mt++) {
        #pragma unroll
        for (int nt = 0; nt < 4; nt++) {
            int col = nWarp + nt*8 + cq;
            float b0 = bias ? bias[col] : 0.f;
            float b1 = bias ? bias[col+1] : 0.f;
            #pragma unroll
            for (int half = 0; half < 2; half++) {
                int row = mWarp + mt*16 + rq + half*8;
                float v0 = acc[mt][nt][2*half+0] + b0;
                float v1 = acc[mt][nt][2*half+1] + b1;
                if (doRelu) { v0 = fmaxf(v0, 0.f); v1 = fmaxf(v1, 0.f); }
                size_t o = ((size_t)p*S_ + row)*N + col;
                if (outF) *(float2*)(outF + o) = make_float2(v0, v1);
                if (outH) {
                    __half2 hv = __floats2half2_rn(v0, v1);
                    *(__half2*)(outH + o) = hv;
                }
            }
        }
    }
}

// ---------------- fused causal attention (2 threads per query) ---------------
__global__ __launch_bounds__(256) void attn_kernel()
{
    int p = blockIdx.x, h = blockIdx.y;
    int e = p / B_, b = p % B_;
    if (g_gates[b*E_ + e] == 0.f) return;
    __shared__ __align__(16) float Ks[64][72];
    __shared__ __align__(16) float Vs[64][72];
    int tid = threadIdx.x;
    int lane = tid & 31;
    unsigned pmask = 3u << (lane & 30);   // pair mask: lanes {2i, 2i+1} only
    int q = blockIdx.z*128 + (tid >> 1);
    int hf = tid & 1;
    int cb = hf * 36;    // halves stored at cols 0..31 and 36..67 (bank-skewed)

    float qreg[32];
    {
        const float* qp = &g_q[((size_t)p*S_ + q)*D_ + h*HD_ + hf*32];
        #pragma unroll
        for (int i = 0; i < 32; i += 4) {
            float4 t = *reinterpret_cast<const float4*>(qp + i);
            qreg[i] = t.x; qreg[i+1] = t.y; qreg[i+2] = t.z; qreg[i+3] = t.w;
        }
    }
    float acc[32];
    #pragma unroll
    for (int i = 0; i < 32; i++) acc[i] = 0.f;
    float m = -CUDART_INF_F, l = 0.f;

    int ntile = (blockIdx.z == 0) ? 2 : 4;
    for (int t = 0; t < ntile; t++) {
        #pragma unroll
        for (int pass = 0; pass < 4; pass++) {
            int r = pass*16 + (tid >> 4);
            int c = (tid & 15) * 4;
            int cs = c + ((c >= 32) ? 4 : 0);
            size_t off = ((size_t)p*S_ + t*64 + r)*D_ + h*HD_ + c;
            *reinterpret_cast<float4*>(&Ks[r][cs]) = *reinterpret_cast<const float4*>(&g_k[off]);
            *reinterpret_cast<float4*>(&Vs[r][cs]) = *reinterpret_cast<const float4*>(&g_v[off]);
        }
        __syncthreads();
        int kmax = q - t*64;
        if (kmax > 63) kmax = 63;
        for (int kk = 0; kk <= kmax; kk++) {
            const float* kr = &Ks[kk][cb];
            float d0 = 0.f, d1 = 0.f, d2 = 0.f, d3 = 0.f;
            #pragma unroll
            for (int i = 0; i < 32; i += 4) {
                d0 = fmaf(qreg[i+0], kr[i+0], d0);
                d1 = fmaf(qreg[i+1], kr[i+1], d1);
                d2 = fmaf(qreg[i+2], kr[i+2], d2);
                d3 = fmaf(qreg[i+3], kr[i+3], d3);
            }
            float s = (d0 + d1) + (d2 + d3);
            s += __shfl_xor_sync(pmask, s, 1);     // pair-convergent: same q, same kmax
            s *= SCALE_;
            float mn = fmaxf(m, s);
            float corr = __expf(m - mn);
            float pw = __expf(s - mn);
            l = l*corr + pw;
            const float* vr = &Vs[kk][cb];
            #pragma unroll
            for (int i = 0; i < 32; i++) acc[i] = fmaf(acc[i], corr, pw*vr[i]);
            m = mn;
        }
        __syncthreads();
    }
    float invl = 1.f / l;
    size_t ob = ((size_t)p*S_ + q)*D_ + h*HD_ + hf*32;
    #pragma unroll
    for (int i = 0; i < 32; i += 2) {
        __half2 hv = __floats2half2_rn(acc[i]*invl, acc[i+1]*invl);
        *(__half2*)(&g_ath[ob + i]) = hv;
    }
}

// ---------------- block reduce (sum, sumsq), blockDim = 256 -----------------
__device__ __forceinline__ float2 block_reduce2(float a, float b)
{
    __shared__ float2 sh[9];
    int tid = threadIdx.x, lane = tid & 31, wid = tid >> 5;
    #pragma unroll
    for (int o = 16; o > 0; o >>= 1) {
        a += __shfl_xor_sync(0xffffffffu, a, o);
        b += __shfl_xor_sync(0xffffffffu, b, o);
    }
    if (lane == 0) sh[wid] = make_float2(a, b);
    __syncthreads();
    if (tid == 0) {
        float sa = 0.f, sb = 0.f;
        #pragma unroll
        for (int w = 0; w < 8; w++) { sa += sh[w].x; sb += sh[w].y; }
        sh[8] = make_float2(sa, sb);
    }
    __syncthreads();
    float2 r = sh[8];
    __syncthreads();
    return r;
}

// ---------------- h1 = LN(x + oproj)*g1+be1 : fp32 + fp16 -------------------
__global__ __launch_bounds__(256) void addln_kernel(
    const float* __restrict__ xbase, const float* __restrict__ res,
    const float* __restrict__ gain, const float* __restrict__ beta,
    float* __restrict__ out)
{
    int p = blockIdx.x; int e = p / B_, b = p % B_;
    if (g_gates[b*E_ + e] == 0.f) return;
    int s = blockIdx.y, tid = threadIdx.x;
    const float* xr = xbase + ((size_t)b*S_ + s)*D_;
    const float* rr = res + ((size_t)p*S_ + s)*D_;
    float v[4]; float sum = 0.f, sq = 0.f;
    #pragma unroll
    for (int j = 0; j < 4; j++) {
        int i = tid + j*256;
        float t = xr[i] + rr[i];
        v[j] = t; sum += t; sq = fmaf(t, t, sq);
    }
    float2 r = block_reduce2(sum, sq);
    float mean = r.x * (1.f/D_);
    float var = r.y * (1.f/D_) - mean*mean;
    float rstd = rsqrtf(var + 1e-5f);
    size_t ob = ((size_t)p*S_ + s)*D_;
    #pragma unroll
    for (int j = 0; j < 4; j++) {
        int i = tid + j*256;
        float o = (v[j] - mean)*rstd*gain[e*D_ + i] + beta[e*D_ + i];
        out[ob + i] = o;
        g_h1h[ob + i] = __float2half_rn(o);
    }
}

// ---------------- y = sum_e gate * LN(h1 + ff2), eps-fill -------------------
__global__ __launch_bounds__(256) void final_kernel(
    const float* __restrict__ h1, const float* __restrict__ f2,
    const float* __restrict__ g2, const float* __restrict__ be2,
    float* __restrict__ y)
{
    int b = blockIdx.x, s = blockIdx.y, tid = threadIdx.x;
    float acc[4] = {0.f, 0.f, 0.f, 0.f};
    for (int e = 0; e < E_; e++) {
        float gv = g_gates[b*E_ + e];
        if (gv == 0.f) continue;
        int p = e*B_ + b;
        const float* hr = h1 + ((size_t)p*S_ + s)*D_;
        const float* fr = f2 + ((size_t)p*S_ + s)*D_;
        float v[4]; float sum = 0.f, sq = 0.f;
        #pragma unroll
        for (int j = 0; j < 4; j++) {
            int i = tid + j*256;
            float t = hr[i] + fr[i];
            v[j] = t; sum += t; sq = fmaf(t, t, sq);
        }
        float2 r = block_reduce2(sum, sq);
        float mean = r.x * (1.f/D_);
        float var = r.y * (1.f/D_) - mean*mean;
        float rstd = rsqrtf(var + 1e-5f);
        #pragma unroll
        for (int j = 0; j < 4; j++) {
            int i = tid + j*256;
            acc[j] += gv * ((v[j]-mean)*rstd*g2[e*D_+i] + be2[e*D_+i]);
        }
    }
    float* yr = y + ((size_t)b*S_ + s)*D_;
    #pragma unroll
    for (int j = 0; j < 4; j++) {
        int i = tid + j*256;
        float o = acc[j];
        if (o == 0.f) o = EPS_FILL_F;
        yr[i] = o;
    }
}

// ---------------- launch ----------------------------------------------------
extern "C" void kernel_launch(void* const* d_in, const int* in_sizes, int n_in,
                              void* d_out, int out_size)
{
    const float* x       = (const float*)d_in[0];
    const float* noise   = (const float*)d_in[2];
    const float* w_gate  = (const float*)d_in[3];
    const float* w_noise = (const float*)d_in[4];
    const float* Wq      = (const float*)d_in[5];
    const float* Wk      = (const float*)d_in[6];
    const float* Wv      = (const float*)d_in[7];
    const float* Wo      = (const float*)d_in[8];
    const float* W1      = (const float*)d_in[9];
    const float* b1      = (const float*)d_in[10];
    const float* W2      = (const float*)d_in[11];
    const float* b2      = (const float*)d_in[12];
    const float* g1      = (const float*)d_in[13];
    const float* be1     = (const float*)d_in[14];
    const float* g2      = (const float*)d_in[15];
    const float* be2     = (const float*)d_in[16];
    float* out = (float*)d_out;

    float *pQ, *pK, *pV;
    __half *pXh, *pAth, *pH1h, *pFFh;
    __half *pWq, *pWk, *pWv, *pWo, *pW1, *pW2;
    cudaGetSymbolAddress((void**)&pQ,   g_q);
    cudaGetSymbolAddress((void**)&pK,   g_k);
    cudaGetSymbolAddress((void**)&pV,   g_v);
    cudaGetSymbolAddress((void**)&pXh,  g_xh);
    cudaGetSymbolAddress((void**)&pAth, g_ath);
    cudaGetSymbolAddress((void**)&pH1h, g_h1h);
    cudaGetSymbolAddress((void**)&pFFh, g_ffh);
    cudaGetSymbolAddress((void**)&pWq,  g_wqH);
    cudaGetSymbolAddress((void**)&pWk,  g_wkH);
    cudaGetSymbolAddress((void**)&pWv,  g_wvH);
    cudaGetSymbolAddress((void**)&pWo,  g_woH);
    cudaGetSymbolAddress((void**)&pW1,  g_w1H);
    cudaGetSymbolAddress((void**)&pW2,  g_w2H);

    cudaFuncSetAttribute(tgemm_kernel, cudaFuncAttributeMaxDynamicSharedMemorySize, SMEM_GEMM);

    const long SD  = (long)S_*D_;
    const long BSD = (long)B_*S_*D_;
    const long SF  = (long)S_*FF_;
    const long BSF = (long)B_*S_*FF_;

    // gating path
    sumx_kernel<<<dim3(D_/256, B_), 256>>>(x);
    gate_kernel<<<1, 1024>>>(w_gate, w_noise, noise, out + (size_t)B_*S_*D_);

    // single coalesced convert: all 6 weights + x -> fp16 (original [K][N] layouts)
    convert_all_kernel<<<NCONV_BLOCKS, 256>>>(Wq, Wk, Wv, Wo, W1, W2, x);

    // fused QKV projections: sel = blockIdx.y/8 picks {Wq,Wk,Wv} and {pQ,pK,pV}
    tgemm_kernel<<<dim3(2, 3*(D_/128), NPAIR), 256, SMEM_GEMM>>>(
        pXh, pWq, pWk, pWv,
        nullptr, pQ, pK, pV, nullptr, D_, D_, 0, SD, 0);

    // attention (fp32 in, writes fp16), 2 CTAs per (p,h)
    attn_kernel<<<dim3(NPAIR, H_, 2), 256>>>();

    // O projection -> fp32 (reuse g_q)
    tgemm_kernel<<<dim3(2, D_/128, NPAIR), 256, SMEM_GEMM>>>(
        pAth, pWo, pWo, pWo,
        nullptr, pQ, nullptr, nullptr, nullptr, D_, D_, BSD, SD, 0);

    // h1 = LN(x + oproj): fp32 into g_k, fp16 into g_h1h
    addln_kernel<<<dim3(NPAIR, S_), 256>>>(x, pQ, g1, be1, pK);

    // FFN1: relu(h1 @ W1 + b1) -> fp16
    tgemm_kernel<<<dim3(2, FF_/128, NPAIR), 256, SMEM_GEMM>>>(
        pH1h, pW1, pW1, pW1,
        b1, nullptr, nullptr, nullptr, pFFh, D_, FF_, BSD, SD, 1);

    // FFN2: ff @ W2 + b2 -> fp32 (reuse g_v)
    tgemm_kernel<<<dim3(2, D_/128, NPAIR), 256, SMEM_GEMM>>>(
        pFFh, pW2, pW2, pW2,
        b2, pV, nullptr, nullptr, nullptr, FF_, D_, BSF, SF, 0);

    // combine
    final_kernel<<<dim3(B_, S_), 256>>>(pK, pV, g2, be2, out);
}